// round 2
// baseline (speedup 1.0000x reference)
#include <cuda_runtime.h>
#include <math.h>

#define D_MODEL 1024
#define N_SEQ   2048
#define BATCH   2
#define NHEADS  16
#define DHEAD   64
#define QSCALE  0.125f        // DIM_HEAD^-0.5 = 64^-0.5
#define MTOT    (BATCH * N_SEQ)   // 4096

// Scratch (device globals: allocation-guard-safe)
__device__ float g_q[MTOT * D_MODEL];
__device__ float g_k[MTOT * D_MODEL];
__device__ float g_v[MTOT * D_MODEL];
__device__ float g_o[MTOT * D_MODEL];
__device__ int   g_mask_kind;   // 0 = uint8/bool, 1 = int32, 2 = float32

// ---------------------------------------------------------------------------
// Mask dtype detection: scan first 64KB of the mask buffer.
//   any byte > 1                      -> float32 (bytes 0x80/0x3f from 1.0f)
//   nonzero bytes at offset % 4 != 0  -> uint8/bool (1 byte per element)
//   else                              -> int32 (little-endian 0/1 words)
// Deterministic (input-dependent only). Mask has >= 8.4MB, so 64KB is safe.
// ---------------------------------------------------------------------------
__global__ void detect_mask_kind(const unsigned char* __restrict__ m)
{
    __shared__ int s_maxb, s_nzoff;
    if (threadIdx.x == 0) { s_maxb = 0; s_nzoff = 0; }
    __syncthreads();

    int maxb = 0, nzoff = 0;
    for (int i = threadIdx.x; i < 65536; i += blockDim.x) {
        int v = m[i];
        if (v > maxb) maxb = v;
        if (v && (i & 3)) nzoff++;
    }
    atomicMax(&s_maxb, maxb);
    atomicAdd(&s_nzoff, nzoff);
    __syncthreads();

    if (threadIdx.x == 0) {
        int kind;
        if (s_maxb > 1)      kind = 2;   // float32
        else if (s_nzoff)    kind = 0;   // uint8/bool
        else                 kind = 1;   // int32
        g_mask_kind = kind;
    }
}

// ---------------------------------------------------------------------------
// SGEMM (NT): C[m][n] = alpha * sum_k A[m][k] * W[n][k]  (+ bias[n])
// 128x128 tile, BK=8, 256 threads, 8x8 per thread.
// ---------------------------------------------------------------------------
__global__ __launch_bounds__(256) void gemm_nt(
    const float* __restrict__ A, const float* __restrict__ W,
    const float* __restrict__ bias, float* __restrict__ C,
    int M, int N, int K, float alpha)
{
    __shared__ float As[8][132];
    __shared__ float Ws[8][132];

    const int tid = threadIdx.x;
    const int tx  = tid & 15;
    const int ty  = tid >> 4;
    const int m0  = blockIdx.y * 128;
    const int n0  = blockIdx.x * 128;

    const int r  = tid >> 1;         // 0..127
    const int cg = (tid & 1) * 4;    // 0 or 4

    float acc[8][8];
#pragma unroll
    for (int i = 0; i < 8; i++)
#pragma unroll
        for (int j = 0; j < 8; j++) acc[i][j] = 0.f;

    for (int k0 = 0; k0 < K; k0 += 8) {
        float4 a4 = *(const float4*)&A[(size_t)(m0 + r) * K + k0 + cg];
        float4 w4 = *(const float4*)&W[(size_t)(n0 + r) * K + k0 + cg];
        As[cg + 0][r] = a4.x; As[cg + 1][r] = a4.y;
        As[cg + 2][r] = a4.z; As[cg + 3][r] = a4.w;
        Ws[cg + 0][r] = w4.x; Ws[cg + 1][r] = w4.y;
        Ws[cg + 2][r] = w4.z; Ws[cg + 3][r] = w4.w;
        __syncthreads();

#pragma unroll
        for (int kk = 0; kk < 8; kk++) {
            float a[8], b[8];
            *(float4*)&a[0] = *(const float4*)&As[kk][ty * 8];
            *(float4*)&a[4] = *(const float4*)&As[kk][ty * 8 + 4];
            *(float4*)&b[0] = *(const float4*)&Ws[kk][tx * 8];
            *(float4*)&b[4] = *(const float4*)&Ws[kk][tx * 8 + 4];
#pragma unroll
            for (int i = 0; i < 8; i++)
#pragma unroll
                for (int j = 0; j < 8; j++)
                    acc[i][j] = fmaf(a[i], b[j], acc[i][j]);
        }
        __syncthreads();
    }

#pragma unroll
    for (int i = 0; i < 8; i++) {
        const int m = m0 + ty * 8 + i;
#pragma unroll
        for (int jg = 0; jg < 8; jg += 4) {
            const int n = n0 + tx * 8 + jg;
            float4 o;
            o.x = alpha * acc[i][jg + 0] + (bias ? bias[n + 0] : 0.f);
            o.y = alpha * acc[i][jg + 1] + (bias ? bias[n + 1] : 0.f);
            o.z = alpha * acc[i][jg + 2] + (bias ? bias[n + 2] : 0.f);
            o.w = alpha * acc[i][jg + 3] + (bias ? bias[n + 3] : 0.f);
            *(float4*)&C[(size_t)m * N + n] = o;
        }
    }
}

// ---------------------------------------------------------------------------
// Flash-attention (fp32, online softmax, mask True/nonzero = masked out).
// Grid: (N_SEQ/64, BATCH*NHEADS). Block: 256 threads.
// Q already scaled by QSCALE. Output layout: [B, N, H*DHEAD].
// ---------------------------------------------------------------------------
__global__ __launch_bounds__(256) void attn_kernel(
    const float* __restrict__ Q, const float* __restrict__ Kg,
    const float* __restrict__ V, const void* __restrict__ mask,
    float* __restrict__ O)
{
    extern __shared__ float sm[];
    float* Qs  = sm;                 // [64][65] transposed: Qs[d*65 + i]
    float* Ks  = Qs + 64 * 65;       // [64][65] transposed: Ks[d*65 + j]
    float* Vs  = Ks + 64 * 65;       // [64][65] direct:     Vs[j*65 + d]
    float* Pt  = Vs + 64 * 65;       // [64][65] transposed: Pt[j*65 + i]
    float* m_s = Pt + 64 * 65;       // [64]
    float* l_s = m_s + 64;           // [64]
    float* f_s = l_s + 64;           // [64]

    const int tid = threadIdx.x;
    const int tx  = tid & 15;        // -> 4 cols
    const int ty  = tid >> 4;        // -> 4 rows
    const int bh  = blockIdx.y;
    const int b   = bh >> 4;
    const int h   = bh & 15;
    const int q0  = blockIdx.x * 64;
    const size_t rowbase = (size_t)b * N_SEQ;
    const int hoff = h * DHEAD;
    const int mkind = g_mask_kind;

    // Load Q tile (64 queries x 64 dims), transposed
    {
        const int i  = tid >> 2;
        const int dg = (tid & 3) * 4;
#pragma unroll
        for (int rep = 0; rep < 4; rep++) {
            const int d = dg + rep * 16;
            float4 v4 = *(const float4*)&Q[(rowbase + q0 + i) * D_MODEL + hoff + d];
            Qs[(d + 0) * 65 + i] = v4.x;
            Qs[(d + 1) * 65 + i] = v4.y;
            Qs[(d + 2) * 65 + i] = v4.z;
            Qs[(d + 3) * 65 + i] = v4.w;
        }
    }
    if (tid < 64) { m_s[tid] = -3.0e38f; l_s[tid] = 0.f; }

    float oacc[4][4];
#pragma unroll
    for (int i = 0; i < 4; i++)
#pragma unroll
        for (int j = 0; j < 4; j++) oacc[i][j] = 0.f;

    for (int k0 = 0; k0 < N_SEQ; k0 += 64) {
        __syncthreads();  // previous iteration done with Ks/Vs/Pt

        // Load K (transposed) and V tiles
        {
            const int j  = tid >> 2;
            const int dg = (tid & 3) * 4;
#pragma unroll
            for (int rep = 0; rep < 4; rep++) {
                const int d = dg + rep * 16;
                float4 kv = *(const float4*)&Kg[(rowbase + k0 + j) * D_MODEL + hoff + d];
                Ks[(d + 0) * 65 + j] = kv.x;
                Ks[(d + 1) * 65 + j] = kv.y;
                Ks[(d + 2) * 65 + j] = kv.z;
                Ks[(d + 3) * 65 + j] = kv.w;
                float4 vv = *(const float4*)&V[(rowbase + k0 + j) * D_MODEL + hoff + d];
                Vs[j * 65 + d + 0] = vv.x;
                Vs[j * 65 + d + 1] = vv.y;
                Vs[j * 65 + d + 2] = vv.z;
                Vs[j * 65 + d + 3] = vv.w;
            }
        }
        __syncthreads();

        // S = Q @ K^T (scale folded into Q)
        float s[4][4];
#pragma unroll
        for (int i = 0; i < 4; i++)
#pragma unroll
            for (int j = 0; j < 4; j++) s[i][j] = 0.f;
#pragma unroll 16
        for (int d = 0; d < 64; d++) {
            float a[4], bb[4];
#pragma unroll
            for (int i = 0; i < 4; i++) a[i]  = Qs[d * 65 + ty * 4 + i];
#pragma unroll
            for (int j = 0; j < 4; j++) bb[j] = Ks[d * 65 + tx * 4 + j];
#pragma unroll
            for (int i = 0; i < 4; i++)
#pragma unroll
                for (int j = 0; j < 4; j++)
                    s[i][j] = fmaf(a[i], bb[j], s[i][j]);
        }

        // Apply mask (True / nonzero = masked out), dtype-dispatched
#pragma unroll
        for (int ii = 0; ii < 4; ii++) {
            const size_t midx =
                ((size_t)b * N_SEQ + q0 + ty * 4 + ii) * N_SEQ + k0 + tx * 4;
            bool mz[4];
            if (mkind == 1) {
                int4 mv = *(const int4*)((const int*)mask + midx);
                mz[0] = mv.x != 0; mz[1] = mv.y != 0;
                mz[2] = mv.z != 0; mz[3] = mv.w != 0;
            } else if (mkind == 0) {
                uchar4 mv = *(const uchar4*)((const unsigned char*)mask + midx);
                mz[0] = mv.x != 0; mz[1] = mv.y != 0;
                mz[2] = mv.z != 0; mz[3] = mv.w != 0;
            } else {
                float4 mv = *(const float4*)((const float*)mask + midx);
                mz[0] = mv.x != 0.f; mz[1] = mv.y != 0.f;
                mz[2] = mv.z != 0.f; mz[3] = mv.w != 0.f;
            }
            if (mz[0]) s[ii][0] = -1.0e30f;
            if (mz[1]) s[ii][1] = -1.0e30f;
            if (mz[2]) s[ii][2] = -1.0e30f;
            if (mz[3]) s[ii][3] = -1.0e30f;
        }

        // Store S transposed: Pt[j][i]
#pragma unroll
        for (int ii = 0; ii < 4; ii++)
#pragma unroll
            for (int jj = 0; jj < 4; jj++)
                Pt[(tx * 4 + jj) * 65 + (ty * 4 + ii)] = s[ii][jj];
        __syncthreads();

        // Online softmax: 4 threads per row (64 rows x 4 parts)
        {
            const int row  = tid >> 2;
            const int part = tid & 3;
            float mx = -3.0e38f;
#pragma unroll
            for (int t = 0; t < 16; t++)
                mx = fmaxf(mx, Pt[(part * 16 + t) * 65 + row]);
            mx = fmaxf(mx, __shfl_xor_sync(0xffffffffu, mx, 1));
            mx = fmaxf(mx, __shfl_xor_sync(0xffffffffu, mx, 2));

            const float m_old = m_s[row];
            const float m_new = fmaxf(m_old, mx);

            float sum = 0.f;
#pragma unroll
            for (int t = 0; t < 16; t++) {
                const int j = part * 16 + t;
                float p = __expf(Pt[j * 65 + row] - m_new);
                Pt[j * 65 + row] = p;
                sum += p;
            }
            sum += __shfl_xor_sync(0xffffffffu, sum, 1);
            sum += __shfl_xor_sync(0xffffffffu, sum, 2);   // lanes synced: m_old reads done

            if (part == 0) {
                const float f = __expf(m_old - m_new);
                l_s[row] = l_s[row] * f + sum;
                m_s[row] = m_new;
                f_s[row] = f;
            }
        }
        __syncthreads();

        // Rescale accumulators, then O += P @ V
        float fr[4];
#pragma unroll
        for (int ii = 0; ii < 4; ii++) fr[ii] = f_s[ty * 4 + ii];
#pragma unroll
        for (int ii = 0; ii < 4; ii++)
#pragma unroll
            for (int dd = 0; dd < 4; dd++) oacc[ii][dd] *= fr[ii];

#pragma unroll 16
        for (int j = 0; j < 64; j++) {
            float a[4], vv[4];
#pragma unroll
            for (int ii = 0; ii < 4; ii++) a[ii] = Pt[j * 65 + ty * 4 + ii];
#pragma unroll
            for (int dd = 0; dd < 4; dd++) vv[dd] = Vs[j * 65 + tx * 4 + dd];
#pragma unroll
            for (int ii = 0; ii < 4; ii++)
#pragma unroll
                for (int dd = 0; dd < 4; dd++)
                    oacc[ii][dd] = fmaf(a[ii], vv[dd], oacc[ii][dd]);
        }
    }

    // Normalize and write out
#pragma unroll
    for (int ii = 0; ii < 4; ii++) {
        const float inv = 1.f / l_s[ty * 4 + ii];
        float4 st;
        st.x = oacc[ii][0] * inv;
        st.y = oacc[ii][1] * inv;
        st.z = oacc[ii][2] * inv;
        st.w = oacc[ii][3] * inv;
        *(float4*)&O[(rowbase + q0 + ty * 4 + ii) * D_MODEL + hoff + tx * 4] = st;
    }
}

// ---------------------------------------------------------------------------
extern "C" void kernel_launch(void* const* d_in, const int* in_sizes, int n_in,
                              void* d_out, int out_size)
{
    const float* q  = (const float*)d_in[0];
    const void*  mk = d_in[1];
    const float* Wq = (const float*)d_in[2];
    const float* Wk = (const float*)d_in[3];
    const float* Wv = (const float*)d_in[4];
    const float* Wo = (const float*)d_in[5];
    const float* bo = (const float*)d_in[6];
    float* out      = (float*)d_out;

    float *pq, *pk, *pv, *po;
    cudaGetSymbolAddress((void**)&pq, g_q);
    cudaGetSymbolAddress((void**)&pk, g_k);
    cudaGetSymbolAddress((void**)&pv, g_v);
    cudaGetSymbolAddress((void**)&po, g_o);

    detect_mask_kind<<<1, 256>>>((const unsigned char*)mk);

    dim3 ggrid(D_MODEL / 128, MTOT / 128);   // (8, 32)

    gemm_nt<<<ggrid, 256>>>(q, Wq, nullptr, pq, MTOT, D_MODEL, D_MODEL, QSCALE);
    gemm_nt<<<ggrid, 256>>>(q, Wk, nullptr, pk, MTOT, D_MODEL, D_MODEL, 1.0f);
    gemm_nt<<<ggrid, 256>>>(q, Wv, nullptr, pv, MTOT, D_MODEL, D_MODEL, 1.0f);

    const int smem_bytes = (4 * 64 * 65 + 3 * 64) * (int)sizeof(float);  // 67328
    cudaFuncSetAttribute(attn_kernel, cudaFuncAttributeMaxDynamicSharedMemorySize,
                         smem_bytes);
    attn_kernel<<<dim3(N_SEQ / 64, BATCH * NHEADS), 256, smem_bytes>>>(
        pq, pk, pv, mk, po);

    gemm_nt<<<ggrid, 256>>>(po, Wo, bo, out, MTOT, D_MODEL, D_MODEL, 1.0f);
}

// round 3
// speedup vs baseline: 1.0473x; 1.0473x over previous
#include <cuda_runtime.h>
#include <math.h>

#define D_MODEL 1024
#define N_SEQ   2048
#define BATCH   2
#define NHEADS  16
#define DHEAD   64
#define QSCALE  0.125f
#define MTOT    (BATCH * N_SEQ)   // 4096

typedef unsigned long long ull;

// ---- packed f32x2 helpers (Blackwell FFMA2 path; see SASS_QUICKREF) ----
__device__ __forceinline__ ull dup2(float v) {
    ull r;
    asm("mov.b64 %0, {%1, %1};" : "=l"(r) : "r"(__float_as_uint(v)));
    return r;
}
__device__ __forceinline__ float2 unpack2(ull v) {
    unsigned lo, hi;
    asm("mov.b64 {%0, %1}, %2;" : "=r"(lo), "=r"(hi) : "l"(v));
    return make_float2(__uint_as_float(lo), __uint_as_float(hi));
}
__device__ __forceinline__ void fma2(ull& d, ull a, ull b) {
    asm("fma.rn.f32x2 %0, %1, %2, %0;" : "+l"(d) : "l"(a), "l"(b));
}
__device__ __forceinline__ void mul2(ull& d, ull a) {
    asm("mul.rn.f32x2 %0, %0, %1;" : "+l"(d) : "l"(a));
}

// Scratch (device globals: allocation-guard-safe)
__device__ float g_q[MTOT * D_MODEL];
__device__ float g_k[MTOT * D_MODEL];
__device__ float g_v[MTOT * D_MODEL];
__device__ float g_o[MTOT * D_MODEL];
__device__ int   g_mask_kind;   // 0 = uint8/bool, 1 = int32, 2 = float32

// ---------------------------------------------------------------------------
// Mask dtype detection (first 64KB scan; deterministic).
// ---------------------------------------------------------------------------
__global__ void detect_mask_kind(const unsigned char* __restrict__ m)
{
    __shared__ int s_maxb, s_nzoff;
    if (threadIdx.x == 0) { s_maxb = 0; s_nzoff = 0; }
    __syncthreads();
    int maxb = 0, nzoff = 0;
    for (int i = threadIdx.x; i < 65536; i += blockDim.x) {
        int v = m[i];
        if (v > maxb) maxb = v;
        if (v && (i & 3)) nzoff++;
    }
    atomicMax(&s_maxb, maxb);
    atomicAdd(&s_nzoff, nzoff);
    __syncthreads();
    if (threadIdx.x == 0)
        g_mask_kind = (s_maxb > 1) ? 2 : (s_nzoff ? 0 : 1);
}

// ---------------------------------------------------------------------------
// SGEMM (NT), FFMA2, double-buffered smem, conflict-free 4/64-split tiles.
// C[m][n] = alpha * sum_k A[m][k] * W[n][k] (+ bias[n]).
// ---------------------------------------------------------------------------
__global__ __launch_bounds__(256, 2) void gemm_nt(
    const float* __restrict__ A, const float* __restrict__ W,
    const float* __restrict__ bias, float* __restrict__ C,
    int M, int N, int K, float alpha)
{
    __shared__ float As[2][8][132];
    __shared__ float Ws[2][8][132];

    const int tid = threadIdx.x;
    const int tx  = tid & 15;
    const int ty  = tid >> 4;
    const int m0  = blockIdx.y * 128;
    const int n0  = blockIdx.x * 128;

    const int r  = tid >> 1;
    const int cg = (tid & 1) * 4;

    const float* Aptr = A + (size_t)(m0 + r) * K + cg;
    const float* Wptr = W + (size_t)(n0 + r) * K + cg;

    ull acc[8][4];
#pragma unroll
    for (int i = 0; i < 8; i++)
#pragma unroll
        for (int j = 0; j < 4; j++) acc[i][j] = 0ull;

    // preload tile 0
    {
        float4 a4 = *(const float4*)Aptr;
        float4 w4 = *(const float4*)Wptr;
        As[0][cg + 0][r] = a4.x; As[0][cg + 1][r] = a4.y;
        As[0][cg + 2][r] = a4.z; As[0][cg + 3][r] = a4.w;
        Ws[0][cg + 0][r] = w4.x; Ws[0][cg + 1][r] = w4.y;
        Ws[0][cg + 2][r] = w4.z; Ws[0][cg + 3][r] = w4.w;
    }
    __syncthreads();

    int buf = 0;
    for (int k0 = 0; k0 < K; k0 += 8) {
        float4 a4n, w4n;
        const bool has_next = (k0 + 8) < K;
        if (has_next) {
            a4n = *(const float4*)(Aptr + k0 + 8);
            w4n = *(const float4*)(Wptr + k0 + 8);
        }

#pragma unroll
        for (int kk = 0; kk < 8; kk++) {
            float4 alo = *(const float4*)&As[buf][kk][ty * 4];
            float4 ahi = *(const float4*)&As[buf][kk][64 + ty * 4];
            ulonglong2 blo = *(const ulonglong2*)&Ws[buf][kk][tx * 4];
            ulonglong2 bhi = *(const ulonglong2*)&Ws[buf][kk][64 + tx * 4];
            ull ad[8];
            ad[0] = dup2(alo.x); ad[1] = dup2(alo.y);
            ad[2] = dup2(alo.z); ad[3] = dup2(alo.w);
            ad[4] = dup2(ahi.x); ad[5] = dup2(ahi.y);
            ad[6] = dup2(ahi.z); ad[7] = dup2(ahi.w);
#pragma unroll
            for (int i = 0; i < 8; i++) {
                fma2(acc[i][0], ad[i], blo.x);
                fma2(acc[i][1], ad[i], blo.y);
                fma2(acc[i][2], ad[i], bhi.x);
                fma2(acc[i][3], ad[i], bhi.y);
            }
        }

        if (has_next) {
            const int nb = buf ^ 1;
            As[nb][cg + 0][r] = a4n.x; As[nb][cg + 1][r] = a4n.y;
            As[nb][cg + 2][r] = a4n.z; As[nb][cg + 3][r] = a4n.w;
            Ws[nb][cg + 0][r] = w4n.x; Ws[nb][cg + 1][r] = w4n.y;
            Ws[nb][cg + 2][r] = w4n.z; Ws[nb][cg + 3][r] = w4n.w;
        }
        __syncthreads();
        buf ^= 1;
    }

    // epilogue: rows m0 + ty*4+{0..3} and m0+64+ty*4+{0..3};
    // col pairs: n0 + tx*4 + {0,2} and n0+64+tx*4+{0,2}
#pragma unroll
    for (int i = 0; i < 8; i++) {
        const int m = m0 + ty * 4 + (i & 3) + ((i >> 2) * 64);
#pragma unroll
        for (int jp = 0; jp < 4; jp++) {
            const int n = n0 + tx * 4 + ((jp & 1) * 2) + ((jp >> 1) * 64);
            float2 v = unpack2(acc[i][jp]);
            v.x = alpha * v.x + (bias ? bias[n + 0] : 0.f);
            v.y = alpha * v.y + (bias ? bias[n + 1] : 0.f);
            *(float2*)&C[(size_t)m * N + n] = v;
        }
    }
}

// ---------------------------------------------------------------------------
// Flash-attention, 128x128 tiles, FFMA2, online softmax.
// Grid: (N_SEQ/128, BATCH*NHEADS), 256 threads.
// ---------------------------------------------------------------------------
#define BQ 128
#define BK 128
// smem float offsets
#define OFF_QT 0                     // [64][132]
#define OFF_KT (OFF_QT + 64 * 132)   // [64][132]
#define OFF_VS (OFF_KT + 64 * 132)   // [128][68]
#define OFF_PT (OFF_VS + 128 * 68)   // [128][132]
#define OFF_MS (OFF_PT + 128 * 132)
#define OFF_LS (OFF_MS + 128)
#define OFF_FS (OFF_LS + 128)
#define ATTN_SMEM_FLOATS (OFF_FS + 128)

__global__ __launch_bounds__(256, 1) void attn_kernel(
    const float* __restrict__ Q, const float* __restrict__ Kg,
    const float* __restrict__ V, const void* __restrict__ mask,
    float* __restrict__ O)
{
    extern __shared__ float sm[];
    float* Qt  = sm + OFF_QT;
    float* Kt  = sm + OFF_KT;
    float* Vs  = sm + OFF_VS;
    float* Pt  = sm + OFF_PT;
    float* m_s = sm + OFF_MS;
    float* l_s = sm + OFF_LS;
    float* f_s = sm + OFF_FS;

    const int tid = threadIdx.x;
    const int tx  = tid & 15;        // QK: 2x4 col groups
    const int ty  = tid >> 4;        // QK: 2x4 row groups
    const int ty2 = tid >> 3;        // PV: 4 q rows
    const int tx2 = tid & 7;         // PV: 8 d cols
    const int li  = tid >> 1;        // loader: row 0..127
    const int lh  = (tid & 1) * 32;  // loader: d half

    const int bh = blockIdx.y;
    const int b  = bh >> 4;
    const int h  = bh & 15;
    const int q0 = blockIdx.x * BQ;
    const size_t rowbase = (size_t)b * N_SEQ;
    const int hoff = h * DHEAD;
    const int mkind = g_mask_kind;

    // Load Q tile (128 x 64) transposed: Qt[d][i]
#pragma unroll
    for (int rep = 0; rep < 8; rep++) {
        const int d = lh + rep * 4;
        float4 v4 = *(const float4*)&Q[(rowbase + q0 + li) * D_MODEL + hoff + d];
        Qt[(d + 0) * 132 + li] = v4.x;
        Qt[(d + 1) * 132 + li] = v4.y;
        Qt[(d + 2) * 132 + li] = v4.z;
        Qt[(d + 3) * 132 + li] = v4.w;
    }
    if (tid < 128) { m_s[tid] = -3.0e38f; l_s[tid] = 0.f; }

    ull oacc[4][4];
#pragma unroll
    for (int i = 0; i < 4; i++)
#pragma unroll
        for (int j = 0; j < 4; j++) oacc[i][j] = 0ull;

    for (int k0 = 0; k0 < N_SEQ; k0 += BK) {
        __syncthreads();   // (A) previous PV done with Vs/Pt

        // Load K (transposed) + V tiles
#pragma unroll
        for (int rep = 0; rep < 8; rep++) {
            const int d = lh + rep * 4;
            float4 kv = *(const float4*)&Kg[(rowbase + k0 + li) * D_MODEL + hoff + d];
            Kt[(d + 0) * 132 + li] = kv.x;
            Kt[(d + 1) * 132 + li] = kv.y;
            Kt[(d + 2) * 132 + li] = kv.z;
            Kt[(d + 3) * 132 + li] = kv.w;
            float4 vv = *(const float4*)&V[(rowbase + k0 + li) * D_MODEL + hoff + d];
            *(float4*)&Vs[li * 68 + d] = vv;
        }
        __syncthreads();   // (B)

        // S = Q @ K^T  (8 rows x 4 col-pairs per thread, FFMA2)
        ull s2[8][4];
#pragma unroll
        for (int i = 0; i < 8; i++)
#pragma unroll
            for (int j = 0; j < 4; j++) s2[i][j] = 0ull;

#pragma unroll 8
        for (int d = 0; d < 64; d++) {
            float4 alo = *(const float4*)&Qt[d * 132 + ty * 4];
            float4 ahi = *(const float4*)&Qt[d * 132 + 64 + ty * 4];
            ulonglong2 blo = *(const ulonglong2*)&Kt[d * 132 + tx * 4];
            ulonglong2 bhi = *(const ulonglong2*)&Kt[d * 132 + 64 + tx * 4];
            ull ad[8];
            ad[0] = dup2(alo.x); ad[1] = dup2(alo.y);
            ad[2] = dup2(alo.z); ad[3] = dup2(alo.w);
            ad[4] = dup2(ahi.x); ad[5] = dup2(ahi.y);
            ad[6] = dup2(ahi.z); ad[7] = dup2(ahi.w);
#pragma unroll
            for (int i = 0; i < 8; i++) {
                fma2(s2[i][0], ad[i], blo.x);
                fma2(s2[i][1], ad[i], blo.y);
                fma2(s2[i][2], ad[i], bhi.x);
                fma2(s2[i][3], ad[i], bhi.y);
            }
        }

        // Mask + store S transposed into Pt[col][row]
#pragma unroll
        for (int ii = 0; ii < 8; ii++) {
            const int qrow = ty * 4 + (ii & 3) + ((ii >> 2) * 64);
            const size_t mrow = ((size_t)b * N_SEQ + q0 + qrow) * N_SEQ;
            const size_t mo0 = mrow + k0 + tx * 4;
            const size_t mo1 = mrow + k0 + 64 + tx * 4;
            bool mz[8];
            if (mkind == 1) {
                int4 a = *(const int4*)((const int*)mask + mo0);
                int4 c = *(const int4*)((const int*)mask + mo1);
                mz[0] = a.x; mz[1] = a.y; mz[2] = a.z; mz[3] = a.w;
                mz[4] = c.x; mz[5] = c.y; mz[6] = c.z; mz[7] = c.w;
            } else if (mkind == 0) {
                uchar4 a = *(const uchar4*)((const unsigned char*)mask + mo0);
                uchar4 c = *(const uchar4*)((const unsigned char*)mask + mo1);
                mz[0] = a.x; mz[1] = a.y; mz[2] = a.z; mz[3] = a.w;
                mz[4] = c.x; mz[5] = c.y; mz[6] = c.z; mz[7] = c.w;
            } else {
                float4 a = *(const float4*)((const float*)mask + mo0);
                float4 c = *(const float4*)((const float*)mask + mo1);
                mz[0] = a.x != 0.f; mz[1] = a.y != 0.f; mz[2] = a.z != 0.f; mz[3] = a.w != 0.f;
                mz[4] = c.x != 0.f; mz[5] = c.y != 0.f; mz[6] = c.z != 0.f; mz[7] = c.w != 0.f;
            }
#pragma unroll
            for (int jp = 0; jp < 4; jp++) {
                const int c = tx * 4 + ((jp & 1) * 2) + ((jp >> 1) * 64);
                float2 p = unpack2(s2[ii][jp]);
                if (mz[(jp & 1) * 2 + ((jp >> 1) * 4) + 0]) p.x = -1.0e30f;
                if (mz[(jp & 1) * 2 + ((jp >> 1) * 4) + 1]) p.y = -1.0e30f;
                Pt[(c + 0) * 132 + qrow] = p.x;
                Pt[(c + 1) * 132 + qrow] = p.y;
            }
        }
        __syncthreads();   // (C)

        // Online softmax: 2 threads per row, 64 cols each
        {
            const int row  = tid >> 1;
            const int part = tid & 1;
            float mx = -3.0e38f;
#pragma unroll 16
            for (int t = 0; t < 64; t++)
                mx = fmaxf(mx, Pt[(part * 64 + t) * 132 + row]);
            mx = fmaxf(mx, __shfl_xor_sync(0xffffffffu, mx, 1));

            const float m_old = m_s[row];
            const float m_new = fmaxf(m_old, mx);

            float sum = 0.f;
#pragma unroll 16
            for (int t = 0; t < 64; t++) {
                const int j = part * 64 + t;
                float p = __expf(Pt[j * 132 + row] - m_new);
                Pt[j * 132 + row] = p;
                sum += p;
            }
            sum += __shfl_xor_sync(0xffffffffu, sum, 1);  // also syncs m_old reads

            if (part == 0) {
                const float f = __expf(m_old - m_new);
                l_s[row] = l_s[row] * f + sum;
                m_s[row] = m_new;
                f_s[row] = f;
            }
        }
        __syncthreads();   // (D)

        // Rescale + O += P @ V  (4 q rows x 4 d-pairs per thread)
#pragma unroll
        for (int r = 0; r < 4; r++) {
            ull fd = dup2(f_s[ty2 * 4 + r]);
#pragma unroll
            for (int dp = 0; dp < 4; dp++) mul2(oacc[r][dp], fd);
        }
#pragma unroll 8
        for (int j = 0; j < BK; j++) {
            float4 a = *(const float4*)&Pt[j * 132 + ty2 * 4];
            ulonglong2 v0 = *(const ulonglong2*)&Vs[j * 68 + tx2 * 8];
            ulonglong2 v1 = *(const ulonglong2*)&Vs[j * 68 + tx2 * 8 + 4];
            ull ad[4];
            ad[0] = dup2(a.x); ad[1] = dup2(a.y);
            ad[2] = dup2(a.z); ad[3] = dup2(a.w);
#pragma unroll
            for (int r = 0; r < 4; r++) {
                fma2(oacc[r][0], ad[r], v0.x);
                fma2(oacc[r][1], ad[r], v0.y);
                fma2(oacc[r][2], ad[r], v1.x);
                fma2(oacc[r][3], ad[r], v1.y);
            }
        }
    }

    // Normalize + store: rows ty2*4+r, cols hoff + tx2*8 .. +7
#pragma unroll
    for (int r = 0; r < 4; r++) {
        const float inv = 1.f / l_s[ty2 * 4 + r];
        float2 o0 = unpack2(oacc[r][0]);
        float2 o1 = unpack2(oacc[r][1]);
        float2 o2 = unpack2(oacc[r][2]);
        float2 o3 = unpack2(oacc[r][3]);
        float4 lo = make_float4(o0.x * inv, o0.y * inv, o1.x * inv, o1.y * inv);
        float4 hi = make_float4(o2.x * inv, o2.y * inv, o3.x * inv, o3.y * inv);
        float* dst = &O[(rowbase + q0 + ty2 * 4 + r) * D_MODEL + hoff + tx2 * 8];
        *(float4*)dst = lo;
        *(float4*)(dst + 4) = hi;
    }
}

// ---------------------------------------------------------------------------
extern "C" void kernel_launch(void* const* d_in, const int* in_sizes, int n_in,
                              void* d_out, int out_size)
{
    const float* q  = (const float*)d_in[0];
    const void*  mk = d_in[1];
    const float* Wq = (const float*)d_in[2];
    const float* Wk = (const float*)d_in[3];
    const float* Wv = (const float*)d_in[4];
    const float* Wo = (const float*)d_in[5];
    const float* bo = (const float*)d_in[6];
    float* out      = (float*)d_out;

    float *pq, *pk, *pv, *po;
    cudaGetSymbolAddress((void**)&pq, g_q);
    cudaGetSymbolAddress((void**)&pk, g_k);
    cudaGetSymbolAddress((void**)&pv, g_v);
    cudaGetSymbolAddress((void**)&po, g_o);

    detect_mask_kind<<<1, 256>>>((const unsigned char*)mk);

    dim3 ggrid(D_MODEL / 128, MTOT / 128);   // (8, 32)

    gemm_nt<<<ggrid, 256>>>(q, Wq, nullptr, pq, MTOT, D_MODEL, D_MODEL, QSCALE);
    gemm_nt<<<ggrid, 256>>>(q, Wk, nullptr, pk, MTOT, D_MODEL, D_MODEL, 1.0f);
    gemm_nt<<<ggrid, 256>>>(q, Wv, nullptr, pv, MTOT, D_MODEL, D_MODEL, 1.0f);

    const int smem_bytes = ATTN_SMEM_FLOATS * (int)sizeof(float);  // 171520
    cudaFuncSetAttribute(attn_kernel, cudaFuncAttributeMaxDynamicSharedMemorySize,
                         smem_bytes);
    attn_kernel<<<dim3(N_SEQ / BQ, BATCH * NHEADS), 256, smem_bytes>>>(
        pq, pk, pv, mk, po);

    gemm_nt<<<ggrid, 256>>>(po, Wo, bo, out, MTOT, D_MODEL, D_MODEL, 1.0f);
}

// round 5
// speedup vs baseline: 1.2091x; 1.1545x over previous
#include <cuda_runtime.h>
#include <cuda_bf16.h>
#include <math.h>
#include <stdint.h>

#define D_MODEL 1024
#define N_SEQ   2048
#define BATCH   2
#define NHEADS  16
#define DHEAD   64
#define QSCALE  0.125f
#define MTOT    (BATCH * N_SEQ)   // 4096

typedef unsigned long long ull;

// ---- packed f32x2 helpers (attention kernel) ----
__device__ __forceinline__ ull dup2(float v) {
    ull r;
    asm("mov.b64 %0, {%1, %1};" : "=l"(r) : "r"(__float_as_uint(v)));
    return r;
}
__device__ __forceinline__ float2 unpack2(ull v) {
    unsigned lo, hi;
    asm("mov.b64 {%0, %1}, %2;" : "=r"(lo), "=r"(hi) : "l"(v));
    return make_float2(__uint_as_float(lo), __uint_as_float(hi));
}
__device__ __forceinline__ void fma2(ull& d, ull a, ull b) {
    asm("fma.rn.f32x2 %0, %1, %2, %0;" : "+l"(d) : "l"(a), "l"(b));
}
__device__ __forceinline__ void mul2(ull& d, ull a) {
    asm("mul.rn.f32x2 %0, %0, %1;" : "+l"(d) : "l"(a));
}

// ---- mma.sync helpers (legal on plain compute_103) ----
__device__ __forceinline__ uint32_t smem_u32(const void* p) {
    uint32_t a;
    asm("{ .reg .u64 t; cvta.to.shared.u64 t, %1; cvt.u32.u64 %0, t; }"
        : "=r"(a) : "l"(p));
    return a;
}
__device__ __forceinline__ void ldsm_x4(uint32_t* r, uint32_t addr) {
    asm volatile("ldmatrix.sync.aligned.m8n8.x4.shared.b16 {%0,%1,%2,%3}, [%4];"
        : "=r"(r[0]), "=r"(r[1]), "=r"(r[2]), "=r"(r[3]) : "r"(addr));
}
__device__ __forceinline__ void mma_bf16(float* d, const uint32_t* a,
                                         const uint32_t* b) {
    asm volatile(
        "mma.sync.aligned.m16n8k16.row.col.f32.bf16.bf16.f32 "
        "{%0,%1,%2,%3}, {%4,%5,%6,%7}, {%8,%9}, {%0,%1,%2,%3};"
        : "+f"(d[0]), "+f"(d[1]), "+f"(d[2]), "+f"(d[3])
        : "r"(a[0]), "r"(a[1]), "r"(a[2]), "r"(a[3]), "r"(b[0]), "r"(b[1]));
}

// ---- scratch (device globals: allocation-guard-safe) ----
__device__ float g_q[MTOT * D_MODEL];
__device__ float g_k[MTOT * D_MODEL];
__device__ float g_v[MTOT * D_MODEL];
__device__ float g_o[MTOT * D_MODEL];
__device__ __nv_bfloat16 g_qhi[MTOT * D_MODEL];
__device__ __nv_bfloat16 g_qlo[MTOT * D_MODEL];
__device__ __nv_bfloat16 g_ohi[MTOT * D_MODEL];
__device__ __nv_bfloat16 g_olo[MTOT * D_MODEL];
__device__ __nv_bfloat16 g_whi[4][D_MODEL * D_MODEL];
__device__ __nv_bfloat16 g_wlo[4][D_MODEL * D_MODEL];
__device__ int g_mask_kind;

// ---------------------------------------------------------------------------
// Mask dtype detection (first 64KB scan; deterministic).
// ---------------------------------------------------------------------------
__global__ void detect_mask_kind(const unsigned char* __restrict__ m)
{
    __shared__ int s_maxb, s_nzoff;
    if (threadIdx.x == 0) { s_maxb = 0; s_nzoff = 0; }
    __syncthreads();
    int maxb = 0, nzoff = 0;
    for (int i = threadIdx.x; i < 65536; i += blockDim.x) {
        int v = m[i];
        if (v > maxb) maxb = v;
        if (v && (i & 3)) nzoff++;
    }
    atomicMax(&s_maxb, maxb);
    atomicAdd(&s_nzoff, nzoff);
    __syncthreads();
    if (threadIdx.x == 0)
        g_mask_kind = (s_maxb > 1) ? 2 : (s_nzoff ? 0 : 1);
}

// ---------------------------------------------------------------------------
// fp32 -> bf16 hi/lo split
// ---------------------------------------------------------------------------
__global__ __launch_bounds__(256) void split_bf16_kernel(
    const float* __restrict__ x, __nv_bfloat16* __restrict__ hi,
    __nv_bfloat16* __restrict__ lo, int n)
{
    int i = (blockIdx.x * 256 + threadIdx.x) * 4;
    if (i >= n) return;
    float4 v = *(const float4*)(x + i);
    __nv_bfloat16 h0 = __float2bfloat16(v.x);
    __nv_bfloat16 h1 = __float2bfloat16(v.y);
    __nv_bfloat16 h2 = __float2bfloat16(v.z);
    __nv_bfloat16 h3 = __float2bfloat16(v.w);
    __nv_bfloat16 l0 = __float2bfloat16(v.x - __bfloat162float(h0));
    __nv_bfloat16 l1 = __float2bfloat16(v.y - __bfloat162float(h1));
    __nv_bfloat16 l2 = __float2bfloat16(v.z - __bfloat162float(h2));
    __nv_bfloat16 l3 = __float2bfloat16(v.w - __bfloat162float(h3));
    uint2 ph, pl;
    ph.x = ((uint32_t)__bfloat16_as_ushort(h1) << 16) | __bfloat16_as_ushort(h0);
    ph.y = ((uint32_t)__bfloat16_as_ushort(h3) << 16) | __bfloat16_as_ushort(h2);
    pl.x = ((uint32_t)__bfloat16_as_ushort(l1) << 16) | __bfloat16_as_ushort(l0);
    pl.y = ((uint32_t)__bfloat16_as_ushort(l3) << 16) | __bfloat16_as_ushort(l2);
    *(uint2*)(hi + i) = ph;
    *(uint2*)(lo + i) = pl;
}

// ---------------------------------------------------------------------------
// mma.sync GEMM (NT): C[m][n] = alpha * sum_k A[m][k]*W[n][k] (+ bias[n])
// A,W as bf16 hi/lo splits, 3 MMA terms. CTA 128x128, BK=32, 8 warps @ 32x64.
// smem rows: 32 bf16 (64B) stored at 80B pitch -> conflict-free ldmatrix.
// ---------------------------------------------------------------------------
#define MBK    32
#define PITCH  80
#define TILE_B (128 * PITCH)          // 10240
#define SM_AHI 0
#define SM_ALO (1 * TILE_B)
#define SM_WHI (2 * TILE_B)
#define SM_WLO (3 * TILE_B)
#define GBUF   (4 * TILE_B)           // 40960 per buffer

__global__ __launch_bounds__(256) void gemm_mma(
    const __nv_bfloat16* __restrict__ Ahi, const __nv_bfloat16* __restrict__ Alo,
    const __nv_bfloat16* __restrict__ Whi, const __nv_bfloat16* __restrict__ Wlo,
    const float* __restrict__ bias, float* __restrict__ C,
    int M, int N, int K, float alpha)
{
    extern __shared__ char dsm[];
    const uint32_t sbase = smem_u32(dsm);

    const int tid  = threadIdx.x;
    const int wid  = tid >> 5;
    const int lane = tid & 31;
    const int wm   = wid & 3;          // 4 m-warps * 32 rows
    const int wn   = wid >> 2;         // 2 n-warps * 64 cols
    const int m0   = blockIdx.y * 128;
    const int n0   = blockIdx.x * 128;

    // ldmatrix lane addressing: quadrant q, row-in-quadrant rin
    const int q   = lane >> 3;
    const int rin = lane & 7;
    const uint32_t lmoff = (uint32_t)(((q & 1) * 8 + rin) * PITCH + (q >> 1) * 16);

    // loader: chunk ch covers row=ch>>2, 16B col chunk = ch&3 (2 chunks/thread/tile)
    const int ch0 = tid;               // and ch0+256
    const int lr0 = ch0 >> 2, lc0 = (ch0 & 3);
    const int lr1 = (ch0 + 256) >> 2, lc1 = ((ch0 + 256) & 3);

    const __nv_bfloat16* gA0 = Ahi + (size_t)(m0 + lr0) * K + lc0 * 8;
    const __nv_bfloat16* gA1 = Ahi + (size_t)(m0 + lr1) * K + lc1 * 8;
    const __nv_bfloat16* gAl0 = Alo + (size_t)(m0 + lr0) * K + lc0 * 8;
    const __nv_bfloat16* gAl1 = Alo + (size_t)(m0 + lr1) * K + lc1 * 8;
    const __nv_bfloat16* gW0 = Whi + (size_t)(n0 + lr0) * K + lc0 * 8;
    const __nv_bfloat16* gW1 = Whi + (size_t)(n0 + lr1) * K + lc1 * 8;
    const __nv_bfloat16* gWl0 = Wlo + (size_t)(n0 + lr0) * K + lc0 * 8;
    const __nv_bfloat16* gWl1 = Wlo + (size_t)(n0 + lr1) * K + lc1 * 8;
    const uint32_t s0 = lr0 * PITCH + lc0 * 16;
    const uint32_t s1 = lr1 * PITCH + lc1 * 16;

    float acc[2][8][4];
#pragma unroll
    for (int s = 0; s < 2; s++)
#pragma unroll
        for (int n = 0; n < 8; n++)
#pragma unroll
            for (int r = 0; r < 4; r++) acc[s][n][r] = 0.f;

    // preload kb=0 into buffer 0
    {
        char* tb = dsm;
        *(uint4*)(tb + SM_AHI + s0) = *(const uint4*)gA0;
        *(uint4*)(tb + SM_AHI + s1) = *(const uint4*)gA1;
        *(uint4*)(tb + SM_ALO + s0) = *(const uint4*)gAl0;
        *(uint4*)(tb + SM_ALO + s1) = *(const uint4*)gAl1;
        *(uint4*)(tb + SM_WHI + s0) = *(const uint4*)gW0;
        *(uint4*)(tb + SM_WHI + s1) = *(const uint4*)gW1;
        *(uint4*)(tb + SM_WLO + s0) = *(const uint4*)gWl0;
        *(uint4*)(tb + SM_WLO + s1) = *(const uint4*)gWl1;
    }
    __syncthreads();

    const int nkb = K / MBK;           // 32
    int buf = 0;
    for (int kb = 0; kb < nkb; kb++) {
        // prefetch next K-block to registers
        uint4 pf[8];
        const bool more = (kb + 1) < nkb;
        if (more) {
            const int ko = (kb + 1) * MBK;
            pf[0] = *(const uint4*)(gA0 + ko);
            pf[1] = *(const uint4*)(gA1 + ko);
            pf[2] = *(const uint4*)(gAl0 + ko);
            pf[3] = *(const uint4*)(gAl1 + ko);
            pf[4] = *(const uint4*)(gW0 + ko);
            pf[5] = *(const uint4*)(gW1 + ko);
            pf[6] = *(const uint4*)(gWl0 + ko);
            pf[7] = *(const uint4*)(gWl1 + ko);
        }

        const uint32_t tb32 = sbase + buf * GBUF;
        const uint32_t aoff = tb32 + (wm * 32) * PITCH + lmoff;
        const uint32_t woff = tb32 + (wn * 64) * PITCH + lmoff;

#pragma unroll
        for (int ks = 0; ks < 2; ks++) {
            const uint32_t kso = ks * 32;
            uint32_t ahi[2][4], alo[2][4];
#pragma unroll
            for (int s = 0; s < 2; s++) {
                ldsm_x4(ahi[s], aoff + SM_AHI + s * 16 * PITCH + kso);
                ldsm_x4(alo[s], aoff + SM_ALO + s * 16 * PITCH + kso);
            }
            uint32_t bhi[8][2], blo[8][2];
#pragma unroll
            for (int g = 0; g < 4; g++) {
                uint32_t r4[4];
                ldsm_x4(r4, woff + SM_WHI + g * 16 * PITCH + kso);
                bhi[2 * g][0] = r4[0]; bhi[2 * g][1] = r4[2];
                bhi[2 * g + 1][0] = r4[1]; bhi[2 * g + 1][1] = r4[3];
                ldsm_x4(r4, woff + SM_WLO + g * 16 * PITCH + kso);
                blo[2 * g][0] = r4[0]; blo[2 * g][1] = r4[2];
                blo[2 * g + 1][0] = r4[1]; blo[2 * g + 1][1] = r4[3];
            }
#pragma unroll
            for (int s = 0; s < 2; s++)
#pragma unroll
                for (int n = 0; n < 8; n++) {
                    mma_bf16(acc[s][n], ahi[s], bhi[n]);
                    mma_bf16(acc[s][n], ahi[s], blo[n]);
                    mma_bf16(acc[s][n], alo[s], bhi[n]);
                }
        }

        if (more) {
            char* tb = dsm + (buf ^ 1) * GBUF;
            *(uint4*)(tb + SM_AHI + s0) = pf[0];
            *(uint4*)(tb + SM_AHI + s1) = pf[1];
            *(uint4*)(tb + SM_ALO + s0) = pf[2];
            *(uint4*)(tb + SM_ALO + s1) = pf[3];
            *(uint4*)(tb + SM_WHI + s0) = pf[4];
            *(uint4*)(tb + SM_WHI + s1) = pf[5];
            *(uint4*)(tb + SM_WLO + s0) = pf[6];
            *(uint4*)(tb + SM_WLO + s1) = pf[7];
        }
        __syncthreads();
        buf ^= 1;
    }

    // epilogue
#pragma unroll
    for (int s = 0; s < 2; s++) {
        const int r0 = m0 + wm * 32 + s * 16 + (lane >> 2);
#pragma unroll
        for (int n = 0; n < 8; n++) {
            const int col = n0 + wn * 64 + n * 8 + (lane & 3) * 2;
            const float b0 = bias ? bias[col] : 0.f;
            const float b1 = bias ? bias[col + 1] : 0.f;
            float2 v0 = make_float2(alpha * acc[s][n][0] + b0,
                                    alpha * acc[s][n][1] + b1);
            float2 v1 = make_float2(alpha * acc[s][n][2] + b0,
                                    alpha * acc[s][n][3] + b1);
            *(float2*)&C[(size_t)r0 * N + col] = v0;
            *(float2*)&C[(size_t)(r0 + 8) * N + col] = v1;
        }
    }
}

// ---------------------------------------------------------------------------
// Flash-attention, 128x128 tiles, FFMA2, online softmax (R3 passing version).
// ---------------------------------------------------------------------------
#define BQ 128
#define BK 128
#define OFF_QT 0
#define OFF_KT (OFF_QT + 64 * 132)
#define OFF_VS (OFF_KT + 64 * 132)
#define OFF_PT (OFF_VS + 128 * 68)
#define OFF_MS (OFF_PT + 128 * 132)
#define OFF_LS (OFF_MS + 128)
#define OFF_FS (OFF_LS + 128)
#define ATTN_SMEM_FLOATS (OFF_FS + 128)

__global__ __launch_bounds__(256, 1) void attn_kernel(
    const float* __restrict__ Q, const float* __restrict__ Kg,
    const float* __restrict__ V, const void* __restrict__ mask,
    float* __restrict__ O)
{
    extern __shared__ float sm[];
    float* Qt  = sm + OFF_QT;
    float* Kt  = sm + OFF_KT;
    float* Vs  = sm + OFF_VS;
    float* Pt  = sm + OFF_PT;
    float* m_s = sm + OFF_MS;
    float* l_s = sm + OFF_LS;
    float* f_s = sm + OFF_FS;

    const int tid = threadIdx.x;
    const int tx  = tid & 15;
    const int ty  = tid >> 4;
    const int ty2 = tid >> 3;
    const int tx2 = tid & 7;
    const int li  = tid >> 1;
    const int lh  = (tid & 1) * 32;

    const int bh = blockIdx.y;
    const int b  = bh >> 4;
    const int h  = bh & 15;
    const int q0 = blockIdx.x * BQ;
    const size_t rowbase = (size_t)b * N_SEQ;
    const int hoff = h * DHEAD;
    const int mkind = g_mask_kind;

#pragma unroll
    for (int rep = 0; rep < 8; rep++) {
        const int d = lh + rep * 4;
        float4 v4 = *(const float4*)&Q[(rowbase + q0 + li) * D_MODEL + hoff + d];
        Qt[(d + 0) * 132 + li] = v4.x;
        Qt[(d + 1) * 132 + li] = v4.y;
        Qt[(d + 2) * 132 + li] = v4.z;
        Qt[(d + 3) * 132 + li] = v4.w;
    }
    if (tid < 128) { m_s[tid] = -3.0e38f; l_s[tid] = 0.f; }

    ull oacc[4][4];
#pragma unroll
    for (int i = 0; i < 4; i++)
#pragma unroll
        for (int j = 0; j < 4; j++) oacc[i][j] = 0ull;

    for (int k0 = 0; k0 < N_SEQ; k0 += BK) {
        __syncthreads();

#pragma unroll
        for (int rep = 0; rep < 8; rep++) {
            const int d = lh + rep * 4;
            float4 kv = *(const float4*)&Kg[(rowbase + k0 + li) * D_MODEL + hoff + d];
            Kt[(d + 0) * 132 + li] = kv.x;
            Kt[(d + 1) * 132 + li] = kv.y;
            Kt[(d + 2) * 132 + li] = kv.z;
            Kt[(d + 3) * 132 + li] = kv.w;
            float4 vv = *(const float4*)&V[(rowbase + k0 + li) * D_MODEL + hoff + d];
            *(float4*)&Vs[li * 68 + d] = vv;
        }
        __syncthreads();

        ull s2[8][4];
#pragma unroll
        for (int i = 0; i < 8; i++)
#pragma unroll
            for (int j = 0; j < 4; j++) s2[i][j] = 0ull;

#pragma unroll 8
        for (int d = 0; d < 64; d++) {
            float4 alo = *(const float4*)&Qt[d * 132 + ty * 4];
            float4 ahi = *(const float4*)&Qt[d * 132 + 64 + ty * 4];
            ulonglong2 blo = *(const ulonglong2*)&Kt[d * 132 + tx * 4];
            ulonglong2 bhi = *(const ulonglong2*)&Kt[d * 132 + 64 + tx * 4];
            ull ad[8];
            ad[0] = dup2(alo.x); ad[1] = dup2(alo.y);
            ad[2] = dup2(alo.z); ad[3] = dup2(alo.w);
            ad[4] = dup2(ahi.x); ad[5] = dup2(ahi.y);
            ad[6] = dup2(ahi.z); ad[7] = dup2(ahi.w);
#pragma unroll
            for (int i = 0; i < 8; i++) {
                fma2(s2[i][0], ad[i], blo.x);
                fma2(s2[i][1], ad[i], blo.y);
                fma2(s2[i][2], ad[i], bhi.x);
                fma2(s2[i][3], ad[i], bhi.y);
            }
        }

#pragma unroll
        for (int ii = 0; ii < 8; ii++) {
            const int qrow = ty * 4 + (ii & 3) + ((ii >> 2) * 64);
            const size_t mrow = ((size_t)b * N_SEQ + q0 + qrow) * N_SEQ;
            const size_t mo0 = mrow + k0 + tx * 4;
            const size_t mo1 = mrow + k0 + 64 + tx * 4;
            bool mz[8];
            if (mkind == 1) {
                int4 a = *(const int4*)((const int*)mask + mo0);
                int4 c = *(const int4*)((const int*)mask + mo1);
                mz[0] = a.x; mz[1] = a.y; mz[2] = a.z; mz[3] = a.w;
                mz[4] = c.x; mz[5] = c.y; mz[6] = c.z; mz[7] = c.w;
            } else if (mkind == 0) {
                uchar4 a = *(const uchar4*)((const unsigned char*)mask + mo0);
                uchar4 c = *(const uchar4*)((const unsigned char*)mask + mo1);
                mz[0] = a.x; mz[1] = a.y; mz[2] = a.z; mz[3] = a.w;
                mz[4] = c.x; mz[5] = c.y; mz[6] = c.z; mz[7] = c.w;
            } else {
                float4 a = *(const float4*)((const float*)mask + mo0);
                float4 c = *(const float4*)((const float*)mask + mo1);
                mz[0] = a.x != 0.f; mz[1] = a.y != 0.f; mz[2] = a.z != 0.f; mz[3] = a.w != 0.f;
                mz[4] = c.x != 0.f; mz[5] = c.y != 0.f; mz[6] = c.z != 0.f; mz[7] = c.w != 0.f;
            }
#pragma unroll
            for (int jp = 0; jp < 4; jp++) {
                const int c = tx * 4 + ((jp & 1) * 2) + ((jp >> 1) * 64);
                float2 p = unpack2(s2[ii][jp]);
                if (mz[(jp & 1) * 2 + ((jp >> 1) * 4) + 0]) p.x = -1.0e30f;
                if (mz[(jp & 1) * 2 + ((jp >> 1) * 4) + 1]) p.y = -1.0e30f;
                Pt[(c + 0) * 132 + qrow] = p.x;
                Pt[(c + 1) * 132 + qrow] = p.y;
            }
        }
        __syncthreads();

        {
            const int row  = tid >> 1;
            const int part = tid & 1;
            float mx = -3.0e38f;
#pragma unroll 16
            for (int t = 0; t < 64; t++)
                mx = fmaxf(mx, Pt[(part * 64 + t) * 132 + row]);
            mx = fmaxf(mx, __shfl_xor_sync(0xffffffffu, mx, 1));

            const float m_old = m_s[row];
            const float m_new = fmaxf(m_old, mx);

            float sum = 0.f;
#pragma unroll 16
            for (int t = 0; t < 64; t++) {
                const int j = part * 64 + t;
                float p = __expf(Pt[j * 132 + row] - m_new);
                Pt[j * 132 + row] = p;
                sum += p;
            }
            sum += __shfl_xor_sync(0xffffffffu, sum, 1);

            if (part == 0) {
                const float f = __expf(m_old - m_new);
                l_s[row] = l_s[row] * f + sum;
                m_s[row] = m_new;
                f_s[row] = f;
            }
        }
        __syncthreads();

#pragma unroll
        for (int r = 0; r < 4; r++) {
            ull fd = dup2(f_s[ty2 * 4 + r]);
#pragma unroll
            for (int dp = 0; dp < 4; dp++) mul2(oacc[r][dp], fd);
        }
#pragma unroll 8
        for (int j = 0; j < BK; j++) {
            float4 a = *(const float4*)&Pt[j * 132 + ty2 * 4];
            ulonglong2 v0 = *(const ulonglong2*)&Vs[j * 68 + tx2 * 8];
            ulonglong2 v1 = *(const ulonglong2*)&Vs[j * 68 + tx2 * 8 + 4];
            ull ad[4];
            ad[0] = dup2(a.x); ad[1] = dup2(a.y);
            ad[2] = dup2(a.z); ad[3] = dup2(a.w);
#pragma unroll
            for (int r = 0; r < 4; r++) {
                fma2(oacc[r][0], ad[r], v0.x);
                fma2(oacc[r][1], ad[r], v0.y);
                fma2(oacc[r][2], ad[r], v1.x);
                fma2(oacc[r][3], ad[r], v1.y);
            }
        }
    }

#pragma unroll
    for (int r = 0; r < 4; r++) {
        const float inv = 1.f / l_s[ty2 * 4 + r];
        float2 o0 = unpack2(oacc[r][0]);
        float2 o1 = unpack2(oacc[r][1]);
        float2 o2 = unpack2(oacc[r][2]);
        float2 o3 = unpack2(oacc[r][3]);
        float4 lo = make_float4(o0.x * inv, o0.y * inv, o1.x * inv, o1.y * inv);
        float4 hi = make_float4(o2.x * inv, o2.y * inv, o3.x * inv, o3.y * inv);
        float* dst = &O[(rowbase + q0 + ty2 * 4 + r) * D_MODEL + hoff + tx2 * 8];
        *(float4*)dst = lo;
        *(float4*)(dst + 4) = hi;
    }
}

// ---------------------------------------------------------------------------
extern "C" void kernel_launch(void* const* d_in, const int* in_sizes, int n_in,
                              void* d_out, int out_size)
{
    const float* q  = (const float*)d_in[0];
    const void*  mk = d_in[1];
    const float* Wq = (const float*)d_in[2];
    const float* Wk = (const float*)d_in[3];
    const float* Wv = (const float*)d_in[4];
    const float* Wo = (const float*)d_in[5];
    const float* bo = (const float*)d_in[6];
    float* out      = (float*)d_out;

    float *pq, *pk, *pv, *po;
    __nv_bfloat16 *qhi, *qlo, *ohi, *olo, *whi, *wlo;
    cudaGetSymbolAddress((void**)&pq, g_q);
    cudaGetSymbolAddress((void**)&pk, g_k);
    cudaGetSymbolAddress((void**)&pv, g_v);
    cudaGetSymbolAddress((void**)&po, g_o);
    cudaGetSymbolAddress((void**)&qhi, g_qhi);
    cudaGetSymbolAddress((void**)&qlo, g_qlo);
    cudaGetSymbolAddress((void**)&ohi, g_ohi);
    cudaGetSymbolAddress((void**)&olo, g_olo);
    cudaGetSymbolAddress((void**)&whi, g_whi);
    cudaGetSymbolAddress((void**)&wlo, g_wlo);

    detect_mask_kind<<<1, 256>>>((const unsigned char*)mk);

    const int nq = MTOT * D_MODEL;          // 4M
    const int nw = D_MODEL * D_MODEL;       // 1M
    split_bf16_kernel<<<nq / 1024, 256>>>(q, qhi, qlo, nq);
    split_bf16_kernel<<<nw / 1024, 256>>>(Wq, whi + 0 * nw, wlo + 0 * nw, nw);
    split_bf16_kernel<<<nw / 1024, 256>>>(Wk, whi + 1 * nw, wlo + 1 * nw, nw);
    split_bf16_kernel<<<nw / 1024, 256>>>(Wv, whi + 2 * nw, wlo + 2 * nw, nw);
    split_bf16_kernel<<<nw / 1024, 256>>>(Wo, whi + 3 * nw, wlo + 3 * nw, nw);

    const int gemm_smem = 2 * GBUF;          // 81920
    cudaFuncSetAttribute(gemm_mma, cudaFuncAttributeMaxDynamicSharedMemorySize,
                         gemm_smem);
    dim3 ggrid(D_MODEL / 128, MTOT / 128);   // (8, 32)

    gemm_mma<<<ggrid, 256, gemm_smem>>>(qhi, qlo, whi + 0 * nw, wlo + 0 * nw,
                                        nullptr, pq, MTOT, D_MODEL, D_MODEL, QSCALE);
    gemm_mma<<<ggrid, 256, gemm_smem>>>(qhi, qlo, whi + 1 * nw, wlo + 1 * nw,
                                        nullptr, pk, MTOT, D_MODEL, D_MODEL, 1.0f);
    gemm_mma<<<ggrid, 256, gemm_smem>>>(qhi, qlo, whi + 2 * nw, wlo + 2 * nw,
                                        nullptr, pv, MTOT, D_MODEL, D_MODEL, 1.0f);

    const int attn_smem = ATTN_SMEM_FLOATS * (int)sizeof(float);  // 171520
    cudaFuncSetAttribute(attn_kernel, cudaFuncAttributeMaxDynamicSharedMemorySize,
                         attn_smem);
    attn_kernel<<<dim3(N_SEQ / BQ, BATCH * NHEADS), 256, attn_smem>>>(
        pq, pk, pv, mk, po);

    split_bf16_kernel<<<nq / 1024, 256>>>(po, ohi, olo, nq);
    gemm_mma<<<ggrid, 256, gemm_smem>>>(ohi, olo, whi + 3 * nw, wlo + 3 * nw,
                                        bo, out, MTOT, D_MODEL, D_MODEL, 1.0f);
}

// round 7
// speedup vs baseline: 2.4626x; 2.0367x over previous
#include <cuda_runtime.h>
#include <cuda_bf16.h>
#include <math.h>
#include <stdint.h>

#define D_MODEL 1024
#define N_SEQ   2048
#define BATCH   2
#define NHEADS  16
#define DHEAD   64
#define QSCALE  0.125f
#define MTOT    (BATCH * N_SEQ)   // 4096
#define NEGINF  -1.0e30f

// ---- mma.sync helpers (legal on plain compute_103) ----
__device__ __forceinline__ uint32_t smem_u32(const void* p) {
    uint32_t a;
    asm("{ .reg .u64 t; cvta.to.shared.u64 t, %1; cvt.u32.u64 %0, t; }"
        : "=r"(a) : "l"(p));
    return a;
}
__device__ __forceinline__ void ldsm_x4(uint32_t* r, uint32_t addr) {
    asm volatile("ldmatrix.sync.aligned.m8n8.x4.shared.b16 {%0,%1,%2,%3}, [%4];"
        : "=r"(r[0]), "=r"(r[1]), "=r"(r[2]), "=r"(r[3]) : "r"(addr));
}
__device__ __forceinline__ void ldsm_x4_t(uint32_t* r, uint32_t addr) {
    asm volatile("ldmatrix.sync.aligned.m8n8.x4.trans.shared.b16 {%0,%1,%2,%3}, [%4];"
        : "=r"(r[0]), "=r"(r[1]), "=r"(r[2]), "=r"(r[3]) : "r"(addr));
}
__device__ __forceinline__ void mma_bf16(float* d, const uint32_t* a,
                                         const uint32_t* b) {
    asm volatile(
        "mma.sync.aligned.m16n8k16.row.col.f32.bf16.bf16.f32 "
        "{%0,%1,%2,%3}, {%4,%5,%6,%7}, {%8,%9}, {%0,%1,%2,%3};"
        : "+f"(d[0]), "+f"(d[1]), "+f"(d[2]), "+f"(d[3])
        : "r"(a[0]), "r"(a[1]), "r"(a[2]), "r"(a[3]), "r"(b[0]), "r"(b[1]));
}
// pack two f32 -> bf16x2 (lo in low half)
__device__ __forceinline__ uint32_t pack_bf16(float lo, float hi) {
    uint32_t d;
    asm("cvt.rn.bf16x2.f32 %0, %1, %2;" : "=r"(d) : "f"(hi), "f"(lo));
    return d;
}
// split (v0,v1) into bf16 hi-pair and lo-pair (residual)
__device__ __forceinline__ void split_pack(float v0, float v1,
                                           uint32_t& h, uint32_t& l) {
    h = pack_bf16(v0, v1);
    float h0 = __uint_as_float(h << 16);
    float h1 = __uint_as_float(h & 0xffff0000u);
    l = pack_bf16(v0 - h0, v1 - h1);
}
#define CP16(dst, src) \
    asm volatile("cp.async.cg.shared.global [%0], [%1], 16;" \
                 :: "r"(dst), "l"(src) : "memory")
#define CP_COMMIT() asm volatile("cp.async.commit_group;" ::: "memory")
#define CP_WAIT0()  asm volatile("cp.async.wait_group 0;" ::: "memory")

// ---- scratch (device globals: allocation-guard-safe) ----
__device__ __nv_bfloat16 g_inhi[MTOT * D_MODEL];
__device__ __nv_bfloat16 g_inlo[MTOT * D_MODEL];
__device__ __nv_bfloat16 g_Qhi[MTOT * D_MODEL];
__device__ __nv_bfloat16 g_Qlo[MTOT * D_MODEL];
__device__ __nv_bfloat16 g_Khi[MTOT * D_MODEL];
__device__ __nv_bfloat16 g_Klo[MTOT * D_MODEL];
__device__ __nv_bfloat16 g_Vhi[MTOT * D_MODEL];
__device__ __nv_bfloat16 g_Vlo[MTOT * D_MODEL];
__device__ __nv_bfloat16 g_Ohi[MTOT * D_MODEL];
__device__ __nv_bfloat16 g_Olo[MTOT * D_MODEL];
__device__ __nv_bfloat16 g_whi[4][D_MODEL * D_MODEL];
__device__ __nv_bfloat16 g_wlo[4][D_MODEL * D_MODEL];
__device__ int g_mask_kind;

// ---------------------------------------------------------------------------
// Mask dtype detection (first 64KB scan; deterministic).
// ---------------------------------------------------------------------------
__global__ void detect_mask_kind(const unsigned char* __restrict__ m)
{
    __shared__ int s_maxb, s_nzoff;
    if (threadIdx.x == 0) { s_maxb = 0; s_nzoff = 0; }
    __syncthreads();
    int maxb = 0, nzoff = 0;
    for (int i = threadIdx.x; i < 65536; i += blockDim.x) {
        int v = m[i];
        if (v > maxb) maxb = v;
        if (v && (i & 3)) nzoff++;
    }
    atomicMax(&s_maxb, maxb);
    atomicAdd(&s_nzoff, nzoff);
    __syncthreads();
    if (threadIdx.x == 0)
        g_mask_kind = (s_maxb > 1) ? 2 : (s_nzoff ? 0 : 1);
}

// ---------------------------------------------------------------------------
// fp32 -> bf16 hi/lo split
// ---------------------------------------------------------------------------
__global__ __launch_bounds__(256) void split_bf16_kernel(
    const float* __restrict__ x, __nv_bfloat16* __restrict__ hi,
    __nv_bfloat16* __restrict__ lo, int n)
{
    int i = (blockIdx.x * 256 + threadIdx.x) * 4;
    if (i >= n) return;
    float4 v = *(const float4*)(x + i);
    uint32_t h0, l0, h1, l1;
    split_pack(v.x, v.y, h0, l0);
    split_pack(v.z, v.w, h1, l1);
    *(uint2*)(hi + i) = make_uint2(h0, h1);
    *(uint2*)(lo + i) = make_uint2(l0, l1);
}

// ---------------------------------------------------------------------------
// mma.sync GEMM (NT): out = alpha * A*W^T (+bias). A,W bf16 hi/lo, 3 terms.
// CTA 128x128, BK=32, 8 warps @ 32x64. Output: fp32 (Cf) or bf16 split.
// ---------------------------------------------------------------------------
#define MBK    32
#define PITCH  80
#define TILE_B (128 * PITCH)          // 10240
#define SM_AHI 0
#define SM_ALO (1 * TILE_B)
#define SM_WHI (2 * TILE_B)
#define SM_WLO (3 * TILE_B)
#define GBUF   (4 * TILE_B)           // 40960 per buffer

__global__ __launch_bounds__(256) void gemm_mma(
    const __nv_bfloat16* __restrict__ Ahi, const __nv_bfloat16* __restrict__ Alo,
    const __nv_bfloat16* __restrict__ Whi, const __nv_bfloat16* __restrict__ Wlo,
    const float* __restrict__ bias, float* __restrict__ Cf,
    __nv_bfloat16* __restrict__ Chi, __nv_bfloat16* __restrict__ Clo,
    int M, int N, int K, float alpha)
{
    extern __shared__ char dsm[];
    const uint32_t sbase = smem_u32(dsm);

    const int tid  = threadIdx.x;
    const int wid  = tid >> 5;
    const int lane = tid & 31;
    const int wm   = wid & 3;
    const int wn   = wid >> 2;
    const int m0   = blockIdx.y * 128;
    const int n0   = blockIdx.x * 128;

    const int q   = lane >> 3;
    const int rin = lane & 7;
    const uint32_t lmoff = (uint32_t)(((q & 1) * 8 + rin) * PITCH + (q >> 1) * 16);

    const int ch0 = tid;
    const int lr0 = ch0 >> 2, lc0 = (ch0 & 3);
    const int lr1 = (ch0 + 256) >> 2, lc1 = ((ch0 + 256) & 3);

    const __nv_bfloat16* gA0 = Ahi + (size_t)(m0 + lr0) * K + lc0 * 8;
    const __nv_bfloat16* gA1 = Ahi + (size_t)(m0 + lr1) * K + lc1 * 8;
    const __nv_bfloat16* gAl0 = Alo + (size_t)(m0 + lr0) * K + lc0 * 8;
    const __nv_bfloat16* gAl1 = Alo + (size_t)(m0 + lr1) * K + lc1 * 8;
    const __nv_bfloat16* gW0 = Whi + (size_t)(n0 + lr0) * K + lc0 * 8;
    const __nv_bfloat16* gW1 = Whi + (size_t)(n0 + lr1) * K + lc1 * 8;
    const __nv_bfloat16* gWl0 = Wlo + (size_t)(n0 + lr0) * K + lc0 * 8;
    const __nv_bfloat16* gWl1 = Wlo + (size_t)(n0 + lr1) * K + lc1 * 8;
    const uint32_t s0 = lr0 * PITCH + lc0 * 16;
    const uint32_t s1 = lr1 * PITCH + lc1 * 16;

    float acc[2][8][4];
#pragma unroll
    for (int s = 0; s < 2; s++)
#pragma unroll
        for (int n = 0; n < 8; n++)
#pragma unroll
            for (int r = 0; r < 4; r++) acc[s][n][r] = 0.f;

    {
        char* tb = dsm;
        *(uint4*)(tb + SM_AHI + s0) = *(const uint4*)gA0;
        *(uint4*)(tb + SM_AHI + s1) = *(const uint4*)gA1;
        *(uint4*)(tb + SM_ALO + s0) = *(const uint4*)gAl0;
        *(uint4*)(tb + SM_ALO + s1) = *(const uint4*)gAl1;
        *(uint4*)(tb + SM_WHI + s0) = *(const uint4*)gW0;
        *(uint4*)(tb + SM_WHI + s1) = *(const uint4*)gW1;
        *(uint4*)(tb + SM_WLO + s0) = *(const uint4*)gWl0;
        *(uint4*)(tb + SM_WLO + s1) = *(const uint4*)gWl1;
    }
    __syncthreads();

    const int nkb = K / MBK;
    int buf = 0;
    for (int kb = 0; kb < nkb; kb++) {
        uint4 pf[8];
        const bool more = (kb + 1) < nkb;
        if (more) {
            const int ko = (kb + 1) * MBK;
            pf[0] = *(const uint4*)(gA0 + ko);
            pf[1] = *(const uint4*)(gA1 + ko);
            pf[2] = *(const uint4*)(gAl0 + ko);
            pf[3] = *(const uint4*)(gAl1 + ko);
            pf[4] = *(const uint4*)(gW0 + ko);
            pf[5] = *(const uint4*)(gW1 + ko);
            pf[6] = *(const uint4*)(gWl0 + ko);
            pf[7] = *(const uint4*)(gWl1 + ko);
        }

        const uint32_t tb32 = sbase + buf * GBUF;
        const uint32_t aoff = tb32 + (wm * 32) * PITCH + lmoff;
        const uint32_t woff = tb32 + (wn * 64) * PITCH + lmoff;

#pragma unroll
        for (int ks = 0; ks < 2; ks++) {
            const uint32_t kso = ks * 32;
            uint32_t ahi[2][4], alo[2][4];
#pragma unroll
            for (int s = 0; s < 2; s++) {
                ldsm_x4(ahi[s], aoff + SM_AHI + s * 16 * PITCH + kso);
                ldsm_x4(alo[s], aoff + SM_ALO + s * 16 * PITCH + kso);
            }
            uint32_t bhi[8][2], blo[8][2];
#pragma unroll
            for (int g = 0; g < 4; g++) {
                uint32_t r4[4];
                ldsm_x4(r4, woff + SM_WHI + g * 16 * PITCH + kso);
                bhi[2 * g][0] = r4[0]; bhi[2 * g][1] = r4[2];
                bhi[2 * g + 1][0] = r4[1]; bhi[2 * g + 1][1] = r4[3];
                ldsm_x4(r4, woff + SM_WLO + g * 16 * PITCH + kso);
                blo[2 * g][0] = r4[0]; blo[2 * g][1] = r4[2];
                blo[2 * g + 1][0] = r4[1]; blo[2 * g + 1][1] = r4[3];
            }
#pragma unroll
            for (int s = 0; s < 2; s++)
#pragma unroll
                for (int n = 0; n < 8; n++) {
                    mma_bf16(acc[s][n], ahi[s], bhi[n]);
                    mma_bf16(acc[s][n], ahi[s], blo[n]);
                    mma_bf16(acc[s][n], alo[s], bhi[n]);
                }
        }

        if (more) {
            char* tb = dsm + (buf ^ 1) * GBUF;
            *(uint4*)(tb + SM_AHI + s0) = pf[0];
            *(uint4*)(tb + SM_AHI + s1) = pf[1];
            *(uint4*)(tb + SM_ALO + s0) = pf[2];
            *(uint4*)(tb + SM_ALO + s1) = pf[3];
            *(uint4*)(tb + SM_WHI + s0) = pf[4];
            *(uint4*)(tb + SM_WHI + s1) = pf[5];
            *(uint4*)(tb + SM_WLO + s0) = pf[6];
            *(uint4*)(tb + SM_WLO + s1) = pf[7];
        }
        __syncthreads();
        buf ^= 1;
    }

#pragma unroll
    for (int s = 0; s < 2; s++) {
        const int r0 = m0 + wm * 32 + s * 16 + (lane >> 2);
#pragma unroll
        for (int n = 0; n < 8; n++) {
            const int col = n0 + wn * 64 + n * 8 + (lane & 3) * 2;
            const float b0 = bias ? bias[col] : 0.f;
            const float b1 = bias ? bias[col + 1] : 0.f;
            const float v0 = alpha * acc[s][n][0] + b0;
            const float v1 = alpha * acc[s][n][1] + b1;
            const float v2 = alpha * acc[s][n][2] + b0;
            const float v3 = alpha * acc[s][n][3] + b1;
            if (Cf) {
                *(float2*)&Cf[(size_t)r0 * N + col] = make_float2(v0, v1);
                *(float2*)&Cf[(size_t)(r0 + 8) * N + col] = make_float2(v2, v3);
            } else {
                uint32_t h, l;
                split_pack(v0, v1, h, l);
                *(uint32_t*)&Chi[(size_t)r0 * N + col] = h;
                *(uint32_t*)&Clo[(size_t)r0 * N + col] = l;
                split_pack(v2, v3, h, l);
                *(uint32_t*)&Chi[(size_t)(r0 + 8) * N + col] = h;
                *(uint32_t*)&Clo[(size_t)(r0 + 8) * N + col] = l;
            }
        }
    }
}

// ---------------------------------------------------------------------------
// Tensor-core flash attention. Block: 256 thr (8 warps), q-tile 128, k-tile 128.
// Warp w owns q rows w*16..w*16+15 -> softmax state fully in registers.
// QK^T and P*V via 3-term bf16 hi/lo mma.sync. K/V smem double-buffered cp.async.
// ---------------------------------------------------------------------------
#define APB    144                   // smem row pitch bytes (64 bf16 + pad)
#define KTILE  (128 * APB)           // 18432
#define S_KHI  0
#define S_KLO  (1 * KTILE)
#define S_VHI  (2 * KTILE)
#define S_VLO  (3 * KTILE)
#define ABUF   (4 * KTILE)           // 73728 per buffer

__global__ __launch_bounds__(256) void attn_mma(
    const __nv_bfloat16* __restrict__ Qhi, const __nv_bfloat16* __restrict__ Qlo,
    const __nv_bfloat16* __restrict__ Khi, const __nv_bfloat16* __restrict__ Klo,
    const __nv_bfloat16* __restrict__ Vhi, const __nv_bfloat16* __restrict__ Vlo,
    const void* __restrict__ mask,
    __nv_bfloat16* __restrict__ Ohi, __nv_bfloat16* __restrict__ Olo)
{
    extern __shared__ char smemb[];
    const uint32_t sb = smem_u32(smemb);

    const int tid  = threadIdx.x;
    const int warp = tid >> 5;
    const int lane = tid & 31;
    const int gq   = lane >> 2;       // quad group = row within fragment
    const int tig  = lane & 3;
    const int q8   = lane >> 3;
    const int rin  = lane & 7;
    const uint32_t lmoff = (uint32_t)(((q8 & 1) * 8 + rin) * APB + (q8 >> 1) * 16);
    const int wrow = warp * 16;

    const int bh = blockIdx.y;
    const int b  = bh >> 4;
    const int h  = bh & 15;
    const int q0 = blockIdx.x * 128;
    const size_t rowbase = (size_t)b * N_SEQ;
    const int hoff = h * DHEAD;
    const int mkind = g_mask_kind;

    // ---- stage Q tile into buf0 K area, build register Q fragments ----
#pragma unroll
    for (int i = 0; i < 4; i++) {
        const int c = tid + 256 * i;
        const int row = c >> 3, colc = c & 7;
        const size_t src = (rowbase + q0 + row) * D_MODEL + hoff + colc * 8;
        *(uint4*)(smemb + S_KHI + row * APB + colc * 16) = *(const uint4*)(Qhi + src);
        *(uint4*)(smemb + S_KLO + row * APB + colc * 16) = *(const uint4*)(Qlo + src);
    }
    __syncthreads();
    uint32_t aQh[4][4], aQl[4][4];
#pragma unroll
    for (int ks = 0; ks < 4; ks++) {
        ldsm_x4(aQh[ks], sb + S_KHI + wrow * APB + lmoff + ks * 32);
        ldsm_x4(aQl[ks], sb + S_KLO + wrow * APB + lmoff + ks * 32);
    }
    __syncthreads();

    float oacc[8][4];
#pragma unroll
    for (int n = 0; n < 8; n++)
#pragma unroll
        for (int r = 0; r < 4; r++) oacc[n][r] = 0.f;
    float mrow0 = NEGINF, mrow1 = NEGINF, lrow0 = 0.f, lrow1 = 0.f;

    // ---- prefetch k-tile 0 ----
#define ISSUE_TILES(kt, bo) do {                                              \
    _Pragma("unroll")                                                         \
    for (int i = 0; i < 4; i++) {                                             \
        const int c = tid + 256 * i;                                          \
        const int row = c >> 3, colc = c & 7;                                 \
        const size_t src = (rowbase + (kt) * 128 + row) * D_MODEL + hoff + colc * 8; \
        const uint32_t dst = sb + (bo) + row * APB + colc * 16;               \
        CP16(dst + S_KHI, Khi + src);                                         \
        CP16(dst + S_KLO, Klo + src);                                         \
        CP16(dst + S_VHI, Vhi + src);                                         \
        CP16(dst + S_VLO, Vlo + src);                                         \
    }                                                                         \
} while (0)

    uint32_t bo = 0;
    ISSUE_TILES(0, 0);
    CP_COMMIT();

    const size_t mrowb = ((size_t)b * N_SEQ + q0 + wrow + gq) * N_SEQ + 2 * tig;

    for (int kt = 0; kt < 16; kt++) {
        CP_WAIT0();
        __syncthreads();
        if (kt < 15) { ISSUE_TILES(kt + 1, bo ^ ABUF); CP_COMMIT(); }

        // ---- S = Q K^T (3-term) ----
        float sc[16][4];
#pragma unroll
        for (int n = 0; n < 16; n++)
#pragma unroll
            for (int r = 0; r < 4; r++) sc[n][r] = 0.f;

#pragma unroll
        for (int ks = 0; ks < 4; ks++) {
#pragma unroll
            for (int g2 = 0; g2 < 8; g2++) {
                uint32_t rh[4], rl[4];
                const uint32_t ka = sb + bo + g2 * 16 * APB + lmoff + ks * 32;
                ldsm_x4(rh, ka + S_KHI);
                ldsm_x4(rl, ka + S_KLO);
                uint32_t b0h[2] = {rh[0], rh[2]}, b1h[2] = {rh[1], rh[3]};
                uint32_t b0l[2] = {rl[0], rl[2]}, b1l[2] = {rl[1], rl[3]};
                mma_bf16(sc[2 * g2], aQh[ks], b0h);
                mma_bf16(sc[2 * g2], aQh[ks], b0l);
                mma_bf16(sc[2 * g2], aQl[ks], b0h);
                mma_bf16(sc[2 * g2 + 1], aQh[ks], b1h);
                mma_bf16(sc[2 * g2 + 1], aQh[ks], b1l);
                mma_bf16(sc[2 * g2 + 1], aQl[ks], b1h);
            }
        }

        // ---- mask ----
        const size_t m0i = mrowb + kt * 128;
        const size_t m1i = m0i + 8 * N_SEQ;
        if (mkind == 1) {
            const int* mp = (const int*)mask;
#pragma unroll
            for (int n = 0; n < 16; n++) {
                int2 a = *(const int2*)(mp + m0i + 8 * n);
                int2 c = *(const int2*)(mp + m1i + 8 * n);
                if (a.x) sc[n][0] = NEGINF;
                if (a.y) sc[n][1] = NEGINF;
                if (c.x) sc[n][2] = NEGINF;
                if (c.y) sc[n][3] = NEGINF;
            }
        } else if (mkind == 0) {
            const unsigned char* mp = (const unsigned char*)mask;
#pragma unroll
            for (int n = 0; n < 16; n++) {
                uchar2 a = *(const uchar2*)(mp + m0i + 8 * n);
                uchar2 c = *(const uchar2*)(mp + m1i + 8 * n);
                if (a.x) sc[n][0] = NEGINF;
                if (a.y) sc[n][1] = NEGINF;
                if (c.x) sc[n][2] = NEGINF;
                if (c.y) sc[n][3] = NEGINF;
            }
        } else {
            const float* mp = (const float*)mask;
#pragma unroll
            for (int n = 0; n < 16; n++) {
                float2 a = *(const float2*)(mp + m0i + 8 * n);
                float2 c = *(const float2*)(mp + m1i + 8 * n);
                if (a.x != 0.f) sc[n][0] = NEGINF;
                if (a.y != 0.f) sc[n][1] = NEGINF;
                if (c.x != 0.f) sc[n][2] = NEGINF;
                if (c.y != 0.f) sc[n][3] = NEGINF;
            }
        }

        // ---- online softmax (register + quad shuffle) ----
        float mx0 = NEGINF, mx1 = NEGINF;
#pragma unroll
        for (int n = 0; n < 16; n++) {
            mx0 = fmaxf(mx0, fmaxf(sc[n][0], sc[n][1]));
            mx1 = fmaxf(mx1, fmaxf(sc[n][2], sc[n][3]));
        }
        mx0 = fmaxf(mx0, __shfl_xor_sync(0xffffffffu, mx0, 1));
        mx0 = fmaxf(mx0, __shfl_xor_sync(0xffffffffu, mx0, 2));
        mx1 = fmaxf(mx1, __shfl_xor_sync(0xffffffffu, mx1, 1));
        mx1 = fmaxf(mx1, __shfl_xor_sync(0xffffffffu, mx1, 2));

        const float mn0 = fmaxf(mrow0, mx0);
        const float mn1 = fmaxf(mrow1, mx1);
        const float f0 = __expf(mrow0 - mn0);
        const float f1 = __expf(mrow1 - mn1);

        float sum0 = 0.f, sum1 = 0.f;
#pragma unroll
        for (int n = 0; n < 16; n++) {
            sc[n][0] = __expf(sc[n][0] - mn0); sum0 += sc[n][0];
            sc[n][1] = __expf(sc[n][1] - mn0); sum0 += sc[n][1];
            sc[n][2] = __expf(sc[n][2] - mn1); sum1 += sc[n][2];
            sc[n][3] = __expf(sc[n][3] - mn1); sum1 += sc[n][3];
        }
        sum0 += __shfl_xor_sync(0xffffffffu, sum0, 1);
        sum0 += __shfl_xor_sync(0xffffffffu, sum0, 2);
        sum1 += __shfl_xor_sync(0xffffffffu, sum1, 1);
        sum1 += __shfl_xor_sync(0xffffffffu, sum1, 2);

        lrow0 = lrow0 * f0 + sum0; mrow0 = mn0;
        lrow1 = lrow1 * f1 + sum1; mrow1 = mn1;
#pragma unroll
        for (int n = 0; n < 8; n++) {
            oacc[n][0] *= f0; oacc[n][1] *= f0;
            oacc[n][2] *= f1; oacc[n][3] *= f1;
        }

        // ---- O += P V (3-term; P from registers, V via ldmatrix.trans) ----
#pragma unroll
        for (int kk = 0; kk < 8; kk++) {
            uint32_t aPh[4], aPl[4];
            split_pack(sc[2 * kk][0], sc[2 * kk][1], aPh[0], aPl[0]);
            split_pack(sc[2 * kk][2], sc[2 * kk][3], aPh[1], aPl[1]);
            split_pack(sc[2 * kk + 1][0], sc[2 * kk + 1][1], aPh[2], aPl[2]);
            split_pack(sc[2 * kk + 1][2], sc[2 * kk + 1][3], aPh[3], aPl[3]);
#pragma unroll
            for (int g2 = 0; g2 < 4; g2++) {
                uint32_t rh[4], rl[4];
                const uint32_t va = sb + bo + kk * 16 * APB + lmoff + g2 * 32;
                ldsm_x4_t(rh, va + S_VHI);
                ldsm_x4_t(rl, va + S_VLO);
                uint32_t b0h[2] = {rh[0], rh[1]}, b1h[2] = {rh[2], rh[3]};
                uint32_t b0l[2] = {rl[0], rl[1]}, b1l[2] = {rl[2], rl[3]};
                mma_bf16(oacc[2 * g2], aPh, b0h);
                mma_bf16(oacc[2 * g2], aPh, b0l);
                mma_bf16(oacc[2 * g2], aPl, b0h);
                mma_bf16(oacc[2 * g2 + 1], aPh, b1h);
                mma_bf16(oacc[2 * g2 + 1], aPh, b1l);
                mma_bf16(oacc[2 * g2 + 1], aPl, b1h);
            }
        }
        bo ^= ABUF;
    }

    // ---- normalize + write bf16 hi/lo ----
    const float inv0 = 1.f / lrow0;
    const float inv1 = 1.f / lrow1;
    const size_t orow0 = (rowbase + q0 + wrow + gq) * D_MODEL + hoff;
    const size_t orow1 = orow0 + 8 * D_MODEL;
#pragma unroll
    for (int n = 0; n < 8; n++) {
        const int col = 8 * n + 2 * tig;
        uint32_t hh, ll;
        split_pack(oacc[n][0] * inv0, oacc[n][1] * inv0, hh, ll);
        *(uint32_t*)&Ohi[orow0 + col] = hh;
        *(uint32_t*)&Olo[orow0 + col] = ll;
        split_pack(oacc[n][2] * inv1, oacc[n][3] * inv1, hh, ll);
        *(uint32_t*)&Ohi[orow1 + col] = hh;
        *(uint32_t*)&Olo[orow1 + col] = ll;
    }
}

// ---------------------------------------------------------------------------
extern "C" void kernel_launch(void* const* d_in, const int* in_sizes, int n_in,
                              void* d_out, int out_size)
{
    const float* q  = (const float*)d_in[0];
    const void*  mk = d_in[1];
    const float* Wq = (const float*)d_in[2];
    const float* Wk = (const float*)d_in[3];
    const float* Wv = (const float*)d_in[4];
    const float* Wo = (const float*)d_in[5];
    const float* bo = (const float*)d_in[6];
    float* out      = (float*)d_out;

    __nv_bfloat16 *inhi, *inlo, *Qhi, *Qlo, *Khi, *Klo, *Vhi, *Vlo, *Ohi, *Olo,
        *whi, *wlo;
    cudaGetSymbolAddress((void**)&inhi, g_inhi);
    cudaGetSymbolAddress((void**)&inlo, g_inlo);
    cudaGetSymbolAddress((void**)&Qhi, g_Qhi);
    cudaGetSymbolAddress((void**)&Qlo, g_Qlo);
    cudaGetSymbolAddress((void**)&Khi, g_Khi);
    cudaGetSymbolAddress((void**)&Klo, g_Klo);
    cudaGetSymbolAddress((void**)&Vhi, g_Vhi);
    cudaGetSymbolAddress((void**)&Vlo, g_Vlo);
    cudaGetSymbolAddress((void**)&Ohi, g_Ohi);
    cudaGetSymbolAddress((void**)&Olo, g_Olo);
    cudaGetSymbolAddress((void**)&whi, g_whi);
    cudaGetSymbolAddress((void**)&wlo, g_wlo);

    detect_mask_kind<<<1, 256>>>((const unsigned char*)mk);

    const int nq = MTOT * D_MODEL;
    const int nw = D_MODEL * D_MODEL;
    split_bf16_kernel<<<nq / 1024, 256>>>(q, inhi, inlo, nq);
    split_bf16_kernel<<<nw / 1024, 256>>>(Wq, whi + 0 * nw, wlo + 0 * nw, nw);
    split_bf16_kernel<<<nw / 1024, 256>>>(Wk, whi + 1 * nw, wlo + 1 * nw, nw);
    split_bf16_kernel<<<nw / 1024, 256>>>(Wv, whi + 2 * nw, wlo + 2 * nw, nw);
    split_bf16_kernel<<<nw / 1024, 256>>>(Wo, whi + 3 * nw, wlo + 3 * nw, nw);

    const int gemm_smem = 2 * GBUF;
    cudaFuncSetAttribute(gemm_mma, cudaFuncAttributeMaxDynamicSharedMemorySize,
                         gemm_smem);
    dim3 ggrid(D_MODEL / 128, MTOT / 128);

    gemm_mma<<<ggrid, 256, gemm_smem>>>(inhi, inlo, whi + 0 * nw, wlo + 0 * nw,
                                        nullptr, nullptr, Qhi, Qlo,
                                        MTOT, D_MODEL, D_MODEL, QSCALE);
    gemm_mma<<<ggrid, 256, gemm_smem>>>(inhi, inlo, whi + 1 * nw, wlo + 1 * nw,
                                        nullptr, nullptr, Khi, Klo,
                                        MTOT, D_MODEL, D_MODEL, 1.0f);
    gemm_mma<<<ggrid, 256, gemm_smem>>>(inhi, inlo, whi + 2 * nw, wlo + 2 * nw,
                                        nullptr, nullptr, Vhi, Vlo,
                                        MTOT, D_MODEL, D_MODEL, 1.0f);

    const int attn_smem = 2 * ABUF;   // 147456
    cudaFuncSetAttribute(attn_mma, cudaFuncAttributeMaxDynamicSharedMemorySize,
                         attn_smem);
    attn_mma<<<dim3(N_SEQ / 128, BATCH * NHEADS), 256, attn_smem>>>(
        Qhi, Qlo, Khi, Klo, Vhi, Vlo, mk, Ohi, Olo);

    gemm_mma<<<ggrid, 256, gemm_smem>>>(Ohi, Olo, whi + 3 * nw, wlo + 3 * nw,
                                        bo, out, nullptr, nullptr,
                                        MTOT, D_MODEL, D_MODEL, 1.0f);
}

// round 8
// speedup vs baseline: 2.7855x; 1.1311x over previous
#include <cuda_runtime.h>
#include <cuda_bf16.h>
#include <math.h>
#include <stdint.h>

#define D_MODEL 1024
#define N_SEQ   2048
#define BATCH   2
#define NHEADS  16
#define DHEAD   64
#define QSCALE  0.125f
#define MTOT    (BATCH * N_SEQ)   // 4096
#define NEGINF  -1.0e30f
typedef __nv_bfloat16 bf16;

// ---- mma.sync helpers ----
__device__ __forceinline__ uint32_t smem_u32(const void* p) {
    uint32_t a;
    asm("{ .reg .u64 t; cvta.to.shared.u64 t, %1; cvt.u32.u64 %0, t; }"
        : "=r"(a) : "l"(p));
    return a;
}
__device__ __forceinline__ void ldsm_x4(uint32_t* r, uint32_t addr) {
    asm volatile("ldmatrix.sync.aligned.m8n8.x4.shared.b16 {%0,%1,%2,%3}, [%4];"
        : "=r"(r[0]), "=r"(r[1]), "=r"(r[2]), "=r"(r[3]) : "r"(addr));
}
__device__ __forceinline__ void ldsm_x4_t(uint32_t* r, uint32_t addr) {
    asm volatile("ldmatrix.sync.aligned.m8n8.x4.trans.shared.b16 {%0,%1,%2,%3}, [%4];"
        : "=r"(r[0]), "=r"(r[1]), "=r"(r[2]), "=r"(r[3]) : "r"(addr));
}
__device__ __forceinline__ void mma_bf16(float* d, const uint32_t* a,
                                         const uint32_t* b) {
    asm volatile(
        "mma.sync.aligned.m16n8k16.row.col.f32.bf16.bf16.f32 "
        "{%0,%1,%2,%3}, {%4,%5,%6,%7}, {%8,%9}, {%0,%1,%2,%3};"
        : "+f"(d[0]), "+f"(d[1]), "+f"(d[2]), "+f"(d[3])
        : "r"(a[0]), "r"(a[1]), "r"(a[2]), "r"(a[3]), "r"(b[0]), "r"(b[1]));
}
__device__ __forceinline__ uint32_t pack_bf16(float lo, float hi) {
    uint32_t d;
    asm("cvt.rn.bf16x2.f32 %0, %1, %2;" : "=r"(d) : "f"(hi), "f"(lo));
    return d;
}
__device__ __forceinline__ void split_pack(float v0, float v1,
                                           uint32_t& h, uint32_t& l) {
    h = pack_bf16(v0, v1);
    float h0 = __uint_as_float(h << 16);
    float h1 = __uint_as_float(h & 0xffff0000u);
    l = pack_bf16(v0 - h0, v1 - h1);
}
#define CP16(dst, src) \
    asm volatile("cp.async.cg.shared.global [%0], [%1], 16;" \
                 :: "r"(dst), "l"(src) : "memory")
#define CP_COMMIT() asm volatile("cp.async.commit_group;" ::: "memory")
#define CP_WAIT0()  asm volatile("cp.async.wait_group 0;" ::: "memory")

// ---- scratch (device globals) ----
__device__ bf16 g_inhi[MTOT * D_MODEL];
__device__ bf16 g_inlo[MTOT * D_MODEL];
__device__ bf16 g_Qhi[MTOT * D_MODEL];
__device__ bf16 g_Qlo[MTOT * D_MODEL];
__device__ bf16 g_Khi[MTOT * D_MODEL];
__device__ bf16 g_Klo[MTOT * D_MODEL];
__device__ bf16 g_Vhi[MTOT * D_MODEL];
__device__ bf16 g_Vlo[MTOT * D_MODEL];
__device__ bf16 g_Ohi[MTOT * D_MODEL];
__device__ bf16 g_Olo[MTOT * D_MODEL];
__device__ bf16 g_whi[4][D_MODEL * D_MODEL];
__device__ bf16 g_wlo[4][D_MODEL * D_MODEL];
__device__ int g_mask_kind;

// ---------------------------------------------------------------------------
__global__ void detect_mask_kind(const unsigned char* __restrict__ m)
{
    __shared__ int s_maxb, s_nzoff;
    if (threadIdx.x == 0) { s_maxb = 0; s_nzoff = 0; }
    __syncthreads();
    int maxb = 0, nzoff = 0;
    for (int i = threadIdx.x; i < 65536; i += blockDim.x) {
        int v = m[i];
        if (v > maxb) maxb = v;
        if (v && (i & 3)) nzoff++;
    }
    atomicMax(&s_maxb, maxb);
    atomicAdd(&s_nzoff, nzoff);
    __syncthreads();
    if (threadIdx.x == 0)
        g_mask_kind = (s_maxb > 1) ? 2 : (s_nzoff ? 0 : 1);
}

// ---------------------------------------------------------------------------
__global__ __launch_bounds__(256) void split_bf16_kernel(
    const float* __restrict__ x, bf16* __restrict__ hi,
    bf16* __restrict__ lo, int n)
{
    int i = (blockIdx.x * 256 + threadIdx.x) * 4;
    if (i >= n) return;
    float4 v = *(const float4*)(x + i);
    uint32_t h0, l0, h1, l1;
    split_pack(v.x, v.y, h0, l0);
    split_pack(v.z, v.w, h1, l1);
    *(uint2*)(hi + i) = make_uint2(h0, h1);
    *(uint2*)(lo + i) = make_uint2(l0, l1);
}

// ---------------------------------------------------------------------------
// GEMM body (NT): out = alpha*A*W^T (+bias). bf16 hi/lo 3-term, cp.async
// double-buffered. CTA 128x128, BK=32, 8 warps @ 32x64.
// ---------------------------------------------------------------------------
#define MBK    32
#define PITCH  80
#define TILE_B (128 * PITCH)          // 10240
#define SM_AHI 0
#define SM_ALO (1 * TILE_B)
#define SM_WHI (2 * TILE_B)
#define SM_WLO (3 * TILE_B)
#define GBUF   (4 * TILE_B)           // 40960 per buffer

__device__ __forceinline__ void gemm_body(
    const bf16* __restrict__ Ahi, const bf16* __restrict__ Alo,
    const bf16* __restrict__ Whi, const bf16* __restrict__ Wlo,
    const float* __restrict__ bias, float* __restrict__ Cf,
    bf16* __restrict__ Chi, bf16* __restrict__ Clo,
    int N, int K, float alpha, char* dsm)
{
    const uint32_t sbase = smem_u32(dsm);
    const int tid  = threadIdx.x;
    const int wid  = tid >> 5;
    const int lane = tid & 31;
    const int wm   = wid & 3;
    const int wn   = wid >> 2;
    const int m0   = blockIdx.y * 128;
    const int n0   = blockIdx.x * 128;

    const int q8  = lane >> 3;
    const int rin = lane & 7;
    const uint32_t lmoff = (uint32_t)(((q8 & 1) * 8 + rin) * PITCH + (q8 >> 1) * 16);

    // loader: 512 chunks (16B) per tensor -> 2 per thread
    const int lr0 = tid >> 2, lc0 = tid & 3;
    const int lr1 = (tid + 256) >> 2, lc1 = (tid + 256) & 3;
    const bf16* gA0  = Ahi + (size_t)(m0 + lr0) * K + lc0 * 8;
    const bf16* gA1  = Ahi + (size_t)(m0 + lr1) * K + lc1 * 8;
    const bf16* gAl0 = Alo + (size_t)(m0 + lr0) * K + lc0 * 8;
    const bf16* gAl1 = Alo + (size_t)(m0 + lr1) * K + lc1 * 8;
    const bf16* gW0  = Whi + (size_t)(n0 + lr0) * K + lc0 * 8;
    const bf16* gW1  = Whi + (size_t)(n0 + lr1) * K + lc1 * 8;
    const bf16* gWl0 = Wlo + (size_t)(n0 + lr0) * K + lc0 * 8;
    const bf16* gWl1 = Wlo + (size_t)(n0 + lr1) * K + lc1 * 8;
    const uint32_t s0 = lr0 * PITCH + lc0 * 16;
    const uint32_t s1 = lr1 * PITCH + lc1 * 16;

#define G_ISSUE(kb, bufo) do {                                                \
    const int _ko = (kb) * MBK;                                               \
    const uint32_t _d = sbase + (bufo);                                       \
    CP16(_d + SM_AHI + s0, gA0 + _ko);  CP16(_d + SM_AHI + s1, gA1 + _ko);    \
    CP16(_d + SM_ALO + s0, gAl0 + _ko); CP16(_d + SM_ALO + s1, gAl1 + _ko);   \
    CP16(_d + SM_WHI + s0, gW0 + _ko);  CP16(_d + SM_WHI + s1, gW1 + _ko);    \
    CP16(_d + SM_WLO + s0, gWl0 + _ko); CP16(_d + SM_WLO + s1, gWl1 + _ko);   \
} while (0)

    float acc[2][8][4];
#pragma unroll
    for (int s = 0; s < 2; s++)
#pragma unroll
        for (int n = 0; n < 8; n++)
#pragma unroll
            for (int r = 0; r < 4; r++) acc[s][n][r] = 0.f;

    G_ISSUE(0, 0);
    CP_COMMIT();

    const int nkb = K / MBK;
    uint32_t bufo = 0;
    for (int kb = 0; kb < nkb; kb++) {
        CP_WAIT0();
        __syncthreads();
        if (kb + 1 < nkb) { G_ISSUE(kb + 1, bufo ^ GBUF); CP_COMMIT(); }

        const uint32_t tb32 = sbase + bufo;
        const uint32_t aoff = tb32 + (wm * 32) * PITCH + lmoff;
        const uint32_t woff = tb32 + (wn * 64) * PITCH + lmoff;

#pragma unroll
        for (int ks = 0; ks < 2; ks++) {
            const uint32_t kso = ks * 32;
            uint32_t ahi[2][4], alo[2][4];
#pragma unroll
            for (int s = 0; s < 2; s++) {
                ldsm_x4(ahi[s], aoff + SM_AHI + s * 16 * PITCH + kso);
                ldsm_x4(alo[s], aoff + SM_ALO + s * 16 * PITCH + kso);
            }
#pragma unroll
            for (int g = 0; g < 4; g++) {
                uint32_t rh[4], rl[4];
                ldsm_x4(rh, woff + SM_WHI + g * 16 * PITCH + kso);
                ldsm_x4(rl, woff + SM_WLO + g * 16 * PITCH + kso);
                uint32_t b0h[2] = {rh[0], rh[2]}, b1h[2] = {rh[1], rh[3]};
                uint32_t b0l[2] = {rl[0], rl[2]}, b1l[2] = {rl[1], rl[3]};
#pragma unroll
                for (int s = 0; s < 2; s++) {
                    mma_bf16(acc[s][2 * g], ahi[s], b0h);
                    mma_bf16(acc[s][2 * g], ahi[s], b0l);
                    mma_bf16(acc[s][2 * g], alo[s], b0h);
                    mma_bf16(acc[s][2 * g + 1], ahi[s], b1h);
                    mma_bf16(acc[s][2 * g + 1], ahi[s], b1l);
                    mma_bf16(acc[s][2 * g + 1], alo[s], b1h);
                }
            }
        }
        __syncthreads();
        bufo ^= GBUF;
    }

#pragma unroll
    for (int s = 0; s < 2; s++) {
        const int r0 = m0 + wm * 32 + s * 16 + (lane >> 2);
#pragma unroll
        for (int n = 0; n < 8; n++) {
            const int col = n0 + wn * 64 + n * 8 + (lane & 3) * 2;
            const float b0 = bias ? bias[col] : 0.f;
            const float b1 = bias ? bias[col + 1] : 0.f;
            const float v0 = alpha * acc[s][n][0] + b0;
            const float v1 = alpha * acc[s][n][1] + b1;
            const float v2 = alpha * acc[s][n][2] + b0;
            const float v3 = alpha * acc[s][n][3] + b1;
            if (Cf) {
                *(float2*)&Cf[(size_t)r0 * N + col] = make_float2(v0, v1);
                *(float2*)&Cf[(size_t)(r0 + 8) * N + col] = make_float2(v2, v3);
            } else {
                uint32_t h, l;
                split_pack(v0, v1, h, l);
                *(uint32_t*)&Chi[(size_t)r0 * N + col] = h;
                *(uint32_t*)&Clo[(size_t)r0 * N + col] = l;
                split_pack(v2, v3, h, l);
                *(uint32_t*)&Chi[(size_t)(r0 + 8) * N + col] = h;
                *(uint32_t*)&Clo[(size_t)(r0 + 8) * N + col] = l;
            }
        }
    }
#undef G_ISSUE
}

// Fused Q/K/V projection: blockIdx.z selects weight + output.
__global__ __launch_bounds__(256, 2) void gemm_qkv(
    const bf16* __restrict__ inhi, const bf16* __restrict__ inlo,
    const bf16* __restrict__ whi, const bf16* __restrict__ wlo,
    bf16* __restrict__ Qhi, bf16* __restrict__ Qlo,
    bf16* __restrict__ Khi, bf16* __restrict__ Klo,
    bf16* __restrict__ Vhi, bf16* __restrict__ Vlo)
{
    extern __shared__ char dsm[];
    const int z = blockIdx.z;
    const int nw = D_MODEL * D_MODEL;
    const bf16* Whi = whi + (size_t)z * nw;
    const bf16* Wlo = wlo + (size_t)z * nw;
    bf16* Chi = (z == 0) ? Qhi : (z == 1) ? Khi : Vhi;
    bf16* Clo = (z == 0) ? Qlo : (z == 1) ? Klo : Vlo;
    const float alpha = (z == 0) ? QSCALE : 1.0f;
    gemm_body(inhi, inlo, Whi, Wlo, nullptr, nullptr, Chi, Clo,
              D_MODEL, D_MODEL, alpha, dsm);
}

// Output projection: fp32 + bias.
__global__ __launch_bounds__(256, 2) void gemm_out(
    const bf16* __restrict__ Ahi, const bf16* __restrict__ Alo,
    const bf16* __restrict__ Whi, const bf16* __restrict__ Wlo,
    const float* __restrict__ bias, float* __restrict__ Cf)
{
    extern __shared__ char dsm[];
    gemm_body(Ahi, Alo, Whi, Wlo, bias, Cf, nullptr, nullptr,
              D_MODEL, D_MODEL, 1.0f, dsm);
}

// ---------------------------------------------------------------------------
// Tensor-core flash attention, k-tile 64 (2 CTAs/SM), q-tile 128.
// Warp w owns q rows w*16..w*16+15; softmax fully in registers.
// ---------------------------------------------------------------------------
#define APB    144
#define KTROWS 64
#define KREG   (KTROWS * APB)         // 9216
#define S_KHI  0
#define S_KLO  (1 * KREG)
#define S_VHI  (2 * KREG)
#define S_VLO  (3 * KREG)
#define ABUF   (4 * KREG)             // 36864 per buffer
#define NKT    (N_SEQ / KTROWS)       // 32

__global__ __launch_bounds__(256, 2) void attn_mma(
    const bf16* __restrict__ Qhi, const bf16* __restrict__ Qlo,
    const bf16* __restrict__ Khi, const bf16* __restrict__ Klo,
    const bf16* __restrict__ Vhi, const bf16* __restrict__ Vlo,
    const void* __restrict__ mask,
    bf16* __restrict__ Ohi, bf16* __restrict__ Olo)
{
    extern __shared__ char smemb[];
    const uint32_t sb = smem_u32(smemb);

    const int tid  = threadIdx.x;
    const int warp = tid >> 5;
    const int lane = tid & 31;
    const int gq   = lane >> 2;
    const int tig  = lane & 3;
    const int q8   = lane >> 3;
    const int rin  = lane & 7;
    const uint32_t lmoff = (uint32_t)(((q8 & 1) * 8 + rin) * APB + (q8 >> 1) * 16);
    const int wrow = warp * 16;

    const int bh = blockIdx.y;
    const int b  = bh >> 4;
    const int h  = bh & 15;
    const int q0 = blockIdx.x * 128;
    const size_t rowbase = (size_t)b * N_SEQ;
    const int hoff = h * DHEAD;
    const int mkind = g_mask_kind;

    // ---- stage Q (128 rows) across buf0/buf1 KHI/KLO areas ----
#pragma unroll
    for (int i = 0; i < 4; i++) {
        const int c = tid + 256 * i;            // 0..1023
        const int row = c >> 3, colc = c & 7;   // row 0..127
        const size_t src = (rowbase + q0 + row) * D_MODEL + hoff + colc * 8;
        const uint32_t off = (row >= 64 ? ABUF : 0) + (row & 63) * APB + colc * 16;
        *(uint4*)(smemb + S_KHI + off) = *(const uint4*)(Qhi + src);
        *(uint4*)(smemb + S_KLO + off) = *(const uint4*)(Qlo + src);
    }
    __syncthreads();
    uint32_t aQh[4][4], aQl[4][4];
    {
        const uint32_t qb = sb + (wrow >= 64 ? ABUF : 0) + (wrow & 63) * APB + lmoff;
#pragma unroll
        for (int ks = 0; ks < 4; ks++) {
            ldsm_x4(aQh[ks], qb + S_KHI + ks * 32);
            ldsm_x4(aQl[ks], qb + S_KLO + ks * 32);
        }
    }
    __syncthreads();

    float oacc[8][4];
#pragma unroll
    for (int n = 0; n < 8; n++)
#pragma unroll
        for (int r = 0; r < 4; r++) oacc[n][r] = 0.f;
    float mrow0 = NEGINF, mrow1 = NEGINF, lrow0 = 0.f, lrow1 = 0.f;

#define ISSUE_TILES(kt, bo) do {                                              \
    _Pragma("unroll")                                                         \
    for (int i = 0; i < 2; i++) {                                             \
        const int c = tid + 256 * i;                                          \
        const int row = c >> 3, colc = c & 7;                                 \
        const size_t src = (rowbase + (kt) * KTROWS + row) * D_MODEL + hoff + colc * 8; \
        const uint32_t dst = sb + (bo) + row * APB + colc * 16;               \
        CP16(dst + S_KHI, Khi + src);                                         \
        CP16(dst + S_KLO, Klo + src);                                         \
        CP16(dst + S_VHI, Vhi + src);                                         \
        CP16(dst + S_VLO, Vlo + src);                                         \
    }                                                                         \
} while (0)

    uint32_t bo = 0;
    ISSUE_TILES(0, 0);
    CP_COMMIT();

    const size_t mrowb = ((size_t)b * N_SEQ + q0 + wrow + gq) * N_SEQ + 2 * tig;

    for (int kt = 0; kt < NKT; kt++) {
        CP_WAIT0();
        __syncthreads();
        if (kt + 1 < NKT) { ISSUE_TILES(kt + 1, bo ^ ABUF); CP_COMMIT(); }

        // ---- S = Q K^T (3-term) ----
        float sc[8][4];
#pragma unroll
        for (int n = 0; n < 8; n++)
#pragma unroll
            for (int r = 0; r < 4; r++) sc[n][r] = 0.f;

#pragma unroll
        for (int ks = 0; ks < 4; ks++) {
#pragma unroll
            for (int g2 = 0; g2 < 4; g2++) {
                uint32_t rh[4], rl[4];
                const uint32_t ka = sb + bo + g2 * 16 * APB + lmoff + ks * 32;
                ldsm_x4(rh, ka + S_KHI);
                ldsm_x4(rl, ka + S_KLO);
                uint32_t b0h[2] = {rh[0], rh[2]}, b1h[2] = {rh[1], rh[3]};
                uint32_t b0l[2] = {rl[0], rl[2]}, b1l[2] = {rl[1], rl[3]};
                mma_bf16(sc[2 * g2], aQh[ks], b0h);
                mma_bf16(sc[2 * g2], aQh[ks], b0l);
                mma_bf16(sc[2 * g2], aQl[ks], b0h);
                mma_bf16(sc[2 * g2 + 1], aQh[ks], b1h);
                mma_bf16(sc[2 * g2 + 1], aQh[ks], b1l);
                mma_bf16(sc[2 * g2 + 1], aQl[ks], b1h);
            }
        }

        // ---- mask ----
        const size_t m0i = mrowb + (size_t)kt * KTROWS;
        const size_t m1i = m0i + 8 * N_SEQ;
        if (mkind == 1) {
            const int* mp = (const int*)mask;
#pragma unroll
            for (int n = 0; n < 8; n++) {
                int2 a = *(const int2*)(mp + m0i + 8 * n);
                int2 c = *(const int2*)(mp + m1i + 8 * n);
                if (a.x) sc[n][0] = NEGINF;
                if (a.y) sc[n][1] = NEGINF;
                if (c.x) sc[n][2] = NEGINF;
                if (c.y) sc[n][3] = NEGINF;
            }
        } else if (mkind == 0) {
            const unsigned char* mp = (const unsigned char*)mask;
#pragma unroll
            for (int n = 0; n < 8; n++) {
                uchar2 a = *(const uchar2*)(mp + m0i + 8 * n);
                uchar2 c = *(const uchar2*)(mp + m1i + 8 * n);
                if (a.x) sc[n][0] = NEGINF;
                if (a.y) sc[n][1] = NEGINF;
                if (c.x) sc[n][2] = NEGINF;
                if (c.y) sc[n][3] = NEGINF;
            }
        } else {
            const float* mp = (const float*)mask;
#pragma unroll
            for (int n = 0; n < 8; n++) {
                float2 a = *(const float2*)(mp + m0i + 8 * n);
                float2 c = *(const float2*)(mp + m1i + 8 * n);
                if (a.x != 0.f) sc[n][0] = NEGINF;
                if (a.y != 0.f) sc[n][1] = NEGINF;
                if (c.x != 0.f) sc[n][2] = NEGINF;
                if (c.y != 0.f) sc[n][3] = NEGINF;
            }
        }

        // ---- online softmax ----
        float mx0 = NEGINF, mx1 = NEGINF;
#pragma unroll
        for (int n = 0; n < 8; n++) {
            mx0 = fmaxf(mx0, fmaxf(sc[n][0], sc[n][1]));
            mx1 = fmaxf(mx1, fmaxf(sc[n][2], sc[n][3]));
        }
        mx0 = fmaxf(mx0, __shfl_xor_sync(0xffffffffu, mx0, 1));
        mx0 = fmaxf(mx0, __shfl_xor_sync(0xffffffffu, mx0, 2));
        mx1 = fmaxf(mx1, __shfl_xor_sync(0xffffffffu, mx1, 1));
        mx1 = fmaxf(mx1, __shfl_xor_sync(0xffffffffu, mx1, 2));

        const float mn0 = fmaxf(mrow0, mx0);
        const float mn1 = fmaxf(mrow1, mx1);
        const float f0 = __expf(mrow0 - mn0);
        const float f1 = __expf(mrow1 - mn1);

        float sum0 = 0.f, sum1 = 0.f;
#pragma unroll
        for (int n = 0; n < 8; n++) {
            sc[n][0] = __expf(sc[n][0] - mn0); sum0 += sc[n][0];
            sc[n][1] = __expf(sc[n][1] - mn0); sum0 += sc[n][1];
            sc[n][2] = __expf(sc[n][2] - mn1); sum1 += sc[n][2];
            sc[n][3] = __expf(sc[n][3] - mn1); sum1 += sc[n][3];
        }
        sum0 += __shfl_xor_sync(0xffffffffu, sum0, 1);
        sum0 += __shfl_xor_sync(0xffffffffu, sum0, 2);
        sum1 += __shfl_xor_sync(0xffffffffu, sum1, 1);
        sum1 += __shfl_xor_sync(0xffffffffu, sum1, 2);

        lrow0 = lrow0 * f0 + sum0; mrow0 = mn0;
        lrow1 = lrow1 * f1 + sum1; mrow1 = mn1;
#pragma unroll
        for (int n = 0; n < 8; n++) {
            oacc[n][0] *= f0; oacc[n][1] *= f0;
            oacc[n][2] *= f1; oacc[n][3] *= f1;
        }

        // ---- O += P V ----
#pragma unroll
        for (int kk = 0; kk < 4; kk++) {
            uint32_t aPh[4], aPl[4];
            split_pack(sc[2 * kk][0], sc[2 * kk][1], aPh[0], aPl[0]);
            split_pack(sc[2 * kk][2], sc[2 * kk][3], aPh[1], aPl[1]);
            split_pack(sc[2 * kk + 1][0], sc[2 * kk + 1][1], aPh[2], aPl[2]);
            split_pack(sc[2 * kk + 1][2], sc[2 * kk + 1][3], aPh[3], aPl[3]);
#pragma unroll
            for (int g2 = 0; g2 < 4; g2++) {
                uint32_t rh[4], rl[4];
                const uint32_t va = sb + bo + kk * 16 * APB + lmoff + g2 * 32;
                ldsm_x4_t(rh, va + S_VHI);
                ldsm_x4_t(rl, va + S_VLO);
                uint32_t b0h[2] = {rh[0], rh[1]}, b1h[2] = {rh[2], rh[3]};
                uint32_t b0l[2] = {rl[0], rl[1]}, b1l[2] = {rl[2], rl[3]};
                mma_bf16(oacc[2 * g2], aPh, b0h);
                mma_bf16(oacc[2 * g2], aPh, b0l);
                mma_bf16(oacc[2 * g2], aPl, b0h);
                mma_bf16(oacc[2 * g2 + 1], aPh, b1h);
                mma_bf16(oacc[2 * g2 + 1], aPh, b1l);
                mma_bf16(oacc[2 * g2 + 1], aPl, b1h);
            }
        }
        bo ^= ABUF;
    }

    // ---- normalize + write ----
    const float inv0 = 1.f / lrow0;
    const float inv1 = 1.f / lrow1;
    const size_t orow0 = (rowbase + q0 + wrow + gq) * D_MODEL + hoff;
    const size_t orow1 = orow0 + 8 * D_MODEL;
#pragma unroll
    for (int n = 0; n < 8; n++) {
        const int col = 8 * n + 2 * tig;
        uint32_t hh, ll;
        split_pack(oacc[n][0] * inv0, oacc[n][1] * inv0, hh, ll);
        *(uint32_t*)&Ohi[orow0 + col] = hh;
        *(uint32_t*)&Olo[orow0 + col] = ll;
        split_pack(oacc[n][2] * inv1, oacc[n][3] * inv1, hh, ll);
        *(uint32_t*)&Ohi[orow1 + col] = hh;
        *(uint32_t*)&Olo[orow1 + col] = ll;
    }
}

// ---------------------------------------------------------------------------
extern "C" void kernel_launch(void* const* d_in, const int* in_sizes, int n_in,
                              void* d_out, int out_size)
{
    const float* q  = (const float*)d_in[0];
    const void*  mk = d_in[1];
    const float* Wq = (const float*)d_in[2];
    const float* Wk = (const float*)d_in[3];
    const float* Wv = (const float*)d_in[4];
    const float* Wo = (const float*)d_in[5];
    const float* bo = (const float*)d_in[6];
    float* out      = (float*)d_out;

    bf16 *inhi, *inlo, *Qhi, *Qlo, *Khi, *Klo, *Vhi, *Vlo, *Ohi, *Olo, *whi, *wlo;
    cudaGetSymbolAddress((void**)&inhi, g_inhi);
    cudaGetSymbolAddress((void**)&inlo, g_inlo);
    cudaGetSymbolAddress((void**)&Qhi, g_Qhi);
    cudaGetSymbolAddress((void**)&Qlo, g_Qlo);
    cudaGetSymbolAddress((void**)&Khi, g_Khi);
    cudaGetSymbolAddress((void**)&Klo, g_Klo);
    cudaGetSymbolAddress((void**)&Vhi, g_Vhi);
    cudaGetSymbolAddress((void**)&Vlo, g_Vlo);
    cudaGetSymbolAddress((void**)&Ohi, g_Ohi);
    cudaGetSymbolAddress((void**)&Olo, g_Olo);
    cudaGetSymbolAddress((void**)&whi, g_whi);
    cudaGetSymbolAddress((void**)&wlo, g_wlo);

    detect_mask_kind<<<1, 256>>>((const unsigned char*)mk);

    const int nq = MTOT * D_MODEL;
    const int nw = D_MODEL * D_MODEL;
    split_bf16_kernel<<<nq / 1024, 256>>>(q, inhi, inlo, nq);
    split_bf16_kernel<<<nw / 1024, 256>>>(Wq, whi + 0 * nw, wlo + 0 * nw, nw);
    split_bf16_kernel<<<nw / 1024, 256>>>(Wk, whi + 1 * nw, wlo + 1 * nw, nw);
    split_bf16_kernel<<<nw / 1024, 256>>>(Wv, whi + 2 * nw, wlo + 2 * nw, nw);
    split_bf16_kernel<<<nw / 1024, 256>>>(Wo, whi + 3 * nw, wlo + 3 * nw, nw);

    const int gemm_smem = 2 * GBUF;   // 81920
    cudaFuncSetAttribute(gemm_qkv, cudaFuncAttributeMaxDynamicSharedMemorySize,
                         gemm_smem);
    cudaFuncSetAttribute(gemm_out, cudaFuncAttributeMaxDynamicSharedMemorySize,
                         gemm_smem);

    gemm_qkv<<<dim3(D_MODEL / 128, MTOT / 128, 3), 256, gemm_smem>>>(
        inhi, inlo, whi, wlo, Qhi, Qlo, Khi, Klo, Vhi, Vlo);

    const int attn_smem = 2 * ABUF;   // 73728
    cudaFuncSetAttribute(attn_mma, cudaFuncAttributeMaxDynamicSharedMemorySize,
                         attn_smem);
    attn_mma<<<dim3(N_SEQ / 128, BATCH * NHEADS), 256, attn_smem>>>(
        Qhi, Qlo, Khi, Klo, Vhi, Vlo, mk, Ohi, Olo);

    gemm_out<<<dim3(D_MODEL / 128, MTOT / 128), 256, gemm_smem>>>(
        Ohi, Olo, whi + 3 * nw, wlo + 3 * nw, bo, out);
}

// round 9
// speedup vs baseline: 3.4750x; 1.2475x over previous
#include <cuda_runtime.h>
#include <cuda_fp16.h>
#include <math.h>
#include <stdint.h>

#define D_MODEL 1024
#define N_SEQ   2048
#define BATCH   2
#define NHEADS  16
#define DHEAD   64
#define QSCALE  0.125f
#define MTOT    (BATCH * N_SEQ)   // 4096
#define NEGINF  -1.0e30f

// ---- mma.sync helpers ----
__device__ __forceinline__ uint32_t smem_u32(const void* p) {
    uint32_t a;
    asm("{ .reg .u64 t; cvta.to.shared.u64 t, %1; cvt.u32.u64 %0, t; }"
        : "=r"(a) : "l"(p));
    return a;
}
__device__ __forceinline__ void ldsm_x4(uint32_t* r, uint32_t addr) {
    asm volatile("ldmatrix.sync.aligned.m8n8.x4.shared.b16 {%0,%1,%2,%3}, [%4];"
        : "=r"(r[0]), "=r"(r[1]), "=r"(r[2]), "=r"(r[3]) : "r"(addr));
}
__device__ __forceinline__ void ldsm_x4_t(uint32_t* r, uint32_t addr) {
    asm volatile("ldmatrix.sync.aligned.m8n8.x4.trans.shared.b16 {%0,%1,%2,%3}, [%4];"
        : "=r"(r[0]), "=r"(r[1]), "=r"(r[2]), "=r"(r[3]) : "r"(addr));
}
__device__ __forceinline__ void mma_f16(float* d, const uint32_t* a,
                                        const uint32_t* b) {
    asm volatile(
        "mma.sync.aligned.m16n8k16.row.col.f32.f16.f16.f32 "
        "{%0,%1,%2,%3}, {%4,%5,%6,%7}, {%8,%9}, {%0,%1,%2,%3};"
        : "+f"(d[0]), "+f"(d[1]), "+f"(d[2]), "+f"(d[3])
        : "r"(a[0]), "r"(a[1]), "r"(a[2]), "r"(a[3]), "r"(b[0]), "r"(b[1]));
}
// split (v0,v1) into fp16 hi-pair and lo-pair (v0 in low half)
__device__ __forceinline__ void split_pack_h(float v0, float v1,
                                             uint32_t& h, uint32_t& l) {
    __half h0 = __float2half_rn(v0);
    __half h1 = __float2half_rn(v1);
    float r0 = v0 - __half2float(h0);
    float r1 = v1 - __half2float(h1);
    __half2 hh = __halves2half2(h0, h1);
    __half2 ll = __halves2half2(__float2half_rn(r0), __float2half_rn(r1));
    h = *(uint32_t*)&hh;
    l = *(uint32_t*)&ll;
}
__device__ __forceinline__ uint32_t pack_h(float v0, float v1) {
    __half2 hh = __halves2half2(__float2half_rn(v0), __float2half_rn(v1));
    return *(uint32_t*)&hh;
}
#define CP16(dst, src) \
    asm volatile("cp.async.cg.shared.global [%0], [%1], 16;" \
                 :: "r"(dst), "l"(src) : "memory")
#define CP_COMMIT() asm volatile("cp.async.commit_group;" ::: "memory")
#define CP_WAIT0()  asm volatile("cp.async.wait_group 0;" ::: "memory")

// ---- scratch (device globals) ----
__device__ __half g_inhi[MTOT * D_MODEL];
__device__ __half g_inlo[MTOT * D_MODEL];
__device__ __half g_Qhi[MTOT * D_MODEL];
__device__ __half g_Qlo[MTOT * D_MODEL];
__device__ __half g_Khi[MTOT * D_MODEL];
__device__ __half g_Klo[MTOT * D_MODEL];
__device__ __half g_Vhi[MTOT * D_MODEL];
__device__ __half g_Ohi[MTOT * D_MODEL];
__device__ __half g_Olo[MTOT * D_MODEL];
__device__ __half g_wh[4][D_MODEL * D_MODEL];   // fp16-rounded weights (no lo)
__device__ int g_mask_kind;

// ---------------------------------------------------------------------------
__global__ void detect_mask_kind(const unsigned char* __restrict__ m)
{
    __shared__ int s_maxb, s_nzoff;
    if (threadIdx.x == 0) { s_maxb = 0; s_nzoff = 0; }
    __syncthreads();
    int maxb = 0, nzoff = 0;
    for (int i = threadIdx.x; i < 65536; i += blockDim.x) {
        int v = m[i];
        if (v > maxb) maxb = v;
        if (v && (i & 3)) nzoff++;
    }
    atomicMax(&s_maxb, maxb);
    atomicAdd(&s_nzoff, nzoff);
    __syncthreads();
    if (threadIdx.x == 0)
        g_mask_kind = (s_maxb > 1) ? 2 : (s_nzoff ? 0 : 1);
}

// ---------------------------------------------------------------------------
// fp32 -> fp16 hi/lo split (activations)
__global__ __launch_bounds__(256) void split_h_kernel(
    const float* __restrict__ x, __half* __restrict__ hi,
    __half* __restrict__ lo, int n)
{
    int i = (blockIdx.x * 256 + threadIdx.x) * 4;
    if (i >= n) return;
    float4 v = *(const float4*)(x + i);
    uint32_t h0, l0, h1, l1;
    split_pack_h(v.x, v.y, h0, l0);
    split_pack_h(v.z, v.w, h1, l1);
    *(uint2*)(hi + i) = make_uint2(h0, h1);
    *(uint2*)(lo + i) = make_uint2(l0, l1);
}
// fp32 -> fp16 round (weights; all 4 at once: n = 4*nw)
__global__ __launch_bounds__(256) void round_h_kernel(
    const float* __restrict__ w0, const float* __restrict__ w1,
    const float* __restrict__ w2, const float* __restrict__ w3,
    __half* __restrict__ out, int nw)
{
    int i = (blockIdx.x * 256 + threadIdx.x) * 4;
    const float* src = (i < nw) ? w0 : (i < 2 * nw) ? w1 : (i < 3 * nw) ? w2 : w3;
    int j = i & (nw - 1);
    float4 v = *(const float4*)(src + j);
    *(uint2*)(out + i) = make_uint2(pack_h(v.x, v.y), pack_h(v.z, v.w));
}

// ---------------------------------------------------------------------------
// GEMM (NT): out = alpha*(Ahi+Alo)*Wh^T (+bias). 2-term fp16.
// CTA 128x128, BK=32, 8 warps @ 32x64, cp.async double-buffered.
// ---------------------------------------------------------------------------
#define MBK    32
#define PITCH  80
#define TILE_B (128 * PITCH)          // 10240
#define SM_AHI 0
#define SM_ALO (1 * TILE_B)
#define SM_WH  (2 * TILE_B)
#define GBUF   (3 * TILE_B)           // 30720 per buffer

__device__ __forceinline__ void gemm_body(
    const __half* __restrict__ Ahi, const __half* __restrict__ Alo,
    const __half* __restrict__ Wh,
    const float* __restrict__ bias, float* __restrict__ Cf,
    __half* __restrict__ Chi, __half* __restrict__ Clo,
    int N, int K, float alpha, char* dsm)
{
    const uint32_t sbase = smem_u32(dsm);
    const int tid  = threadIdx.x;
    const int wid  = tid >> 5;
    const int lane = tid & 31;
    const int wm   = wid & 3;
    const int wn   = wid >> 2;
    const int m0   = blockIdx.y * 128;
    const int n0   = blockIdx.x * 128;

    const int q8  = lane >> 3;
    const int rin = lane & 7;
    const uint32_t lmoff = (uint32_t)(((q8 & 1) * 8 + rin) * PITCH + (q8 >> 1) * 16);

    const int lr0 = tid >> 2, lc0 = tid & 3;
    const int lr1 = (tid + 256) >> 2, lc1 = (tid + 256) & 3;
    const __half* gA0  = Ahi + (size_t)(m0 + lr0) * K + lc0 * 8;
    const __half* gA1  = Ahi + (size_t)(m0 + lr1) * K + lc1 * 8;
    const __half* gAl0 = Alo + (size_t)(m0 + lr0) * K + lc0 * 8;
    const __half* gAl1 = Alo + (size_t)(m0 + lr1) * K + lc1 * 8;
    const __half* gW0  = Wh + (size_t)(n0 + lr0) * K + lc0 * 8;
    const __half* gW1  = Wh + (size_t)(n0 + lr1) * K + lc1 * 8;
    const uint32_t s0 = lr0 * PITCH + lc0 * 16;
    const uint32_t s1 = lr1 * PITCH + lc1 * 16;

#define G_ISSUE(kb, bufo) do {                                                \
    const int _ko = (kb) * MBK;                                               \
    const uint32_t _d = sbase + (bufo);                                       \
    CP16(_d + SM_AHI + s0, gA0 + _ko);  CP16(_d + SM_AHI + s1, gA1 + _ko);    \
    CP16(_d + SM_ALO + s0, gAl0 + _ko); CP16(_d + SM_ALO + s1, gAl1 + _ko);   \
    CP16(_d + SM_WH + s0, gW0 + _ko);   CP16(_d + SM_WH + s1, gW1 + _ko);     \
} while (0)

    float acc[2][8][4];
#pragma unroll
    for (int s = 0; s < 2; s++)
#pragma unroll
        for (int n = 0; n < 8; n++)
#pragma unroll
            for (int r = 0; r < 4; r++) acc[s][n][r] = 0.f;

    G_ISSUE(0, 0);
    CP_COMMIT();

    const int nkb = K / MBK;
    uint32_t bufo = 0;
    for (int kb = 0; kb < nkb; kb++) {
        CP_WAIT0();
        __syncthreads();
        if (kb + 1 < nkb) { G_ISSUE(kb + 1, bufo ^ GBUF); CP_COMMIT(); }

        const uint32_t tb32 = sbase + bufo;
        const uint32_t aoff = tb32 + (wm * 32) * PITCH + lmoff;
        const uint32_t woff = tb32 + (wn * 64) * PITCH + lmoff;

#pragma unroll
        for (int ks = 0; ks < 2; ks++) {
            const uint32_t kso = ks * 32;
            uint32_t ahi[2][4], alo[2][4];
#pragma unroll
            for (int s = 0; s < 2; s++) {
                ldsm_x4(ahi[s], aoff + SM_AHI + s * 16 * PITCH + kso);
                ldsm_x4(alo[s], aoff + SM_ALO + s * 16 * PITCH + kso);
            }
#pragma unroll
            for (int g = 0; g < 4; g++) {
                uint32_t rh[4];
                ldsm_x4(rh, woff + SM_WH + g * 16 * PITCH + kso);
                uint32_t b0[2] = {rh[0], rh[2]}, b1[2] = {rh[1], rh[3]};
#pragma unroll
                for (int s = 0; s < 2; s++) {
                    mma_f16(acc[s][2 * g], ahi[s], b0);
                    mma_f16(acc[s][2 * g], alo[s], b0);
                    mma_f16(acc[s][2 * g + 1], ahi[s], b1);
                    mma_f16(acc[s][2 * g + 1], alo[s], b1);
                }
            }
        }
        __syncthreads();
        bufo ^= GBUF;
    }

#pragma unroll
    for (int s = 0; s < 2; s++) {
        const int r0 = m0 + wm * 32 + s * 16 + (lane >> 2);
#pragma unroll
        for (int n = 0; n < 8; n++) {
            const int col = n0 + wn * 64 + n * 8 + (lane & 3) * 2;
            const float b0 = bias ? bias[col] : 0.f;
            const float b1 = bias ? bias[col + 1] : 0.f;
            const float v0 = alpha * acc[s][n][0] + b0;
            const float v1 = alpha * acc[s][n][1] + b1;
            const float v2 = alpha * acc[s][n][2] + b0;
            const float v3 = alpha * acc[s][n][3] + b1;
            if (Cf) {
                *(float2*)&Cf[(size_t)r0 * N + col] = make_float2(v0, v1);
                *(float2*)&Cf[(size_t)(r0 + 8) * N + col] = make_float2(v2, v3);
            } else if (Clo) {
                uint32_t h, l;
                split_pack_h(v0, v1, h, l);
                *(uint32_t*)&Chi[(size_t)r0 * N + col] = h;
                *(uint32_t*)&Clo[(size_t)r0 * N + col] = l;
                split_pack_h(v2, v3, h, l);
                *(uint32_t*)&Chi[(size_t)(r0 + 8) * N + col] = h;
                *(uint32_t*)&Clo[(size_t)(r0 + 8) * N + col] = l;
            } else {
                *(uint32_t*)&Chi[(size_t)r0 * N + col] = pack_h(v0, v1);
                *(uint32_t*)&Chi[(size_t)(r0 + 8) * N + col] = pack_h(v2, v3);
            }
        }
    }
#undef G_ISSUE
}

__global__ __launch_bounds__(256, 2) void gemm_qkv(
    const __half* __restrict__ inhi, const __half* __restrict__ inlo,
    const __half* __restrict__ wh,
    __half* __restrict__ Qhi, __half* __restrict__ Qlo,
    __half* __restrict__ Khi, __half* __restrict__ Klo,
    __half* __restrict__ Vhi)
{
    extern __shared__ char dsm[];
    const int z = blockIdx.z;
    const int nw = D_MODEL * D_MODEL;
    const __half* Wh = wh + (size_t)z * nw;
    __half* Chi = (z == 0) ? Qhi : (z == 1) ? Khi : Vhi;
    __half* Clo = (z == 0) ? Qlo : (z == 1) ? Klo : nullptr;  // V: hi only
    const float alpha = (z == 0) ? QSCALE : 1.0f;
    gemm_body(inhi, inlo, Wh, nullptr, nullptr, Chi, Clo,
              D_MODEL, D_MODEL, alpha, dsm);
}

__global__ __launch_bounds__(256, 2) void gemm_out(
    const __half* __restrict__ Ahi, const __half* __restrict__ Alo,
    const __half* __restrict__ Wh,
    const float* __restrict__ bias, float* __restrict__ Cf)
{
    extern __shared__ char dsm[];
    gemm_body(Ahi, Alo, Wh, bias, Cf, nullptr, nullptr,
              D_MODEL, D_MODEL, 1.0f, dsm);
}

// ---------------------------------------------------------------------------
// Tensor-core flash attention, k-tile 64 (2 CTAs/SM), q-tile 128.
// QK^T: 3-term fp16 (Q,K hi/lo). PV: 2-term fp16 (P hi/lo, V hi only).
// ---------------------------------------------------------------------------
#define APB    144
#define KTROWS 64
#define KREG   (KTROWS * APB)         // 9216
#define S_KHI  0
#define S_KLO  (1 * KREG)
#define S_VHI  (2 * KREG)
#define ABUF   (3 * KREG)             // 27648 per buffer
#define NKT    (N_SEQ / KTROWS)       // 32

__global__ __launch_bounds__(256, 2) void attn_mma(
    const __half* __restrict__ Qhi, const __half* __restrict__ Qlo,
    const __half* __restrict__ Khi, const __half* __restrict__ Klo,
    const __half* __restrict__ Vhi,
    const void* __restrict__ mask,
    __half* __restrict__ Ohi, __half* __restrict__ Olo)
{
    extern __shared__ char smemb[];
    const uint32_t sb = smem_u32(smemb);

    const int tid  = threadIdx.x;
    const int warp = tid >> 5;
    const int lane = tid & 31;
    const int gq   = lane >> 2;
    const int tig  = lane & 3;
    const int q8   = lane >> 3;
    const int rin  = lane & 7;
    const uint32_t lmoff = (uint32_t)(((q8 & 1) * 8 + rin) * APB + (q8 >> 1) * 16);
    const int wrow = warp * 16;

    const int bh = blockIdx.y;
    const int b  = bh >> 4;
    const int h  = bh & 15;
    const int q0 = blockIdx.x * 128;
    const size_t rowbase = (size_t)b * N_SEQ;
    const int hoff = h * DHEAD;
    const int mkind = g_mask_kind;

    // ---- stage Q (128 rows) across buf0/buf1 KHI/KLO areas ----
#pragma unroll
    for (int i = 0; i < 4; i++) {
        const int c = tid + 256 * i;
        const int row = c >> 3, colc = c & 7;
        const size_t src = (rowbase + q0 + row) * D_MODEL + hoff + colc * 8;
        const uint32_t off = (row >= 64 ? ABUF : 0) + (row & 63) * APB + colc * 16;
        *(uint4*)(smemb + S_KHI + off) = *(const uint4*)(Qhi + src);
        *(uint4*)(smemb + S_KLO + off) = *(const uint4*)(Qlo + src);
    }
    __syncthreads();
    uint32_t aQh[4][4], aQl[4][4];
    {
        const uint32_t qb = sb + (wrow >= 64 ? ABUF : 0) + (wrow & 63) * APB + lmoff;
#pragma unroll
        for (int ks = 0; ks < 4; ks++) {
            ldsm_x4(aQh[ks], qb + S_KHI + ks * 32);
            ldsm_x4(aQl[ks], qb + S_KLO + ks * 32);
        }
    }
    __syncthreads();

    float oacc[8][4];
#pragma unroll
    for (int n = 0; n < 8; n++)
#pragma unroll
        for (int r = 0; r < 4; r++) oacc[n][r] = 0.f;
    float mrow0 = NEGINF, mrow1 = NEGINF, lrow0 = 0.f, lrow1 = 0.f;

#define ISSUE_TILES(kt, bo) do {                                              \
    _Pragma("unroll")                                                         \
    for (int i = 0; i < 2; i++) {                                             \
        const int c = tid + 256 * i;                                          \
        const int row = c >> 3, colc = c & 7;                                 \
        const size_t src = (rowbase + (kt) * KTROWS + row) * D_MODEL + hoff + colc * 8; \
        const uint32_t dst = sb + (bo) + row * APB + colc * 16;               \
        CP16(dst + S_KHI, Khi + src);                                         \
        CP16(dst + S_KLO, Klo + src);                                         \
        CP16(dst + S_VHI, Vhi + src);                                         \
    }                                                                         \
} while (0)

    uint32_t bo = 0;
    ISSUE_TILES(0, 0);
    CP_COMMIT();

    const size_t mrowb = ((size_t)b * N_SEQ + q0 + wrow + gq) * N_SEQ + 2 * tig;

    for (int kt = 0; kt < NKT; kt++) {
        CP_WAIT0();
        __syncthreads();
        if (kt + 1 < NKT) { ISSUE_TILES(kt + 1, bo ^ ABUF); CP_COMMIT(); }

        // ---- S = Q K^T (3-term fp16) ----
        float sc[8][4];
#pragma unroll
        for (int n = 0; n < 8; n++)
#pragma unroll
            for (int r = 0; r < 4; r++) sc[n][r] = 0.f;

#pragma unroll
        for (int ks = 0; ks < 4; ks++) {
#pragma unroll
            for (int g2 = 0; g2 < 4; g2++) {
                uint32_t rh[4], rl[4];
                const uint32_t ka = sb + bo + g2 * 16 * APB + lmoff + ks * 32;
                ldsm_x4(rh, ka + S_KHI);
                ldsm_x4(rl, ka + S_KLO);
                uint32_t b0h[2] = {rh[0], rh[2]}, b1h[2] = {rh[1], rh[3]};
                uint32_t b0l[2] = {rl[0], rl[2]}, b1l[2] = {rl[1], rl[3]};
                mma_f16(sc[2 * g2], aQh[ks], b0h);
                mma_f16(sc[2 * g2], aQh[ks], b0l);
                mma_f16(sc[2 * g2], aQl[ks], b0h);
                mma_f16(sc[2 * g2 + 1], aQh[ks], b1h);
                mma_f16(sc[2 * g2 + 1], aQh[ks], b1l);
                mma_f16(sc[2 * g2 + 1], aQl[ks], b1h);
            }
        }

        // ---- mask ----
        const size_t m0i = mrowb + (size_t)kt * KTROWS;
        const size_t m1i = m0i + 8 * N_SEQ;
        if (mkind == 1) {
            const int* mp = (const int*)mask;
#pragma unroll
            for (int n = 0; n < 8; n++) {
                int2 a = *(const int2*)(mp + m0i + 8 * n);
                int2 c = *(const int2*)(mp + m1i + 8 * n);
                if (a.x) sc[n][0] = NEGINF;
                if (a.y) sc[n][1] = NEGINF;
                if (c.x) sc[n][2] = NEGINF;
                if (c.y) sc[n][3] = NEGINF;
            }
        } else if (mkind == 0) {
            const unsigned char* mp = (const unsigned char*)mask;
#pragma unroll
            for (int n = 0; n < 8; n++) {
                uchar2 a = *(const uchar2*)(mp + m0i + 8 * n);
                uchar2 c = *(const uchar2*)(mp + m1i + 8 * n);
                if (a.x) sc[n][0] = NEGINF;
                if (a.y) sc[n][1] = NEGINF;
                if (c.x) sc[n][2] = NEGINF;
                if (c.y) sc[n][3] = NEGINF;
            }
        } else {
            const float* mp = (const float*)mask;
#pragma unroll
            for (int n = 0; n < 8; n++) {
                float2 a = *(const float2*)(mp + m0i + 8 * n);
                float2 c = *(const float2*)(mp + m1i + 8 * n);
                if (a.x != 0.f) sc[n][0] = NEGINF;
                if (a.y != 0.f) sc[n][1] = NEGINF;
                if (c.x != 0.f) sc[n][2] = NEGINF;
                if (c.y != 0.f) sc[n][3] = NEGINF;
            }
        }

        // ---- online softmax ----
        float mx0 = NEGINF, mx1 = NEGINF;
#pragma unroll
        for (int n = 0; n < 8; n++) {
            mx0 = fmaxf(mx0, fmaxf(sc[n][0], sc[n][1]));
            mx1 = fmaxf(mx1, fmaxf(sc[n][2], sc[n][3]));
        }
        mx0 = fmaxf(mx0, __shfl_xor_sync(0xffffffffu, mx0, 1));
        mx0 = fmaxf(mx0, __shfl_xor_sync(0xffffffffu, mx0, 2));
        mx1 = fmaxf(mx1, __shfl_xor_sync(0xffffffffu, mx1, 1));
        mx1 = fmaxf(mx1, __shfl_xor_sync(0xffffffffu, mx1, 2));

        const float mn0 = fmaxf(mrow0, mx0);
        const float mn1 = fmaxf(mrow1, mx1);
        const float f0 = __expf(mrow0 - mn0);
        const float f1 = __expf(mrow1 - mn1);

        float sum0 = 0.f, sum1 = 0.f;
#pragma unroll
        for (int n = 0; n < 8; n++) {
            sc[n][0] = __expf(sc[n][0] - mn0); sum0 += sc[n][0];
            sc[n][1] = __expf(sc[n][1] - mn0); sum0 += sc[n][1];
            sc[n][2] = __expf(sc[n][2] - mn1); sum1 += sc[n][2];
            sc[n][3] = __expf(sc[n][3] - mn1); sum1 += sc[n][3];
        }
        sum0 += __shfl_xor_sync(0xffffffffu, sum0, 1);
        sum0 += __shfl_xor_sync(0xffffffffu, sum0, 2);
        sum1 += __shfl_xor_sync(0xffffffffu, sum1, 1);
        sum1 += __shfl_xor_sync(0xffffffffu, sum1, 2);

        lrow0 = lrow0 * f0 + sum0; mrow0 = mn0;
        lrow1 = lrow1 * f1 + sum1; mrow1 = mn1;
#pragma unroll
        for (int n = 0; n < 8; n++) {
            oacc[n][0] *= f0; oacc[n][1] *= f0;
            oacc[n][2] *= f1; oacc[n][3] *= f1;
        }

        // ---- O += P V (2-term: P hi/lo fp16, V hi only) ----
#pragma unroll
        for (int kk = 0; kk < 4; kk++) {
            uint32_t aPh[4], aPl[4];
            split_pack_h(sc[2 * kk][0], sc[2 * kk][1], aPh[0], aPl[0]);
            split_pack_h(sc[2 * kk][2], sc[2 * kk][3], aPh[1], aPl[1]);
            split_pack_h(sc[2 * kk + 1][0], sc[2 * kk + 1][1], aPh[2], aPl[2]);
            split_pack_h(sc[2 * kk + 1][2], sc[2 * kk + 1][3], aPh[3], aPl[3]);
#pragma unroll
            for (int g2 = 0; g2 < 4; g2++) {
                uint32_t rh[4];
                const uint32_t va = sb + bo + kk * 16 * APB + lmoff + g2 * 32;
                ldsm_x4_t(rh, va + S_VHI);
                uint32_t b0[2] = {rh[0], rh[1]}, b1[2] = {rh[2], rh[3]};
                mma_f16(oacc[2 * g2], aPh, b0);
                mma_f16(oacc[2 * g2], aPl, b0);
                mma_f16(oacc[2 * g2 + 1], aPh, b1);
                mma_f16(oacc[2 * g2 + 1], aPl, b1);
            }
        }
        bo ^= ABUF;
    }

    // ---- normalize + write fp16 hi/lo ----
    const float inv0 = 1.f / lrow0;
    const float inv1 = 1.f / lrow1;
    const size_t orow0 = (rowbase + q0 + wrow + gq) * D_MODEL + hoff;
    const size_t orow1 = orow0 + 8 * D_MODEL;
#pragma unroll
    for (int n = 0; n < 8; n++) {
        const int col = 8 * n + 2 * tig;
        uint32_t hh, ll;
        split_pack_h(oacc[n][0] * inv0, oacc[n][1] * inv0, hh, ll);
        *(uint32_t*)&Ohi[orow0 + col] = hh;
        *(uint32_t*)&Olo[orow0 + col] = ll;
        split_pack_h(oacc[n][2] * inv1, oacc[n][3] * inv1, hh, ll);
        *(uint32_t*)&Ohi[orow1 + col] = hh;
        *(uint32_t*)&Olo[orow1 + col] = ll;
    }
}

// ---------------------------------------------------------------------------
extern "C" void kernel_launch(void* const* d_in, const int* in_sizes, int n_in,
                              void* d_out, int out_size)
{
    const float* q  = (const float*)d_in[0];
    const void*  mk = d_in[1];
    const float* Wq = (const float*)d_in[2];
    const float* Wk = (const float*)d_in[3];
    const float* Wv = (const float*)d_in[4];
    const float* Wo = (const float*)d_in[5];
    const float* bo = (const float*)d_in[6];
    float* out      = (float*)d_out;

    __half *inhi, *inlo, *Qhi, *Qlo, *Khi, *Klo, *Vhi, *Ohi, *Olo, *wh;
    cudaGetSymbolAddress((void**)&inhi, g_inhi);
    cudaGetSymbolAddress((void**)&inlo, g_inlo);
    cudaGetSymbolAddress((void**)&Qhi, g_Qhi);
    cudaGetSymbolAddress((void**)&Qlo, g_Qlo);
    cudaGetSymbolAddress((void**)&Khi, g_Khi);
    cudaGetSymbolAddress((void**)&Klo, g_Klo);
    cudaGetSymbolAddress((void**)&Vhi, g_Vhi);
    cudaGetSymbolAddress((void**)&Ohi, g_Ohi);
    cudaGetSymbolAddress((void**)&Olo, g_Olo);
    cudaGetSymbolAddress((void**)&wh, g_wh);

    detect_mask_kind<<<1, 256>>>((const unsigned char*)mk);

    const int nq = MTOT * D_MODEL;
    const int nw = D_MODEL * D_MODEL;
    split_h_kernel<<<nq / 1024, 256>>>(q, inhi, inlo, nq);
    round_h_kernel<<<4 * nw / 1024, 256>>>(Wq, Wk, Wv, Wo, wh, nw);

    const int gemm_smem = 2 * GBUF;   // 61440
    cudaFuncSetAttribute(gemm_qkv, cudaFuncAttributeMaxDynamicSharedMemorySize,
                         gemm_smem);
    cudaFuncSetAttribute(gemm_out, cudaFuncAttributeMaxDynamicSharedMemorySize,
                         gemm_smem);

    gemm_qkv<<<dim3(D_MODEL / 128, MTOT / 128, 3), 256, gemm_smem>>>(
        inhi, inlo, wh, Qhi, Qlo, Khi, Klo, Vhi);

    const int attn_smem = 2 * ABUF;   // 55296
    cudaFuncSetAttribute(attn_mma, cudaFuncAttributeMaxDynamicSharedMemorySize,
                         attn_smem);
    attn_mma<<<dim3(N_SEQ / 128, BATCH * NHEADS), 256, attn_smem>>>(
        Qhi, Qlo, Khi, Klo, Vhi, mk, Ohi, Olo);

    gemm_out<<<dim3(D_MODEL / 128, MTOT / 128), 256, gemm_smem>>>(
        Ohi, Olo, wh + 3 * (size_t)nw, bo, out);
}

// round 10
// speedup vs baseline: 3.5633x; 1.0254x over previous
#include <cuda_runtime.h>
#include <cuda_fp16.h>
#include <math.h>
#include <stdint.h>

#define D_MODEL 1024
#define N_SEQ   2048
#define BATCH   2
#define NHEADS  16
#define DHEAD   64
#define QSCALE  0.125f
#define MTOT    (BATCH * N_SEQ)   // 4096
#define NEGINF  -1.0e30f
typedef unsigned long long u64;

// ---- mma.sync helpers ----
__device__ __forceinline__ uint32_t smem_u32(const void* p) {
    uint32_t a;
    asm("{ .reg .u64 t; cvta.to.shared.u64 t, %1; cvt.u32.u64 %0, t; }"
        : "=r"(a) : "l"(p));
    return a;
}
__device__ __forceinline__ void ldsm_x4(uint32_t* r, uint32_t addr) {
    asm volatile("ldmatrix.sync.aligned.m8n8.x4.shared.b16 {%0,%1,%2,%3}, [%4];"
        : "=r"(r[0]), "=r"(r[1]), "=r"(r[2]), "=r"(r[3]) : "r"(addr));
}
__device__ __forceinline__ void ldsm_x4_t(uint32_t* r, uint32_t addr) {
    asm volatile("ldmatrix.sync.aligned.m8n8.x4.trans.shared.b16 {%0,%1,%2,%3}, [%4];"
        : "=r"(r[0]), "=r"(r[1]), "=r"(r[2]), "=r"(r[3]) : "r"(addr));
}
__device__ __forceinline__ void mma_f16(float* d, const uint32_t* a,
                                        const uint32_t* b) {
    asm volatile(
        "mma.sync.aligned.m16n8k16.row.col.f32.f16.f16.f32 "
        "{%0,%1,%2,%3}, {%4,%5,%6,%7}, {%8,%9}, {%0,%1,%2,%3};"
        : "+f"(d[0]), "+f"(d[1]), "+f"(d[2]), "+f"(d[3])
        : "r"(a[0]), "r"(a[1]), "r"(a[2]), "r"(a[3]), "r"(b[0]), "r"(b[1]));
}
__device__ __forceinline__ void split_pack_h(float v0, float v1,
                                             uint32_t& h, uint32_t& l) {
    __half h0 = __float2half_rn(v0);
    __half h1 = __float2half_rn(v1);
    float r0 = v0 - __half2float(h0);
    float r1 = v1 - __half2float(h1);
    __half2 hh = __halves2half2(h0, h1);
    __half2 ll = __halves2half2(__float2half_rn(r0), __float2half_rn(r1));
    h = *(uint32_t*)&hh;
    l = *(uint32_t*)&ll;
}
__device__ __forceinline__ uint32_t pack_h(float v0, float v1) {
    __half2 hh = __halves2half2(__float2half_rn(v0), __float2half_rn(v1));
    return *(uint32_t*)&hh;
}
#define CP16(dst, src) \
    asm volatile("cp.async.cg.shared.global [%0], [%1], 16;" \
                 :: "r"(dst), "l"(src) : "memory")
#define CP_COMMIT() asm volatile("cp.async.commit_group;" ::: "memory")
#define CP_WAIT0()  asm volatile("cp.async.wait_group 0;" ::: "memory")
#define CP_WAIT1()  asm volatile("cp.async.wait_group 1;" ::: "memory")

// ---- scratch (device globals) ----
__device__ __half g_inhi[MTOT * D_MODEL];
__device__ __half g_inlo[MTOT * D_MODEL];
__device__ __half g_Qhi[MTOT * D_MODEL];
__device__ __half g_Qlo[MTOT * D_MODEL];
__device__ __half g_Khi[MTOT * D_MODEL];
__device__ __half g_Klo[MTOT * D_MODEL];
__device__ __half g_Vhi[MTOT * D_MODEL];
__device__ __half g_Ohi[MTOT * D_MODEL];
__device__ __half g_Olo[MTOT * D_MODEL];
__device__ __half g_wh[4][D_MODEL * D_MODEL];
__device__ u64    g_mbits[BATCH * N_SEQ * (N_SEQ / 64)];   // 1 MB bitmask
__device__ int    g_mask_kind;

// ---------------------------------------------------------------------------
__global__ void detect_mask_kind(const unsigned char* __restrict__ m)
{
    __shared__ int s_maxb, s_nzoff;
    if (threadIdx.x == 0) { s_maxb = 0; s_nzoff = 0; }
    __syncthreads();
    int maxb = 0, nzoff = 0;
    for (int i = threadIdx.x; i < 65536; i += blockDim.x) {
        int v = m[i];
        if (v > maxb) maxb = v;
        if (v && (i & 3)) nzoff++;
    }
    atomicMax(&s_maxb, maxb);
    atomicAdd(&s_nzoff, nzoff);
    __syncthreads();
    if (threadIdx.x == 0)
        g_mask_kind = (s_maxb > 1) ? 2 : (s_nzoff ? 0 : 1);
}

// ---------------------------------------------------------------------------
// Pack mask to bits: word wi covers row = wi/(N/64), cols [seg*64, seg*64+64).
// One warp per u64 word via two ballots. Coalesced global reads.
// ---------------------------------------------------------------------------
__global__ __launch_bounds__(256) void pack_mask(
    const void* __restrict__ m, u64* __restrict__ out)
{
    const int kind = g_mask_kind;
    const int wi = blockIdx.x * 8 + (threadIdx.x >> 5);
    const int lane = threadIdx.x & 31;
    const int wpr = N_SEQ / 64;   // 32
    const size_t base = (size_t)(wi / wpr) * N_SEQ + (size_t)(wi % wpr) * 64 + lane;
    bool v0, v1;
    if (kind == 1) {
        const int* p = (const int*)m;
        v0 = p[base] != 0; v1 = p[base + 32] != 0;
    } else if (kind == 0) {
        const unsigned char* p = (const unsigned char*)m;
        v0 = p[base] != 0; v1 = p[base + 32] != 0;
    } else {
        const float* p = (const float*)m;
        v0 = p[base] != 0.f; v1 = p[base + 32] != 0.f;
    }
    unsigned b0 = __ballot_sync(0xffffffffu, v0);
    unsigned b1 = __ballot_sync(0xffffffffu, v1);
    if (lane == 0) out[wi] = (u64)b0 | ((u64)b1 << 32);
}

// ---------------------------------------------------------------------------
__global__ __launch_bounds__(256) void split_h_kernel(
    const float* __restrict__ x, __half* __restrict__ hi,
    __half* __restrict__ lo, int n)
{
    int i = (blockIdx.x * 256 + threadIdx.x) * 4;
    if (i >= n) return;
    float4 v = *(const float4*)(x + i);
    uint32_t h0, l0, h1, l1;
    split_pack_h(v.x, v.y, h0, l0);
    split_pack_h(v.z, v.w, h1, l1);
    *(uint2*)(hi + i) = make_uint2(h0, h1);
    *(uint2*)(lo + i) = make_uint2(l0, l1);
}
__global__ __launch_bounds__(256) void round_h_kernel(
    const float* __restrict__ w0, const float* __restrict__ w1,
    const float* __restrict__ w2, const float* __restrict__ w3,
    __half* __restrict__ out, int nw)
{
    int i = (blockIdx.x * 256 + threadIdx.x) * 4;
    const float* src = (i < nw) ? w0 : (i < 2 * nw) ? w1 : (i < 3 * nw) ? w2 : w3;
    int j = i & (nw - 1);
    float4 v = *(const float4*)(src + j);
    *(uint2*)(out + i) = make_uint2(pack_h(v.x, v.y), pack_h(v.z, v.w));
}

// ---------------------------------------------------------------------------
// GEMM (NT): out = alpha*(Ahi+Alo)*Wh^T (+bias). 2-term fp16.
// CTA 128x128, BK=32, 8 warps @ 32x64, 3-stage cp.async pipeline.
// ---------------------------------------------------------------------------
#define MBK    32
#define PITCH  80
#define TILE_B (128 * PITCH)          // 10240
#define SM_AHI 0
#define SM_ALO (1 * TILE_B)
#define SM_WH  (2 * TILE_B)
#define GBUF   (3 * TILE_B)           // 30720 per stage

__device__ __forceinline__ void gemm_body(
    const __half* __restrict__ Ahi, const __half* __restrict__ Alo,
    const __half* __restrict__ Wh,
    const float* __restrict__ bias, float* __restrict__ Cf,
    __half* __restrict__ Chi, __half* __restrict__ Clo,
    int N, int K, float alpha, char* dsm)
{
    const uint32_t sbase = smem_u32(dsm);
    const int tid  = threadIdx.x;
    const int wid  = tid >> 5;
    const int lane = tid & 31;
    const int wm   = wid & 3;
    const int wn   = wid >> 2;
    const int m0   = blockIdx.y * 128;
    const int n0   = blockIdx.x * 128;

    const int q8  = lane >> 3;
    const int rin = lane & 7;
    const uint32_t lmoff = (uint32_t)(((q8 & 1) * 8 + rin) * PITCH + (q8 >> 1) * 16);

    const int lr0 = tid >> 2, lc0 = tid & 3;
    const int lr1 = (tid + 256) >> 2, lc1 = (tid + 256) & 3;
    const __half* gA0  = Ahi + (size_t)(m0 + lr0) * K + lc0 * 8;
    const __half* gA1  = Ahi + (size_t)(m0 + lr1) * K + lc1 * 8;
    const __half* gAl0 = Alo + (size_t)(m0 + lr0) * K + lc0 * 8;
    const __half* gAl1 = Alo + (size_t)(m0 + lr1) * K + lc1 * 8;
    const __half* gW0  = Wh + (size_t)(n0 + lr0) * K + lc0 * 8;
    const __half* gW1  = Wh + (size_t)(n0 + lr1) * K + lc1 * 8;
    const uint32_t s0 = lr0 * PITCH + lc0 * 16;
    const uint32_t s1 = lr1 * PITCH + lc1 * 16;

#define G_ISSUE(kb, bufo) do {                                                \
    const int _ko = (kb) * MBK;                                               \
    const uint32_t _d = sbase + (bufo);                                       \
    CP16(_d + SM_AHI + s0, gA0 + _ko);  CP16(_d + SM_AHI + s1, gA1 + _ko);    \
    CP16(_d + SM_ALO + s0, gAl0 + _ko); CP16(_d + SM_ALO + s1, gAl1 + _ko);   \
    CP16(_d + SM_WH + s0, gW0 + _ko);   CP16(_d + SM_WH + s1, gW1 + _ko);     \
} while (0)

    float acc[2][8][4];
#pragma unroll
    for (int s = 0; s < 2; s++)
#pragma unroll
        for (int n = 0; n < 8; n++)
#pragma unroll
            for (int r = 0; r < 4; r++) acc[s][n][r] = 0.f;

    G_ISSUE(0, 0);
    CP_COMMIT();
    G_ISSUE(1, GBUF);
    CP_COMMIT();

    const int nkb = K / MBK;
    uint32_t bufo = 0;             // compute stage
    uint32_t bufi = 2 * GBUF;      // issue stage (kb+2)
    for (int kb = 0; kb < nkb; kb++) {
        if (kb + 1 < nkb) CP_WAIT1(); else CP_WAIT0();
        __syncthreads();
        if (kb + 2 < nkb) {
            G_ISSUE(kb + 2, bufi);
            CP_COMMIT();
            bufi = (bufi == 2 * GBUF) ? 0 : bufi + GBUF;
        }

        const uint32_t tb32 = sbase + bufo;
        const uint32_t aoff = tb32 + (wm * 32) * PITCH + lmoff;
        const uint32_t woff = tb32 + (wn * 64) * PITCH + lmoff;

#pragma unroll
        for (int ks = 0; ks < 2; ks++) {
            const uint32_t kso = ks * 32;
            uint32_t ahi[2][4], alo[2][4];
#pragma unroll
            for (int s = 0; s < 2; s++) {
                ldsm_x4(ahi[s], aoff + SM_AHI + s * 16 * PITCH + kso);
                ldsm_x4(alo[s], aoff + SM_ALO + s * 16 * PITCH + kso);
            }
#pragma unroll
            for (int g = 0; g < 4; g++) {
                uint32_t rh[4];
                ldsm_x4(rh, woff + SM_WH + g * 16 * PITCH + kso);
                uint32_t b0[2] = {rh[0], rh[2]}, b1[2] = {rh[1], rh[3]};
#pragma unroll
                for (int s = 0; s < 2; s++) {
                    mma_f16(acc[s][2 * g], ahi[s], b0);
                    mma_f16(acc[s][2 * g], alo[s], b0);
                    mma_f16(acc[s][2 * g + 1], ahi[s], b1);
                    mma_f16(acc[s][2 * g + 1], alo[s], b1);
                }
            }
        }
        bufo = (bufo == 2 * GBUF) ? 0 : bufo + GBUF;
    }

#pragma unroll
    for (int s = 0; s < 2; s++) {
        const int r0 = m0 + wm * 32 + s * 16 + (lane >> 2);
#pragma unroll
        for (int n = 0; n < 8; n++) {
            const int col = n0 + wn * 64 + n * 8 + (lane & 3) * 2;
            const float b0 = bias ? bias[col] : 0.f;
            const float b1 = bias ? bias[col + 1] : 0.f;
            const float v0 = alpha * acc[s][n][0] + b0;
            const float v1 = alpha * acc[s][n][1] + b1;
            const float v2 = alpha * acc[s][n][2] + b0;
            const float v3 = alpha * acc[s][n][3] + b1;
            if (Cf) {
                *(float2*)&Cf[(size_t)r0 * N + col] = make_float2(v0, v1);
                *(float2*)&Cf[(size_t)(r0 + 8) * N + col] = make_float2(v2, v3);
            } else if (Clo) {
                uint32_t h, l;
                split_pack_h(v0, v1, h, l);
                *(uint32_t*)&Chi[(size_t)r0 * N + col] = h;
                *(uint32_t*)&Clo[(size_t)r0 * N + col] = l;
                split_pack_h(v2, v3, h, l);
                *(uint32_t*)&Chi[(size_t)(r0 + 8) * N + col] = h;
                *(uint32_t*)&Clo[(size_t)(r0 + 8) * N + col] = l;
            } else {
                *(uint32_t*)&Chi[(size_t)r0 * N + col] = pack_h(v0, v1);
                *(uint32_t*)&Chi[(size_t)(r0 + 8) * N + col] = pack_h(v2, v3);
            }
        }
    }
#undef G_ISSUE
}

__global__ __launch_bounds__(256, 2) void gemm_qkv(
    const __half* __restrict__ inhi, const __half* __restrict__ inlo,
    const __half* __restrict__ wh,
    __half* __restrict__ Qhi, __half* __restrict__ Qlo,
    __half* __restrict__ Khi, __half* __restrict__ Klo,
    __half* __restrict__ Vhi)
{
    extern __shared__ char dsm[];
    const int z = blockIdx.z;
    const int nw = D_MODEL * D_MODEL;
    const __half* Wh = wh + (size_t)z * nw;
    __half* Chi = (z == 0) ? Qhi : (z == 1) ? Khi : Vhi;
    __half* Clo = (z == 0) ? Qlo : (z == 1) ? Klo : nullptr;
    const float alpha = (z == 0) ? QSCALE : 1.0f;
    gemm_body(inhi, inlo, Wh, nullptr, nullptr, Chi, Clo,
              D_MODEL, D_MODEL, alpha, dsm);
}

__global__ __launch_bounds__(256, 2) void gemm_out(
    const __half* __restrict__ Ahi, const __half* __restrict__ Alo,
    const __half* __restrict__ Wh,
    const float* __restrict__ bias, float* __restrict__ Cf)
{
    extern __shared__ char dsm[];
    gemm_body(Ahi, Alo, Wh, bias, Cf, nullptr, nullptr,
              D_MODEL, D_MODEL, 1.0f, dsm);
}

// ---------------------------------------------------------------------------
// Tensor-core flash attention, k-tile 64, q-tile 128, 3-stage pipeline.
// QK^T: 3-term fp16. PV: 2-term fp16. Mask: packed bits (1 u64 / row / tile).
// ---------------------------------------------------------------------------
#define APB    144
#define KTROWS 64
#define KREG   (KTROWS * APB)         // 9216
#define S_KHI  0
#define S_KLO  (1 * KREG)
#define S_VHI  (2 * KREG)
#define ABUF   (3 * KREG)             // 27648 per stage
#define NKT    (N_SEQ / KTROWS)       // 32

__global__ __launch_bounds__(256, 2) void attn_mma(
    const __half* __restrict__ Qhi, const __half* __restrict__ Qlo,
    const __half* __restrict__ Khi, const __half* __restrict__ Klo,
    const __half* __restrict__ Vhi,
    const u64* __restrict__ mbits,
    __half* __restrict__ Ohi, __half* __restrict__ Olo)
{
    extern __shared__ char smemb[];
    const uint32_t sb = smem_u32(smemb);

    const int tid  = threadIdx.x;
    const int warp = tid >> 5;
    const int lane = tid & 31;
    const int gq   = lane >> 2;
    const int tig  = lane & 3;
    const int q8   = lane >> 3;
    const int rin  = lane & 7;
    const uint32_t lmoff = (uint32_t)(((q8 & 1) * 8 + rin) * APB + (q8 >> 1) * 16);
    const int wrow = warp * 16;

    const int bh = blockIdx.y;
    const int b  = bh >> 4;
    const int h  = bh & 15;
    const int q0 = blockIdx.x * 128;
    const size_t rowbase = (size_t)b * N_SEQ;
    const int hoff = h * DHEAD;

    // ---- stage Q (128 rows) into stage-0/1 KHI/KLO areas; read to regs ----
#pragma unroll
    for (int i = 0; i < 4; i++) {
        const int c = tid + 256 * i;
        const int row = c >> 3, colc = c & 7;
        const size_t src = (rowbase + q0 + row) * D_MODEL + hoff + colc * 8;
        const uint32_t off = (row >= 64 ? ABUF : 0) + (row & 63) * APB + colc * 16;
        *(uint4*)(smemb + S_KHI + off) = *(const uint4*)(Qhi + src);
        *(uint4*)(smemb + S_KLO + off) = *(const uint4*)(Qlo + src);
    }
    __syncthreads();
    uint32_t aQh[4][4], aQl[4][4];
    {
        const uint32_t qb = sb + (wrow >= 64 ? ABUF : 0) + (wrow & 63) * APB + lmoff;
#pragma unroll
        for (int ks = 0; ks < 4; ks++) {
            ldsm_x4(aQh[ks], qb + S_KHI + ks * 32);
            ldsm_x4(aQl[ks], qb + S_KLO + ks * 32);
        }
    }
    __syncthreads();

    float oacc[8][4];
#pragma unroll
    for (int n = 0; n < 8; n++)
#pragma unroll
        for (int r = 0; r < 4; r++) oacc[n][r] = 0.f;
    float mrow0 = NEGINF, mrow1 = NEGINF, lrow0 = 0.f, lrow1 = 0.f;

#define ISSUE_TILES(kt, bo) do {                                              \
    _Pragma("unroll")                                                         \
    for (int i = 0; i < 2; i++) {                                             \
        const int c = tid + 256 * i;                                          \
        const int row = c >> 3, colc = c & 7;                                 \
        const size_t src = (rowbase + (kt) * KTROWS + row) * D_MODEL + hoff + colc * 8; \
        const uint32_t dst = sb + (bo) + row * APB + colc * 16;               \
        CP16(dst + S_KHI, Khi + src);                                         \
        CP16(dst + S_KLO, Klo + src);                                         \
        CP16(dst + S_VHI, Vhi + src);                                         \
    }                                                                         \
} while (0)

    ISSUE_TILES(0, 0);
    CP_COMMIT();
    ISSUE_TILES(1, ABUF);
    CP_COMMIT();

    const u64* mb0 = mbits + (size_t)(b * N_SEQ + q0 + wrow + gq) * (N_SEQ / 64);
    const u64* mb1 = mb0 + 8 * (N_SEQ / 64);

    uint32_t bo = 0;
    uint32_t bi = 2 * ABUF;
    for (int kt = 0; kt < NKT; kt++) {
        if (kt + 1 < NKT) CP_WAIT1(); else CP_WAIT0();
        __syncthreads();
        if (kt + 2 < NKT) {
            ISSUE_TILES(kt + 2, bi);
            CP_COMMIT();
            bi = (bi == 2 * ABUF) ? 0 : bi + ABUF;
        }

        // ---- S = Q K^T (3-term fp16) ----
        float sc[8][4];
#pragma unroll
        for (int n = 0; n < 8; n++)
#pragma unroll
            for (int r = 0; r < 4; r++) sc[n][r] = 0.f;

#pragma unroll
        for (int ks = 0; ks < 4; ks++) {
#pragma unroll
            for (int g2 = 0; g2 < 4; g2++) {
                uint32_t rh[4], rl[4];
                const uint32_t ka = sb + bo + g2 * 16 * APB + lmoff + ks * 32;
                ldsm_x4(rh, ka + S_KHI);
                ldsm_x4(rl, ka + S_KLO);
                uint32_t b0h[2] = {rh[0], rh[2]}, b1h[2] = {rh[1], rh[3]};
                uint32_t b0l[2] = {rl[0], rl[2]}, b1l[2] = {rl[1], rl[3]};
                mma_f16(sc[2 * g2], aQh[ks], b0h);
                mma_f16(sc[2 * g2], aQh[ks], b0l);
                mma_f16(sc[2 * g2], aQl[ks], b0h);
                mma_f16(sc[2 * g2 + 1], aQh[ks], b1h);
                mma_f16(sc[2 * g2 + 1], aQh[ks], b1l);
                mma_f16(sc[2 * g2 + 1], aQl[ks], b1h);
            }
        }

        // ---- mask from packed bits ----
        {
            const u64 w0 = mb0[kt];
            const u64 w1 = mb1[kt];
#pragma unroll
            for (int n = 0; n < 8; n++) {
                const unsigned s0 = (unsigned)(w0 >> (8 * n + 2 * tig));
                const unsigned s1 = (unsigned)(w1 >> (8 * n + 2 * tig));
                if (s0 & 1) sc[n][0] = NEGINF;
                if (s0 & 2) sc[n][1] = NEGINF;
                if (s1 & 1) sc[n][2] = NEGINF;
                if (s1 & 2) sc[n][3] = NEGINF;
            }
        }

        // ---- online softmax ----
        float mx0 = NEGINF, mx1 = NEGINF;
#pragma unroll
        for (int n = 0; n < 8; n++) {
            mx0 = fmaxf(mx0, fmaxf(sc[n][0], sc[n][1]));
            mx1 = fmaxf(mx1, fmaxf(sc[n][2], sc[n][3]));
        }
        mx0 = fmaxf(mx0, __shfl_xor_sync(0xffffffffu, mx0, 1));
        mx0 = fmaxf(mx0, __shfl_xor_sync(0xffffffffu, mx0, 2));
        mx1 = fmaxf(mx1, __shfl_xor_sync(0xffffffffu, mx1, 1));
        mx1 = fmaxf(mx1, __shfl_xor_sync(0xffffffffu, mx1, 2));

        const float mn0 = fmaxf(mrow0, mx0);
        const float mn1 = fmaxf(mrow1, mx1);
        const float f0 = __expf(mrow0 - mn0);
        const float f1 = __expf(mrow1 - mn1);

        float sum0 = 0.f, sum1 = 0.f;
#pragma unroll
        for (int n = 0; n < 8; n++) {
            sc[n][0] = __expf(sc[n][0] - mn0); sum0 += sc[n][0];
            sc[n][1] = __expf(sc[n][1] - mn0); sum0 += sc[n][1];
            sc[n][2] = __expf(sc[n][2] - mn1); sum1 += sc[n][2];
            sc[n][3] = __expf(sc[n][3] - mn1); sum1 += sc[n][3];
        }
        sum0 += __shfl_xor_sync(0xffffffffu, sum0, 1);
        sum0 += __shfl_xor_sync(0xffffffffu, sum0, 2);
        sum1 += __shfl_xor_sync(0xffffffffu, sum1, 1);
        sum1 += __shfl_xor_sync(0xffffffffu, sum1, 2);

        lrow0 = lrow0 * f0 + sum0; mrow0 = mn0;
        lrow1 = lrow1 * f1 + sum1; mrow1 = mn1;
#pragma unroll
        for (int n = 0; n < 8; n++) {
            oacc[n][0] *= f0; oacc[n][1] *= f0;
            oacc[n][2] *= f1; oacc[n][3] *= f1;
        }

        // ---- O += P V (2-term) ----
#pragma unroll
        for (int kk = 0; kk < 4; kk++) {
            uint32_t aPh[4], aPl[4];
            split_pack_h(sc[2 * kk][0], sc[2 * kk][1], aPh[0], aPl[0]);
            split_pack_h(sc[2 * kk][2], sc[2 * kk][3], aPh[1], aPl[1]);
            split_pack_h(sc[2 * kk + 1][0], sc[2 * kk + 1][1], aPh[2], aPl[2]);
            split_pack_h(sc[2 * kk + 1][2], sc[2 * kk + 1][3], aPh[3], aPl[3]);
#pragma unroll
            for (int g2 = 0; g2 < 4; g2++) {
                uint32_t rh[4];
                const uint32_t va = sb + bo + kk * 16 * APB + lmoff + g2 * 32;
                ldsm_x4_t(rh, va + S_VHI);
                uint32_t b0[2] = {rh[0], rh[1]}, b1[2] = {rh[2], rh[3]};
                mma_f16(oacc[2 * g2], aPh, b0);
                mma_f16(oacc[2 * g2], aPl, b0);
                mma_f16(oacc[2 * g2 + 1], aPh, b1);
                mma_f16(oacc[2 * g2 + 1], aPl, b1);
            }
        }
        bo = (bo == 2 * ABUF) ? 0 : bo + ABUF;
    }

    // ---- normalize + write fp16 hi/lo ----
    const float inv0 = 1.f / lrow0;
    const float inv1 = 1.f / lrow1;
    const size_t orow0 = (rowbase + q0 + wrow + gq) * D_MODEL + hoff;
    const size_t orow1 = orow0 + 8 * D_MODEL;
#pragma unroll
    for (int n = 0; n < 8; n++) {
        const int col = 8 * n + 2 * tig;
        uint32_t hh, ll;
        split_pack_h(oacc[n][0] * inv0, oacc[n][1] * inv0, hh, ll);
        *(uint32_t*)&Ohi[orow0 + col] = hh;
        *(uint32_t*)&Olo[orow0 + col] = ll;
        split_pack_h(oacc[n][2] * inv1, oacc[n][3] * inv1, hh, ll);
        *(uint32_t*)&Ohi[orow1 + col] = hh;
        *(uint32_t*)&Olo[orow1 + col] = ll;
    }
}

// ---------------------------------------------------------------------------
extern "C" void kernel_launch(void* const* d_in, const int* in_sizes, int n_in,
                              void* d_out, int out_size)
{
    const float* q  = (const float*)d_in[0];
    const void*  mk = d_in[1];
    const float* Wq = (const float*)d_in[2];
    const float* Wk = (const float*)d_in[3];
    const float* Wv = (const float*)d_in[4];
    const float* Wo = (const float*)d_in[5];
    const float* bo = (const float*)d_in[6];
    float* out      = (float*)d_out;

    __half *inhi, *inlo, *Qhi, *Qlo, *Khi, *Klo, *Vhi, *Ohi, *Olo, *wh;
    u64* mbits;
    cudaGetSymbolAddress((void**)&inhi, g_inhi);
    cudaGetSymbolAddress((void**)&inlo, g_inlo);
    cudaGetSymbolAddress((void**)&Qhi, g_Qhi);
    cudaGetSymbolAddress((void**)&Qlo, g_Qlo);
    cudaGetSymbolAddress((void**)&Khi, g_Khi);
    cudaGetSymbolAddress((void**)&Klo, g_Klo);
    cudaGetSymbolAddress((void**)&Vhi, g_Vhi);
    cudaGetSymbolAddress((void**)&Ohi, g_Ohi);
    cudaGetSymbolAddress((void**)&Olo, g_Olo);
    cudaGetSymbolAddress((void**)&wh, g_wh);
    cudaGetSymbolAddress((void**)&mbits, g_mbits);

    detect_mask_kind<<<1, 256>>>((const unsigned char*)mk);

    const int nq = MTOT * D_MODEL;
    const int nw = D_MODEL * D_MODEL;
    split_h_kernel<<<nq / 1024, 256>>>(q, inhi, inlo, nq);
    round_h_kernel<<<4 * nw / 1024, 256>>>(Wq, Wk, Wv, Wo, wh, nw);
    pack_mask<<<(BATCH * N_SEQ * (N_SEQ / 64)) / 8, 256>>>(mk, mbits);

    const int gemm_smem = 3 * GBUF;   // 92160
    cudaFuncSetAttribute(gemm_qkv, cudaFuncAttributeMaxDynamicSharedMemorySize,
                         gemm_smem);
    cudaFuncSetAttribute(gemm_out, cudaFuncAttributeMaxDynamicSharedMemorySize,
                         gemm_smem);

    gemm_qkv<<<dim3(D_MODEL / 128, MTOT / 128, 3), 256, gemm_smem>>>(
        inhi, inlo, wh, Qhi, Qlo, Khi, Klo, Vhi);

    const int attn_smem = 3 * ABUF;   // 82944
    cudaFuncSetAttribute(attn_mma, cudaFuncAttributeMaxDynamicSharedMemorySize,
                         attn_smem);
    attn_mma<<<dim3(N_SEQ / 128, BATCH * NHEADS), 256, attn_smem>>>(
        Qhi, Qlo, Khi, Klo, Vhi, mbits, Ohi, Olo);

    gemm_out<<<dim3(D_MODEL / 128, MTOT / 128), 256, gemm_smem>>>(
        Ohi, Olo, wh + 3 * (size_t)nw, bo, out);
}

// round 12
// speedup vs baseline: 4.6388x; 1.3018x over previous
#include <cuda_runtime.h>
#include <cuda_fp16.h>
#include <math.h>
#include <stdint.h>

#define D_MODEL 1024
#define N_SEQ   2048
#define BATCH   2
#define NHEADS  16
#define DHEAD   64
#define QSCALE  0.125f
#define MTOT    (BATCH * N_SEQ)   // 4096
#define NEGINF  -1.0e30f
typedef unsigned long long u64;

// ---- mma.sync helpers ----
__device__ __forceinline__ uint32_t smem_u32(const void* p) {
    uint32_t a;
    asm("{ .reg .u64 t; cvta.to.shared.u64 t, %1; cvt.u32.u64 %0, t; }"
        : "=r"(a) : "l"(p));
    return a;
}
__device__ __forceinline__ void ldsm_x4(uint32_t* r, uint32_t addr) {
    asm volatile("ldmatrix.sync.aligned.m8n8.x4.shared.b16 {%0,%1,%2,%3}, [%4];"
        : "=r"(r[0]), "=r"(r[1]), "=r"(r[2]), "=r"(r[3]) : "r"(addr));
}
__device__ __forceinline__ void ldsm_x4_t(uint32_t* r, uint32_t addr) {
    asm volatile("ldmatrix.sync.aligned.m8n8.x4.trans.shared.b16 {%0,%1,%2,%3}, [%4];"
        : "=r"(r[0]), "=r"(r[1]), "=r"(r[2]), "=r"(r[3]) : "r"(addr));
}
__device__ __forceinline__ void mma_f16(float* d, const uint32_t* a,
                                        const uint32_t* b) {
    asm volatile(
        "mma.sync.aligned.m16n8k16.row.col.f32.f16.f16.f32 "
        "{%0,%1,%2,%3}, {%4,%5,%6,%7}, {%8,%9}, {%0,%1,%2,%3};"
        : "+f"(d[0]), "+f"(d[1]), "+f"(d[2]), "+f"(d[3])
        : "r"(a[0]), "r"(a[1]), "r"(a[2]), "r"(a[3]), "r"(b[0]), "r"(b[1]));
}
__device__ __forceinline__ void split_pack_h(float v0, float v1,
                                             uint32_t& h, uint32_t& l) {
    __half h0 = __float2half_rn(v0);
    __half h1 = __float2half_rn(v1);
    float r0 = v0 - __half2float(h0);
    float r1 = v1 - __half2float(h1);
    __half2 hh = __halves2half2(h0, h1);
    __half2 ll = __halves2half2(__float2half_rn(r0), __float2half_rn(r1));
    h = *(uint32_t*)&hh;
    l = *(uint32_t*)&ll;
}
__device__ __forceinline__ uint32_t pack_h(float v0, float v1) {
    __half2 hh = __halves2half2(__float2half_rn(v0), __float2half_rn(v1));
    return *(uint32_t*)&hh;
}
#define CP16(dst, src) \
    asm volatile("cp.async.cg.shared.global [%0], [%1], 16;" \
                 :: "r"(dst), "l"(src) : "memory")
#define CP_COMMIT() asm volatile("cp.async.commit_group;" ::: "memory")
#define CP_WAIT0()  asm volatile("cp.async.wait_group 0;" ::: "memory")
#define CP_WAIT1()  asm volatile("cp.async.wait_group 1;" ::: "memory")

// ---- scratch (device globals) ----
__device__ __half g_inh[MTOT * D_MODEL];
__device__ __half g_Qhi[MTOT * D_MODEL];
__device__ __half g_Qlo[MTOT * D_MODEL];
__device__ __half g_Khi[MTOT * D_MODEL];
__device__ __half g_Vhi[MTOT * D_MODEL];
__device__ __half g_Ohi[MTOT * D_MODEL];
__device__ __half g_Olo[MTOT * D_MODEL];
__device__ __half g_wh[4][D_MODEL * D_MODEL];
__device__ u64    g_mbits[BATCH * N_SEQ * (N_SEQ / 64)];
__device__ int    g_mask_kind;

// ---------------------------------------------------------------------------
__global__ void detect_mask_kind(const unsigned char* __restrict__ m)
{
    __shared__ int s_maxb, s_nzoff;
    if (threadIdx.x == 0) { s_maxb = 0; s_nzoff = 0; }
    __syncthreads();
    int maxb = 0, nzoff = 0;
    for (int i = threadIdx.x; i < 65536; i += blockDim.x) {
        int v = m[i];
        if (v > maxb) maxb = v;
        if (v && (i & 3)) nzoff++;
    }
    atomicMax(&s_maxb, maxb);
    atomicAdd(&s_nzoff, nzoff);
    __syncthreads();
    if (threadIdx.x == 0)
        g_mask_kind = (s_maxb > 1) ? 2 : (s_nzoff ? 0 : 1);
}

// ---------------------------------------------------------------------------
// Pack mask to bits. Each warp packs 2 u64 words (128 elems, stride-32 lanes).
// ---------------------------------------------------------------------------
__global__ __launch_bounds__(256) void pack_mask(
    const void* __restrict__ m, u64* __restrict__ out)
{
    const int kind = g_mask_kind;
    const int wp   = blockIdx.x * 8 + (threadIdx.x >> 5);   // warp -> 2 words
    const int wi   = wp * 2;
    const int lane = threadIdx.x & 31;
    const int wpr  = N_SEQ / 64;   // 32
    const size_t base = (size_t)(wi / wpr) * N_SEQ + (size_t)(wi % wpr) * 64 + lane;
    bool v[4];
    if (kind == 1) {
        const int* p = (const int*)m;
#pragma unroll
        for (int j = 0; j < 4; j++) v[j] = p[base + 32 * j] != 0;
    } else if (kind == 0) {
        const unsigned char* p = (const unsigned char*)m;
#pragma unroll
        for (int j = 0; j < 4; j++) v[j] = p[base + 32 * j] != 0;
    } else {
        const float* p = (const float*)m;
#pragma unroll
        for (int j = 0; j < 4; j++) v[j] = p[base + 32 * j] != 0.f;
    }
    unsigned b0 = __ballot_sync(0xffffffffu, v[0]);
    unsigned b1 = __ballot_sync(0xffffffffu, v[1]);
    unsigned b2 = __ballot_sync(0xffffffffu, v[2]);
    unsigned b3 = __ballot_sync(0xffffffffu, v[3]);
    if (lane == 0) {
        out[wi + 0] = (u64)b0 | ((u64)b1 << 32);
        out[wi + 1] = (u64)b2 | ((u64)b3 << 32);
    }
}

// ---------------------------------------------------------------------------
// fp32 -> fp16 round (single tensor)
__global__ __launch_bounds__(256) void round1_kernel(
    const float* __restrict__ x, __half* __restrict__ out, int n)
{
    int i = (blockIdx.x * 256 + threadIdx.x) * 4;
    if (i >= n) return;
    float4 v = *(const float4*)(x + i);
    *(uint2*)(out + i) = make_uint2(pack_h(v.x, v.y), pack_h(v.z, v.w));
}
// fp32 -> fp16 round (4 weights)
__global__ __launch_bounds__(256) void round_h_kernel(
    const float* __restrict__ w0, const float* __restrict__ w1,
    const float* __restrict__ w2, const float* __restrict__ w3,
    __half* __restrict__ out, int nw)
{
    int i = (blockIdx.x * 256 + threadIdx.x) * 4;
    const float* src = (i < nw) ? w0 : (i < 2 * nw) ? w1 : (i < 3 * nw) ? w2 : w3;
    int j = i & (nw - 1);
    float4 v = *(const float4*)(src + j);
    *(uint2*)(out + i) = make_uint2(pack_h(v.x, v.y), pack_h(v.z, v.w));
}

// ---------------------------------------------------------------------------
// GEMM (NT): out = alpha*(Ahi[+Alo])*Wh^T (+bias). 1- or 2-term fp16.
// CTA 128x128, BK=32, 8 warps @ 32x64, 3-stage cp.async pipeline.
// ---------------------------------------------------------------------------
#define MBK    32
#define PITCH  80
#define TILE_B (128 * PITCH)          // 10240

template <bool TWO>
__device__ __forceinline__ void gemm_body(
    const __half* __restrict__ Ahi, const __half* __restrict__ Alo,
    const __half* __restrict__ Wh,
    const float* __restrict__ bias, float* __restrict__ Cf,
    __half* __restrict__ Chi, __half* __restrict__ Clo,
    int N, int K, float alpha, char* dsm)
{
    constexpr uint32_t SMAL = TILE_B;                       // Alo field (TWO only)
    constexpr uint32_t SMW  = TWO ? 2u * TILE_B : TILE_B;   // W field
    constexpr uint32_t BUF  = TWO ? 3u * TILE_B : 2u * TILE_B;

    const uint32_t sbase = smem_u32(dsm);
    const int tid  = threadIdx.x;
    const int wid  = tid >> 5;
    const int lane = tid & 31;
    const int wm   = wid & 3;
    const int wn   = wid >> 2;
    const int m0   = blockIdx.y * 128;
    const int n0   = blockIdx.x * 128;

    const int q8  = lane >> 3;
    const int rin = lane & 7;
    const uint32_t lmoff = (uint32_t)(((q8 & 1) * 8 + rin) * PITCH + (q8 >> 1) * 16);

    const int lr0 = tid >> 2, lc0 = tid & 3;
    const int lr1 = (tid + 256) >> 2, lc1 = (tid + 256) & 3;
    const __half* gA0  = Ahi + (size_t)(m0 + lr0) * K + lc0 * 8;
    const __half* gA1  = Ahi + (size_t)(m0 + lr1) * K + lc1 * 8;
    const __half* gAl0 = TWO ? Alo + (size_t)(m0 + lr0) * K + lc0 * 8 : gA0;
    const __half* gAl1 = TWO ? Alo + (size_t)(m0 + lr1) * K + lc1 * 8 : gA1;
    const __half* gW0  = Wh + (size_t)(n0 + lr0) * K + lc0 * 8;
    const __half* gW1  = Wh + (size_t)(n0 + lr1) * K + lc1 * 8;
    const uint32_t s0 = lr0 * PITCH + lc0 * 16;
    const uint32_t s1 = lr1 * PITCH + lc1 * 16;

#define G_ISSUE(kb, bufo) do {                                                \
    const int _ko = (kb) * MBK;                                               \
    const uint32_t _d = sbase + (bufo);                                       \
    CP16(_d + s0, gA0 + _ko);  CP16(_d + s1, gA1 + _ko);                      \
    if (TWO) { CP16(_d + SMAL + s0, gAl0 + _ko);                              \
               CP16(_d + SMAL + s1, gAl1 + _ko); }                            \
    CP16(_d + SMW + s0, gW0 + _ko);   CP16(_d + SMW + s1, gW1 + _ko);         \
} while (0)

    float acc[2][8][4];
#pragma unroll
    for (int s = 0; s < 2; s++)
#pragma unroll
        for (int n = 0; n < 8; n++)
#pragma unroll
            for (int r = 0; r < 4; r++) acc[s][n][r] = 0.f;

    G_ISSUE(0, 0);
    CP_COMMIT();
    G_ISSUE(1, BUF);
    CP_COMMIT();

    const int nkb = K / MBK;
    uint32_t bufo = 0;
    uint32_t bufi = 2 * BUF;
    for (int kb = 0; kb < nkb; kb++) {
        if (kb + 1 < nkb) CP_WAIT1(); else CP_WAIT0();
        __syncthreads();
        if (kb + 2 < nkb) {
            G_ISSUE(kb + 2, bufi);
            CP_COMMIT();
            bufi = (bufi == 2 * BUF) ? 0 : bufi + BUF;
        }

        const uint32_t tb32 = sbase + bufo;
        const uint32_t aoff = tb32 + (wm * 32) * PITCH + lmoff;
        const uint32_t woff = tb32 + (wn * 64) * PITCH + lmoff;

#pragma unroll
        for (int ks = 0; ks < 2; ks++) {
            const uint32_t kso = ks * 32;
            uint32_t ahi[2][4], alo[2][4];
#pragma unroll
            for (int s = 0; s < 2; s++) {
                ldsm_x4(ahi[s], aoff + s * 16 * PITCH + kso);
                if (TWO) ldsm_x4(alo[s], aoff + SMAL + s * 16 * PITCH + kso);
            }
#pragma unroll
            for (int g = 0; g < 4; g++) {
                uint32_t rh[4];
                ldsm_x4(rh, woff + SMW + g * 16 * PITCH + kso);
                uint32_t b0[2] = {rh[0], rh[2]}, b1[2] = {rh[1], rh[3]};
#pragma unroll
                for (int s = 0; s < 2; s++) {
                    mma_f16(acc[s][2 * g], ahi[s], b0);
                    if (TWO) mma_f16(acc[s][2 * g], alo[s], b0);
                    mma_f16(acc[s][2 * g + 1], ahi[s], b1);
                    if (TWO) mma_f16(acc[s][2 * g + 1], alo[s], b1);
                }
            }
        }
        bufo = (bufo == 2 * BUF) ? 0 : bufo + BUF;
    }

#pragma unroll
    for (int s = 0; s < 2; s++) {
        const int r0 = m0 + wm * 32 + s * 16 + (lane >> 2);
#pragma unroll
        for (int n = 0; n < 8; n++) {
            const int col = n0 + wn * 64 + n * 8 + (lane & 3) * 2;
            const float b0 = bias ? bias[col] : 0.f;
            const float b1 = bias ? bias[col + 1] : 0.f;
            const float v0 = alpha * acc[s][n][0] + b0;
            const float v1 = alpha * acc[s][n][1] + b1;
            const float v2 = alpha * acc[s][n][2] + b0;
            const float v3 = alpha * acc[s][n][3] + b1;
            if (Cf) {
                *(float2*)&Cf[(size_t)r0 * N + col] = make_float2(v0, v1);
                *(float2*)&Cf[(size_t)(r0 + 8) * N + col] = make_float2(v2, v3);
            } else if (Clo) {
                uint32_t h, l;
                split_pack_h(v0, v1, h, l);
                *(uint32_t*)&Chi[(size_t)r0 * N + col] = h;
                *(uint32_t*)&Clo[(size_t)r0 * N + col] = l;
                split_pack_h(v2, v3, h, l);
                *(uint32_t*)&Chi[(size_t)(r0 + 8) * N + col] = h;
                *(uint32_t*)&Clo[(size_t)(r0 + 8) * N + col] = l;
            } else {
                *(uint32_t*)&Chi[(size_t)r0 * N + col] = pack_h(v0, v1);
                *(uint32_t*)&Chi[(size_t)(r0 + 8) * N + col] = pack_h(v2, v3);
            }
        }
    }
#undef G_ISSUE
}

// QKV projection, 1-term (x rounded to fp16). Q gets hi/lo split output.
__global__ __launch_bounds__(256, 2) void gemm_qkv(
    const __half* __restrict__ inh, const __half* __restrict__ wh,
    __half* __restrict__ Qhi, __half* __restrict__ Qlo,
    __half* __restrict__ Khi, __half* __restrict__ Vhi)
{
    extern __shared__ char dsm[];
    const int z = blockIdx.z;
    const int nw = D_MODEL * D_MODEL;
    const __half* Wh = wh + (size_t)z * nw;
    __half* Chi = (z == 0) ? Qhi : (z == 1) ? Khi : Vhi;
    __half* Clo = (z == 0) ? Qlo : nullptr;
    const float alpha = (z == 0) ? QSCALE : 1.0f;
    gemm_body<false>(inh, nullptr, Wh, nullptr, nullptr, Chi, Clo,
                     D_MODEL, D_MODEL, alpha, dsm);
}

// Output projection, 2-term (O hi/lo), fp32 + bias.
__global__ __launch_bounds__(256, 2) void gemm_out(
    const __half* __restrict__ Ahi, const __half* __restrict__ Alo,
    const __half* __restrict__ Wh,
    const float* __restrict__ bias, float* __restrict__ Cf)
{
    extern __shared__ char dsm[];
    gemm_body<true>(Ahi, Alo, Wh, bias, Cf, nullptr, nullptr,
                    D_MODEL, D_MODEL, 1.0f, dsm);
}

// ---------------------------------------------------------------------------
// Tensor-core flash attention, k-tile 64, q-tile 128, 3-stage pipeline.
// QK^T: 2-term ((Qhi+Qlo)*Khi). PV: 2-term (P hi/lo, V hi). Bitmask.
// ---------------------------------------------------------------------------
#define APB    144
#define KTROWS 64
#define KREG   (KTROWS * APB)         // 9216
#define S_KHI  0
#define S_VHI  (1 * KREG)
#define ABUF   (2 * KREG)             // 18432 per stage
#define NKT    (N_SEQ / KTROWS)       // 32

__global__ __launch_bounds__(256, 2) void attn_mma(
    const __half* __restrict__ Qhi, const __half* __restrict__ Qlo,
    const __half* __restrict__ Khi, const __half* __restrict__ Vhi,
    const u64* __restrict__ mbits,
    __half* __restrict__ Ohi, __half* __restrict__ Olo)
{
    extern __shared__ char smemb[];
    const uint32_t sb = smem_u32(smemb);

    const int tid  = threadIdx.x;
    const int warp = tid >> 5;
    const int lane = tid & 31;
    const int gq   = lane >> 2;
    const int tig  = lane & 3;
    const int q8   = lane >> 3;
    const int rin  = lane & 7;
    const uint32_t lmoff = (uint32_t)(((q8 & 1) * 8 + rin) * APB + (q8 >> 1) * 16);
    const int wrow = warp * 16;

    const int bh = blockIdx.y;
    const int b  = bh >> 4;
    const int h  = bh & 15;
    const int q0 = blockIdx.x * 128;
    const size_t rowbase = (size_t)b * N_SEQ;
    const int hoff = h * DHEAD;

    // ---- stage Q (128 rows): Qhi in stage0/1 S_KHI, Qlo in stage0/1 S_VHI ----
#pragma unroll
    for (int i = 0; i < 4; i++) {
        const int c = tid + 256 * i;
        const int row = c >> 3, colc = c & 7;
        const size_t src = (rowbase + q0 + row) * D_MODEL + hoff + colc * 8;
        const uint32_t off = (row >= 64 ? ABUF : 0) + (row & 63) * APB + colc * 16;
        *(uint4*)(smemb + S_KHI + off) = *(const uint4*)(Qhi + src);
        *(uint4*)(smemb + S_VHI + off) = *(const uint4*)(Qlo + src);
    }
    __syncthreads();
    uint32_t aQh[4][4], aQl[4][4];
    {
        const uint32_t qb = sb + (wrow >= 64 ? ABUF : 0) + (wrow & 63) * APB + lmoff;
#pragma unroll
        for (int ks = 0; ks < 4; ks++) {
            ldsm_x4(aQh[ks], qb + S_KHI + ks * 32);
            ldsm_x4(aQl[ks], qb + S_VHI + ks * 32);
        }
    }
    __syncthreads();

    float oacc[8][4];
#pragma unroll
    for (int n = 0; n < 8; n++)
#pragma unroll
        for (int r = 0; r < 4; r++) oacc[n][r] = 0.f;
    float mrow0 = NEGINF, mrow1 = NEGINF, lrow0 = 0.f, lrow1 = 0.f;

#define ISSUE_TILES(kt, bo) do {                                              \
    _Pragma("unroll")                                                         \
    for (int i = 0; i < 2; i++) {                                             \
        const int c = tid + 256 * i;                                          \
        const int row = c >> 3, colc = c & 7;                                 \
        const size_t src = (rowbase + (kt) * KTROWS + row) * D_MODEL + hoff + colc * 8; \
        const uint32_t dst = sb + (bo) + row * APB + colc * 16;               \
        CP16(dst + S_KHI, Khi + src);                                         \
        CP16(dst + S_VHI, Vhi + src);                                         \
    }                                                                         \
} while (0)

    ISSUE_TILES(0, 0);
    CP_COMMIT();
    ISSUE_TILES(1, ABUF);
    CP_COMMIT();

    const u64* mb0 = mbits + (size_t)(b * N_SEQ + q0 + wrow + gq) * (N_SEQ / 64);
    const u64* mb1 = mb0 + 8 * (N_SEQ / 64);

    uint32_t bo = 0;
    uint32_t bi = 2 * ABUF;
    for (int kt = 0; kt < NKT; kt++) {
        if (kt + 1 < NKT) CP_WAIT1(); else CP_WAIT0();
        __syncthreads();
        if (kt + 2 < NKT) {
            ISSUE_TILES(kt + 2, bi);
            CP_COMMIT();
            bi = (bi == 2 * ABUF) ? 0 : bi + ABUF;
        }

        // ---- S = (Qhi+Qlo) Khi^T (2-term fp16) ----
        float sc[8][4];
#pragma unroll
        for (int n = 0; n < 8; n++)
#pragma unroll
            for (int r = 0; r < 4; r++) sc[n][r] = 0.f;

#pragma unroll
        for (int ks = 0; ks < 4; ks++) {
#pragma unroll
            for (int g2 = 0; g2 < 4; g2++) {
                uint32_t rh[4];
                const uint32_t ka = sb + bo + g2 * 16 * APB + lmoff + ks * 32;
                ldsm_x4(rh, ka + S_KHI);
                uint32_t b0h[2] = {rh[0], rh[2]}, b1h[2] = {rh[1], rh[3]};
                mma_f16(sc[2 * g2], aQh[ks], b0h);
                mma_f16(sc[2 * g2], aQl[ks], b0h);
                mma_f16(sc[2 * g2 + 1], aQh[ks], b1h);
                mma_f16(sc[2 * g2 + 1], aQl[ks], b1h);
            }
        }

        // ---- mask from packed bits ----
        {
            const u64 w0 = mb0[kt];
            const u64 w1 = mb1[kt];
#pragma unroll
            for (int n = 0; n < 8; n++) {
                const unsigned s0 = (unsigned)(w0 >> (8 * n + 2 * tig));
                const unsigned s1 = (unsigned)(w1 >> (8 * n + 2 * tig));
                if (s0 & 1) sc[n][0] = NEGINF;
                if (s0 & 2) sc[n][1] = NEGINF;
                if (s1 & 1) sc[n][2] = NEGINF;
                if (s1 & 2) sc[n][3] = NEGINF;
            }
        }

        // ---- online softmax ----
        float mx0 = NEGINF, mx1 = NEGINF;
#pragma unroll
        for (int n = 0; n < 8; n++) {
            mx0 = fmaxf(mx0, fmaxf(sc[n][0], sc[n][1]));
            mx1 = fmaxf(mx1, fmaxf(sc[n][2], sc[n][3]));
        }
        mx0 = fmaxf(mx0, __shfl_xor_sync(0xffffffffu, mx0, 1));
        mx0 = fmaxf(mx0, __shfl_xor_sync(0xffffffffu, mx0, 2));
        mx1 = fmaxf(mx1, __shfl_xor_sync(0xffffffffu, mx1, 1));
        mx1 = fmaxf(mx1, __shfl_xor_sync(0xffffffffu, mx1, 2));

        const float mn0 = fmaxf(mrow0, mx0);
        const float mn1 = fmaxf(mrow1, mx1);
        const float f0 = __expf(mrow0 - mn0);
        const float f1 = __expf(mrow1 - mn1);

        float sum0 = 0.f, sum1 = 0.f;
#pragma unroll
        for (int n = 0; n < 8; n++) {
            sc[n][0] = __expf(sc[n][0] - mn0); sum0 += sc[n][0];
            sc[n][1] = __expf(sc[n][1] - mn0); sum0 += sc[n][1];
            sc[n][2] = __expf(sc[n][2] - mn1); sum1 += sc[n][2];
            sc[n][3] = __expf(sc[n][3] - mn1); sum1 += sc[n][3];
        }
        sum0 += __shfl_xor_sync(0xffffffffu, sum0, 1);
        sum0 += __shfl_xor_sync(0xffffffffu, sum0, 2);
        sum1 += __shfl_xor_sync(0xffffffffu, sum1, 1);
        sum1 += __shfl_xor_sync(0xffffffffu, sum1, 2);

        lrow0 = lrow0 * f0 + sum0; mrow0 = mn0;
        lrow1 = lrow1 * f1 + sum1; mrow1 = mn1;
#pragma unroll
        for (int n = 0; n < 8; n++) {
            oacc[n][0] *= f0; oacc[n][1] *= f0;
            oacc[n][2] *= f1; oacc[n][3] *= f1;
        }

        // ---- O += P V (2-term: P hi/lo, V hi) ----
#pragma unroll
        for (int kk = 0; kk < 4; kk++) {
            uint32_t aPh[4], aPl[4];
            split_pack_h(sc[2 * kk][0], sc[2 * kk][1], aPh[0], aPl[0]);
            split_pack_h(sc[2 * kk][2], sc[2 * kk][3], aPh[1], aPl[1]);
            split_pack_h(sc[2 * kk + 1][0], sc[2 * kk + 1][1], aPh[2], aPl[2]);
            split_pack_h(sc[2 * kk + 1][2], sc[2 * kk + 1][3], aPh[3], aPl[3]);
#pragma unroll
            for (int g2 = 0; g2 < 4; g2++) {
                uint32_t rh[4];
                const uint32_t va = sb + bo + kk * 16 * APB + lmoff + g2 * 32;
                ldsm_x4_t(rh, va + S_VHI);
                uint32_t b0[2] = {rh[0], rh[1]}, b1[2] = {rh[2], rh[3]};
                mma_f16(oacc[2 * g2], aPh, b0);
                mma_f16(oacc[2 * g2], aPl, b0);
                mma_f16(oacc[2 * g2 + 1], aPh, b1);
                mma_f16(oacc[2 * g2 + 1], aPl, b1);
            }
        }
        bo = (bo == 2 * ABUF) ? 0 : bo + ABUF;
    }

    // ---- normalize + write fp16 hi/lo ----
    const float inv0 = 1.f / lrow0;
    const float inv1 = 1.f / lrow1;
    const size_t orow0 = (rowbase + q0 + wrow + gq) * D_MODEL + hoff;
    const size_t orow1 = orow0 + 8 * D_MODEL;
#pragma unroll
    for (int n = 0; n < 8; n++) {
        const int col = 8 * n + 2 * tig;
        uint32_t hh, ll;
        split_pack_h(oacc[n][0] * inv0, oacc[n][1] * inv0, hh, ll);
        *(uint32_t*)&Ohi[orow0 + col] = hh;
        *(uint32_t*)&Olo[orow0 + col] = ll;
        split_pack_h(oacc[n][2] * inv1, oacc[n][3] * inv1, hh, ll);
        *(uint32_t*)&Ohi[orow1 + col] = hh;
        *(uint32_t*)&Olo[orow1 + col] = ll;
    }
}

// ---------------------------------------------------------------------------
extern "C" void kernel_launch(void* const* d_in, const int* in_sizes, int n_in,
                              void* d_out, int out_size)
{
    const float* q  = (const float*)d_in[0];
    const void*  mk = d_in[1];
    const float* Wq = (const float*)d_in[2];
    const float* Wk = (const float*)d_in[3];
    const float* Wv = (const float*)d_in[4];
    const float* Wo = (const float*)d_in[5];
    const float* bo = (const float*)d_in[6];
    float* out      = (float*)d_out;

    __half *inh, *Qhi, *Qlo, *Khi, *Vhi, *Ohi, *Olo, *wh;
    u64* mbits;
    cudaGetSymbolAddress((void**)&inh, g_inh);
    cudaGetSymbolAddress((void**)&Qhi, g_Qhi);
    cudaGetSymbolAddress((void**)&Qlo, g_Qlo);
    cudaGetSymbolAddress((void**)&Khi, g_Khi);
    cudaGetSymbolAddress((void**)&Vhi, g_Vhi);
    cudaGetSymbolAddress((void**)&Ohi, g_Ohi);
    cudaGetSymbolAddress((void**)&Olo, g_Olo);
    cudaGetSymbolAddress((void**)&wh, g_wh);
    cudaGetSymbolAddress((void**)&mbits, g_mbits);

    detect_mask_kind<<<1, 256>>>((const unsigned char*)mk);

    const int nq = MTOT * D_MODEL;
    const int nw = D_MODEL * D_MODEL;
    round1_kernel<<<nq / 1024, 256>>>(q, inh, nq);
    round_h_kernel<<<4 * nw / 1024, 256>>>(Wq, Wk, Wv, Wo, wh, nw);
    pack_mask<<<(BATCH * N_SEQ * (N_SEQ / 64)) / 16, 256>>>(mk, mbits);

    const int qkv_smem = 3 * 2 * TILE_B;   // 61440
    const int out_smem = 3 * 3 * TILE_B;   // 92160
    cudaFuncSetAttribute(gemm_qkv, cudaFuncAttributeMaxDynamicSharedMemorySize,
                         qkv_smem);
    cudaFuncSetAttribute(gemm_out, cudaFuncAttributeMaxDynamicSharedMemorySize,
                         out_smem);

    gemm_qkv<<<dim3(D_MODEL / 128, MTOT / 128, 3), 256, qkv_smem>>>(
        inh, wh, Qhi, Qlo, Khi, Vhi);

    const int attn_smem = 3 * ABUF;   // 55296
    cudaFuncSetAttribute(attn_mma, cudaFuncAttributeMaxDynamicSharedMemorySize,
                         attn_smem);
    attn_mma<<<dim3(N_SEQ / 128, BATCH * NHEADS), 256, attn_smem>>>(
        Qhi, Qlo, Khi, Vhi, mbits, Ohi, Olo);

    gemm_out<<<dim3(D_MODEL / 128, MTOT / 128), 256, out_smem>>>(
        Ohi, Olo, wh + 3 * (size_t)nw, bo, out);
}

// round 13
// speedup vs baseline: 5.0581x; 1.0904x over previous
#include <cuda_runtime.h>
#include <cuda_fp16.h>
#include <math.h>
#include <stdint.h>

#define D_MODEL 1024
#define N_SEQ   2048
#define BATCH   2
#define NHEADS  16
#define DHEAD   64
#define QSCALE  0.125f
#define MTOT    (BATCH * N_SEQ)   // 4096
#define NEGINF  -1.0e30f
typedef unsigned long long u64;

// ---- mma.sync helpers ----
__device__ __forceinline__ uint32_t smem_u32(const void* p) {
    uint32_t a;
    asm("{ .reg .u64 t; cvta.to.shared.u64 t, %1; cvt.u32.u64 %0, t; }"
        : "=r"(a) : "l"(p));
    return a;
}
__device__ __forceinline__ void ldsm_x4(uint32_t* r, uint32_t addr) {
    asm volatile("ldmatrix.sync.aligned.m8n8.x4.shared.b16 {%0,%1,%2,%3}, [%4];"
        : "=r"(r[0]), "=r"(r[1]), "=r"(r[2]), "=r"(r[3]) : "r"(addr));
}
__device__ __forceinline__ void ldsm_x4_t(uint32_t* r, uint32_t addr) {
    asm volatile("ldmatrix.sync.aligned.m8n8.x4.trans.shared.b16 {%0,%1,%2,%3}, [%4];"
        : "=r"(r[0]), "=r"(r[1]), "=r"(r[2]), "=r"(r[3]) : "r"(addr));
}
__device__ __forceinline__ void mma_f16(float* d, const uint32_t* a,
                                        const uint32_t* b) {
    asm volatile(
        "mma.sync.aligned.m16n8k16.row.col.f32.f16.f16.f32 "
        "{%0,%1,%2,%3}, {%4,%5,%6,%7}, {%8,%9}, {%0,%1,%2,%3};"
        : "+f"(d[0]), "+f"(d[1]), "+f"(d[2]), "+f"(d[3])
        : "r"(a[0]), "r"(a[1]), "r"(a[2]), "r"(a[3]), "r"(b[0]), "r"(b[1]));
}
__device__ __forceinline__ void split_pack_h(float v0, float v1,
                                             uint32_t& h, uint32_t& l) {
    __half h0 = __float2half_rn(v0);
    __half h1 = __float2half_rn(v1);
    float r0 = v0 - __half2float(h0);
    float r1 = v1 - __half2float(h1);
    __half2 hh = __halves2half2(h0, h1);
    __half2 ll = __halves2half2(__float2half_rn(r0), __float2half_rn(r1));
    h = *(uint32_t*)&hh;
    l = *(uint32_t*)&ll;
}
__device__ __forceinline__ uint32_t pack_h(float v0, float v1) {
    __half2 hh = __halves2half2(__float2half_rn(v0), __float2half_rn(v1));
    return *(uint32_t*)&hh;
}
#define CP16(dst, src) \
    asm volatile("cp.async.cg.shared.global [%0], [%1], 16;" \
                 :: "r"(dst), "l"(src) : "memory")
#define CP_COMMIT() asm volatile("cp.async.commit_group;" ::: "memory")
#define CP_WAIT0()  asm volatile("cp.async.wait_group 0;" ::: "memory")
#define CP_WAIT1()  asm volatile("cp.async.wait_group 1;" ::: "memory")

// ---- scratch (device globals) ----
__device__ __half g_inh[MTOT * D_MODEL];
__device__ __half g_Qhi[MTOT * D_MODEL];
__device__ __half g_Qlo[MTOT * D_MODEL];
__device__ __half g_Khi[MTOT * D_MODEL];
__device__ __half g_Vhi[MTOT * D_MODEL];
__device__ __half g_Ohi[MTOT * D_MODEL];
__device__ __half g_Olo[MTOT * D_MODEL];
__device__ __half g_wh[4][D_MODEL * D_MODEL];
__device__ u64    g_mbits[BATCH * N_SEQ * (N_SEQ / 64)];
__device__ int    g_mask_kind;

// ---------------------------------------------------------------------------
__global__ void detect_mask_kind(const unsigned char* __restrict__ m)
{
    __shared__ int s_maxb, s_nzoff;
    if (threadIdx.x == 0) { s_maxb = 0; s_nzoff = 0; }
    __syncthreads();
    int maxb = 0, nzoff = 0;
    for (int i = threadIdx.x; i < 65536; i += blockDim.x) {
        int v = m[i];
        if (v > maxb) maxb = v;
        if (v && (i & 3)) nzoff++;
    }
    atomicMax(&s_maxb, maxb);
    atomicAdd(&s_nzoff, nzoff);
    __syncthreads();
    if (threadIdx.x == 0)
        g_mask_kind = (s_maxb > 1) ? 2 : (s_nzoff ? 0 : 1);
}

// ---------------------------------------------------------------------------
// Pack mask to bits. Each warp packs 2 u64 words (128 elems, stride-32 lanes).
// ---------------------------------------------------------------------------
__global__ __launch_bounds__(256) void pack_mask(
    const void* __restrict__ m, u64* __restrict__ out)
{
    const int kind = g_mask_kind;
    const int wp   = blockIdx.x * 8 + (threadIdx.x >> 5);
    const int wi   = wp * 2;
    const int lane = threadIdx.x & 31;
    const int wpr  = N_SEQ / 64;   // 32
    const size_t base = (size_t)(wi / wpr) * N_SEQ + (size_t)(wi % wpr) * 64 + lane;
    bool v[4];
    if (kind == 1) {
        const int* p = (const int*)m;
#pragma unroll
        for (int j = 0; j < 4; j++) v[j] = p[base + 32 * j] != 0;
    } else if (kind == 0) {
        const unsigned char* p = (const unsigned char*)m;
#pragma unroll
        for (int j = 0; j < 4; j++) v[j] = p[base + 32 * j] != 0;
    } else {
        const float* p = (const float*)m;
#pragma unroll
        for (int j = 0; j < 4; j++) v[j] = p[base + 32 * j] != 0.f;
    }
    unsigned b0 = __ballot_sync(0xffffffffu, v[0]);
    unsigned b1 = __ballot_sync(0xffffffffu, v[1]);
    unsigned b2 = __ballot_sync(0xffffffffu, v[2]);
    unsigned b3 = __ballot_sync(0xffffffffu, v[3]);
    if (lane == 0) {
        out[wi + 0] = (u64)b0 | ((u64)b1 << 32);
        out[wi + 1] = (u64)b2 | ((u64)b3 << 32);
    }
}

// ---------------------------------------------------------------------------
__global__ __launch_bounds__(256) void round1_kernel(
    const float* __restrict__ x, __half* __restrict__ out, int n)
{
    int i = (blockIdx.x * 256 + threadIdx.x) * 4;
    if (i >= n) return;
    float4 v = *(const float4*)(x + i);
    *(uint2*)(out + i) = make_uint2(pack_h(v.x, v.y), pack_h(v.z, v.w));
}
__global__ __launch_bounds__(256) void round_h_kernel(
    const float* __restrict__ w0, const float* __restrict__ w1,
    const float* __restrict__ w2, const float* __restrict__ w3,
    __half* __restrict__ out, int nw)
{
    int i = (blockIdx.x * 256 + threadIdx.x) * 4;
    const float* src = (i < nw) ? w0 : (i < 2 * nw) ? w1 : (i < 3 * nw) ? w2 : w3;
    int j = i & (nw - 1);
    float4 v = *(const float4*)(src + j);
    *(uint2*)(out + i) = make_uint2(pack_h(v.x, v.y), pack_h(v.z, v.w));
}

// ---------------------------------------------------------------------------
// GEMM (NT): out = alpha*(Ahi[+Alo])*Wh^T (+bias). 1- or 2-term fp16.
// CTA 128x128, BK=32, 8 warps @ 32x64, 3-stage cp.async pipeline.
// ---------------------------------------------------------------------------
#define MBK    32
#define PITCH  80
#define TILE_B (128 * PITCH)          // 10240

template <bool TWO>
__device__ __forceinline__ void gemm_body(
    const __half* __restrict__ Ahi, const __half* __restrict__ Alo,
    const __half* __restrict__ Wh,
    const float* __restrict__ bias, float* __restrict__ Cf,
    __half* __restrict__ Chi, __half* __restrict__ Clo,
    int N, int K, float alpha, char* dsm)
{
    constexpr uint32_t SMAL = TILE_B;
    constexpr uint32_t SMW  = TWO ? 2u * TILE_B : TILE_B;
    constexpr uint32_t BUF  = TWO ? 3u * TILE_B : 2u * TILE_B;

    const uint32_t sbase = smem_u32(dsm);
    const int tid  = threadIdx.x;
    const int wid  = tid >> 5;
    const int lane = tid & 31;
    const int wm   = wid & 3;
    const int wn   = wid >> 2;
    const int m0   = blockIdx.y * 128;
    const int n0   = blockIdx.x * 128;

    const int q8  = lane >> 3;
    const int rin = lane & 7;
    const uint32_t lmoff = (uint32_t)(((q8 & 1) * 8 + rin) * PITCH + (q8 >> 1) * 16);

    const int lr0 = tid >> 2, lc0 = tid & 3;
    const int lr1 = (tid + 256) >> 2, lc1 = (tid + 256) & 3;
    const __half* gA0  = Ahi + (size_t)(m0 + lr0) * K + lc0 * 8;
    const __half* gA1  = Ahi + (size_t)(m0 + lr1) * K + lc1 * 8;
    const __half* gAl0 = TWO ? Alo + (size_t)(m0 + lr0) * K + lc0 * 8 : gA0;
    const __half* gAl1 = TWO ? Alo + (size_t)(m0 + lr1) * K + lc1 * 8 : gA1;
    const __half* gW0  = Wh + (size_t)(n0 + lr0) * K + lc0 * 8;
    const __half* gW1  = Wh + (size_t)(n0 + lr1) * K + lc1 * 8;
    const uint32_t s0 = lr0 * PITCH + lc0 * 16;
    const uint32_t s1 = lr1 * PITCH + lc1 * 16;

#define G_ISSUE(kb, bufo) do {                                                \
    const int _ko = (kb) * MBK;                                               \
    const uint32_t _d = sbase + (bufo);                                       \
    CP16(_d + s0, gA0 + _ko);  CP16(_d + s1, gA1 + _ko);                      \
    if (TWO) { CP16(_d + SMAL + s0, gAl0 + _ko);                              \
               CP16(_d + SMAL + s1, gAl1 + _ko); }                            \
    CP16(_d + SMW + s0, gW0 + _ko);   CP16(_d + SMW + s1, gW1 + _ko);         \
} while (0)

    float acc[2][8][4];
#pragma unroll
    for (int s = 0; s < 2; s++)
#pragma unroll
        for (int n = 0; n < 8; n++)
#pragma unroll
            for (int r = 0; r < 4; r++) acc[s][n][r] = 0.f;

    G_ISSUE(0, 0);
    CP_COMMIT();
    G_ISSUE(1, BUF);
    CP_COMMIT();

    const int nkb = K / MBK;
    uint32_t bufo = 0;
    uint32_t bufi = 2 * BUF;
    for (int kb = 0; kb < nkb; kb++) {
        if (kb + 1 < nkb) CP_WAIT1(); else CP_WAIT0();
        __syncthreads();
        if (kb + 2 < nkb) {
            G_ISSUE(kb + 2, bufi);
            CP_COMMIT();
            bufi = (bufi == 2 * BUF) ? 0 : bufi + BUF;
        }

        const uint32_t tb32 = sbase + bufo;
        const uint32_t aoff = tb32 + (wm * 32) * PITCH + lmoff;
        const uint32_t woff = tb32 + (wn * 64) * PITCH + lmoff;

#pragma unroll
        for (int ks = 0; ks < 2; ks++) {
            const uint32_t kso = ks * 32;
            uint32_t ahi[2][4], alo[2][4];
#pragma unroll
            for (int s = 0; s < 2; s++) {
                ldsm_x4(ahi[s], aoff + s * 16 * PITCH + kso);
                if (TWO) ldsm_x4(alo[s], aoff + SMAL + s * 16 * PITCH + kso);
            }
#pragma unroll
            for (int g = 0; g < 4; g++) {
                uint32_t rh[4];
                ldsm_x4(rh, woff + SMW + g * 16 * PITCH + kso);
                uint32_t b0[2] = {rh[0], rh[2]}, b1[2] = {rh[1], rh[3]};
#pragma unroll
                for (int s = 0; s < 2; s++) {
                    mma_f16(acc[s][2 * g], ahi[s], b0);
                    if (TWO) mma_f16(acc[s][2 * g], alo[s], b0);
                    mma_f16(acc[s][2 * g + 1], ahi[s], b1);
                    if (TWO) mma_f16(acc[s][2 * g + 1], alo[s], b1);
                }
            }
        }
        bufo = (bufo == 2 * BUF) ? 0 : bufo + BUF;
    }

#pragma unroll
    for (int s = 0; s < 2; s++) {
        const int r0 = m0 + wm * 32 + s * 16 + (lane >> 2);
#pragma unroll
        for (int n = 0; n < 8; n++) {
            const int col = n0 + wn * 64 + n * 8 + (lane & 3) * 2;
            const float b0 = bias ? bias[col] : 0.f;
            const float b1 = bias ? bias[col + 1] : 0.f;
            const float v0 = alpha * acc[s][n][0] + b0;
            const float v1 = alpha * acc[s][n][1] + b1;
            const float v2 = alpha * acc[s][n][2] + b0;
            const float v3 = alpha * acc[s][n][3] + b1;
            if (Cf) {
                *(float2*)&Cf[(size_t)r0 * N + col] = make_float2(v0, v1);
                *(float2*)&Cf[(size_t)(r0 + 8) * N + col] = make_float2(v2, v3);
            } else if (Clo) {
                uint32_t h, l;
                split_pack_h(v0, v1, h, l);
                *(uint32_t*)&Chi[(size_t)r0 * N + col] = h;
                *(uint32_t*)&Clo[(size_t)r0 * N + col] = l;
                split_pack_h(v2, v3, h, l);
                *(uint32_t*)&Chi[(size_t)(r0 + 8) * N + col] = h;
                *(uint32_t*)&Clo[(size_t)(r0 + 8) * N + col] = l;
            } else {
                *(uint32_t*)&Chi[(size_t)r0 * N + col] = pack_h(v0, v1);
                *(uint32_t*)&Chi[(size_t)(r0 + 8) * N + col] = pack_h(v2, v3);
            }
        }
    }
#undef G_ISSUE
}

// QKV projection, 1-term (x rounded to fp16). Q gets hi/lo split output.
__global__ __launch_bounds__(256, 2) void gemm_qkv(
    const __half* __restrict__ inh, const __half* __restrict__ wh,
    __half* __restrict__ Qhi, __half* __restrict__ Qlo,
    __half* __restrict__ Khi, __half* __restrict__ Vhi)
{
    extern __shared__ char dsm[];
    const int z = blockIdx.z;
    const int nw = D_MODEL * D_MODEL;
    const __half* Wh = wh + (size_t)z * nw;
    __half* Chi = (z == 0) ? Qhi : (z == 1) ? Khi : Vhi;
    __half* Clo = (z == 0) ? Qlo : nullptr;
    const float alpha = (z == 0) ? QSCALE : 1.0f;
    gemm_body<false>(inh, nullptr, Wh, nullptr, nullptr, Chi, Clo,
                     D_MODEL, D_MODEL, alpha, dsm);
}

// Output projection, 2-term (O hi/lo), fp32 + bias.
__global__ __launch_bounds__(256, 2) void gemm_out(
    const __half* __restrict__ Ahi, const __half* __restrict__ Alo,
    const __half* __restrict__ Wh,
    const float* __restrict__ bias, float* __restrict__ Cf)
{
    extern __shared__ char dsm[];
    gemm_body<true>(Ahi, Alo, Wh, bias, Cf, nullptr, nullptr,
                    D_MODEL, D_MODEL, 1.0f, dsm);
}

// ---------------------------------------------------------------------------
// Tensor-core flash attention, k-tile 64, q-tile 128, 3-stage pipeline.
// QK^T: 2-term ((Qhi+Qlo)*Khi). PV: 1-term (P fp16, V hi). Bitmask.
// ---------------------------------------------------------------------------
#define APB    144
#define KTROWS 64
#define KREG   (KTROWS * APB)         // 9216
#define S_KHI  0
#define S_VHI  (1 * KREG)
#define ABUF   (2 * KREG)             // 18432 per stage
#define NKT    (N_SEQ / KTROWS)       // 32

__global__ __launch_bounds__(256, 2) void attn_mma(
    const __half* __restrict__ Qhi, const __half* __restrict__ Qlo,
    const __half* __restrict__ Khi, const __half* __restrict__ Vhi,
    const u64* __restrict__ mbits,
    __half* __restrict__ Ohi, __half* __restrict__ Olo)
{
    extern __shared__ char smemb[];
    const uint32_t sb = smem_u32(smemb);

    const int tid  = threadIdx.x;
    const int warp = tid >> 5;
    const int lane = tid & 31;
    const int gq   = lane >> 2;
    const int tig  = lane & 3;
    const int q8   = lane >> 3;
    const int rin  = lane & 7;
    const uint32_t lmoff = (uint32_t)(((q8 & 1) * 8 + rin) * APB + (q8 >> 1) * 16);
    const int wrow = warp * 16;

    const int bh = blockIdx.y;
    const int b  = bh >> 4;
    const int h  = bh & 15;
    const int q0 = blockIdx.x * 128;
    const size_t rowbase = (size_t)b * N_SEQ;
    const int hoff = h * DHEAD;

    // ---- stage Q (128 rows): Qhi in stage0/1 S_KHI, Qlo in stage0/1 S_VHI ----
#pragma unroll
    for (int i = 0; i < 4; i++) {
        const int c = tid + 256 * i;
        const int row = c >> 3, colc = c & 7;
        const size_t src = (rowbase + q0 + row) * D_MODEL + hoff + colc * 8;
        const uint32_t off = (row >= 64 ? ABUF : 0) + (row & 63) * APB + colc * 16;
        *(uint4*)(smemb + S_KHI + off) = *(const uint4*)(Qhi + src);
        *(uint4*)(smemb + S_VHI + off) = *(const uint4*)(Qlo + src);
    }
    __syncthreads();
    uint32_t aQh[4][4], aQl[4][4];
    {
        const uint32_t qb = sb + (wrow >= 64 ? ABUF : 0) + (wrow & 63) * APB + lmoff;
#pragma unroll
        for (int ks = 0; ks < 4; ks++) {
            ldsm_x4(aQh[ks], qb + S_KHI + ks * 32);
            ldsm_x4(aQl[ks], qb + S_VHI + ks * 32);
        }
    }
    __syncthreads();

    float oacc[8][4];
#pragma unroll
    for (int n = 0; n < 8; n++)
#pragma unroll
        for (int r = 0; r < 4; r++) oacc[n][r] = 0.f;
    float mrow0 = NEGINF, mrow1 = NEGINF, lrow0 = 0.f, lrow1 = 0.f;

#define ISSUE_TILES(kt, bo) do {                                              \
    _Pragma("unroll")                                                         \
    for (int i = 0; i < 2; i++) {                                             \
        const int c = tid + 256 * i;                                          \
        const int row = c >> 3, colc = c & 7;                                 \
        const size_t src = (rowbase + (kt) * KTROWS + row) * D_MODEL + hoff + colc * 8; \
        const uint32_t dst = sb + (bo) + row * APB + colc * 16;               \
        CP16(dst + S_KHI, Khi + src);                                         \
        CP16(dst + S_VHI, Vhi + src);                                         \
    }                                                                         \
} while (0)

    ISSUE_TILES(0, 0);
    CP_COMMIT();
    ISSUE_TILES(1, ABUF);
    CP_COMMIT();

    const u64* mb0 = mbits + (size_t)(b * N_SEQ + q0 + wrow + gq) * (N_SEQ / 64);
    const u64* mb1 = mb0 + 8 * (N_SEQ / 64);

    uint32_t bo = 0;
    uint32_t bi = 2 * ABUF;
    for (int kt = 0; kt < NKT; kt++) {
        if (kt + 1 < NKT) CP_WAIT1(); else CP_WAIT0();
        __syncthreads();
        if (kt + 2 < NKT) {
            ISSUE_TILES(kt + 2, bi);
            CP_COMMIT();
            bi = (bi == 2 * ABUF) ? 0 : bi + ABUF;
        }

        // ---- S = (Qhi+Qlo) Khi^T (2-term fp16) ----
        float sc[8][4];
#pragma unroll
        for (int n = 0; n < 8; n++)
#pragma unroll
            for (int r = 0; r < 4; r++) sc[n][r] = 0.f;

#pragma unroll
        for (int ks = 0; ks < 4; ks++) {
#pragma unroll
            for (int g2 = 0; g2 < 4; g2++) {
                uint32_t rh[4];
                const uint32_t ka = sb + bo + g2 * 16 * APB + lmoff + ks * 32;
                ldsm_x4(rh, ka + S_KHI);
                uint32_t b0h[2] = {rh[0], rh[2]}, b1h[2] = {rh[1], rh[3]};
                mma_f16(sc[2 * g2], aQh[ks], b0h);
                mma_f16(sc[2 * g2], aQl[ks], b0h);
                mma_f16(sc[2 * g2 + 1], aQh[ks], b1h);
                mma_f16(sc[2 * g2 + 1], aQl[ks], b1h);
            }
        }

        // ---- mask from packed bits ----
        {
            const u64 w0 = mb0[kt];
            const u64 w1 = mb1[kt];
#pragma unroll
            for (int n = 0; n < 8; n++) {
                const unsigned s0 = (unsigned)(w0 >> (8 * n + 2 * tig));
                const unsigned s1 = (unsigned)(w1 >> (8 * n + 2 * tig));
                if (s0 & 1) sc[n][0] = NEGINF;
                if (s0 & 2) sc[n][1] = NEGINF;
                if (s1 & 1) sc[n][2] = NEGINF;
                if (s1 & 2) sc[n][3] = NEGINF;
            }
        }

        // ---- online softmax ----
        float mx0 = NEGINF, mx1 = NEGINF;
#pragma unroll
        for (int n = 0; n < 8; n++) {
            mx0 = fmaxf(mx0, fmaxf(sc[n][0], sc[n][1]));
            mx1 = fmaxf(mx1, fmaxf(sc[n][2], sc[n][3]));
        }
        mx0 = fmaxf(mx0, __shfl_xor_sync(0xffffffffu, mx0, 1));
        mx0 = fmaxf(mx0, __shfl_xor_sync(0xffffffffu, mx0, 2));
        mx1 = fmaxf(mx1, __shfl_xor_sync(0xffffffffu, mx1, 1));
        mx1 = fmaxf(mx1, __shfl_xor_sync(0xffffffffu, mx1, 2));

        const float mn0 = fmaxf(mrow0, mx0);
        const float mn1 = fmaxf(mrow1, mx1);
        const float f0 = __expf(mrow0 - mn0);
        const float f1 = __expf(mrow1 - mn1);

        float sum0 = 0.f, sum1 = 0.f;
#pragma unroll
        for (int n = 0; n < 8; n++) {
            sc[n][0] = __expf(sc[n][0] - mn0); sum0 += sc[n][0];
            sc[n][1] = __expf(sc[n][1] - mn0); sum0 += sc[n][1];
            sc[n][2] = __expf(sc[n][2] - mn1); sum1 += sc[n][2];
            sc[n][3] = __expf(sc[n][3] - mn1); sum1 += sc[n][3];
        }
        sum0 += __shfl_xor_sync(0xffffffffu, sum0, 1);
        sum0 += __shfl_xor_sync(0xffffffffu, sum0, 2);
        sum1 += __shfl_xor_sync(0xffffffffu, sum1, 1);
        sum1 += __shfl_xor_sync(0xffffffffu, sum1, 2);

        lrow0 = lrow0 * f0 + sum0; mrow0 = mn0;
        lrow1 = lrow1 * f1 + sum1; mrow1 = mn1;
#pragma unroll
        for (int n = 0; n < 8; n++) {
            oacc[n][0] *= f0; oacc[n][1] *= f0;
            oacc[n][2] *= f1; oacc[n][3] *= f1;
        }

        // ---- O += P V (1-term: P fp16, V hi) ----
#pragma unroll
        for (int kk = 0; kk < 4; kk++) {
            uint32_t aP[4];
            aP[0] = pack_h(sc[2 * kk][0], sc[2 * kk][1]);
            aP[1] = pack_h(sc[2 * kk][2], sc[2 * kk][3]);
            aP[2] = pack_h(sc[2 * kk + 1][0], sc[2 * kk + 1][1]);
            aP[3] = pack_h(sc[2 * kk + 1][2], sc[2 * kk + 1][3]);
#pragma unroll
            for (int g2 = 0; g2 < 4; g2++) {
                uint32_t rh[4];
                const uint32_t va = sb + bo + kk * 16 * APB + lmoff + g2 * 32;
                ldsm_x4_t(rh, va + S_VHI);
                uint32_t b0[2] = {rh[0], rh[1]}, b1[2] = {rh[2], rh[3]};
                mma_f16(oacc[2 * g2], aP, b0);
                mma_f16(oacc[2 * g2 + 1], aP, b1);
            }
        }
        bo = (bo == 2 * ABUF) ? 0 : bo + ABUF;
    }

    // ---- normalize + write fp16 hi/lo ----
    const float inv0 = 1.f / lrow0;
    const float inv1 = 1.f / lrow1;
    const size_t orow0 = (rowbase + q0 + wrow + gq) * D_MODEL + hoff;
    const size_t orow1 = orow0 + 8 * D_MODEL;
#pragma unroll
    for (int n = 0; n < 8; n++) {
        const int col = 8 * n + 2 * tig;
        uint32_t hh, ll;
        split_pack_h(oacc[n][0] * inv0, oacc[n][1] * inv0, hh, ll);
        *(uint32_t*)&Ohi[orow0 + col] = hh;
        *(uint32_t*)&Olo[orow0 + col] = ll;
        split_pack_h(oacc[n][2] * inv1, oacc[n][3] * inv1, hh, ll);
        *(uint32_t*)&Ohi[orow1 + col] = hh;
        *(uint32_t*)&Olo[orow1 + col] = ll;
    }
}

// ---------------------------------------------------------------------------
extern "C" void kernel_launch(void* const* d_in, const int* in_sizes, int n_in,
                              void* d_out, int out_size)
{
    const float* q  = (const float*)d_in[0];
    const void*  mk = d_in[1];
    const float* Wq = (const float*)d_in[2];
    const float* Wk = (const float*)d_in[3];
    const float* Wv = (const float*)d_in[4];
    const float* Wo = (const float*)d_in[5];
    const float* bo = (const float*)d_in[6];
    float* out      = (float*)d_out;

    __half *inh, *Qhi, *Qlo, *Khi, *Vhi, *Ohi, *Olo, *wh;
    u64* mbits;
    cudaGetSymbolAddress((void**)&inh, g_inh);
    cudaGetSymbolAddress((void**)&Qhi, g_Qhi);
    cudaGetSymbolAddress((void**)&Qlo, g_Qlo);
    cudaGetSymbolAddress((void**)&Khi, g_Khi);
    cudaGetSymbolAddress((void**)&Vhi, g_Vhi);
    cudaGetSymbolAddress((void**)&Ohi, g_Ohi);
    cudaGetSymbolAddress((void**)&Olo, g_Olo);
    cudaGetSymbolAddress((void**)&wh, g_wh);
    cudaGetSymbolAddress((void**)&mbits, g_mbits);

    detect_mask_kind<<<1, 256>>>((const unsigned char*)mk);

    const int nq = MTOT * D_MODEL;
    const int nw = D_MODEL * D_MODEL;
    round1_kernel<<<nq / 1024, 256>>>(q, inh, nq);
    round_h_kernel<<<4 * nw / 1024, 256>>>(Wq, Wk, Wv, Wo, wh, nw);
    pack_mask<<<(BATCH * N_SEQ * (N_SEQ / 64)) / 16, 256>>>(mk, mbits);

    const int qkv_smem = 3 * 2 * TILE_B;   // 61440
    const int out_smem = 3 * 3 * TILE_B;   // 92160
    cudaFuncSetAttribute(gemm_qkv, cudaFuncAttributeMaxDynamicSharedMemorySize,
                         qkv_smem);
    cudaFuncSetAttribute(gemm_out, cudaFuncAttributeMaxDynamicSharedMemorySize,
                         out_smem);

    gemm_qkv<<<dim3(D_MODEL / 128, MTOT / 128, 3), 256, qkv_smem>>>(
        inh, wh, Qhi, Qlo, Khi, Vhi);

    const int attn_smem = 3 * ABUF;   // 55296
    cudaFuncSetAttribute(attn_mma, cudaFuncAttributeMaxDynamicSharedMemorySize,
                         attn_smem);
    attn_mma<<<dim3(N_SEQ / 128, BATCH * NHEADS), 256, attn_smem>>>(
        Qhi, Qlo, Khi, Vhi, mbits, Ohi, Olo);

    gemm_out<<<dim3(D_MODEL / 128, MTOT / 128), 256, out_smem>>>(
        Ohi, Olo, wh + 3 * (size_t)nw, bo, out);
}

// round 14
// speedup vs baseline: 5.5407x; 1.0954x over previous
#include <cuda_runtime.h>
#include <cuda_fp16.h>
#include <math.h>
#include <stdint.h>

#define D_MODEL 1024
#define N_SEQ   2048
#define BATCH   2
#define NHEADS  16
#define DHEAD   64
#define QSCALE  0.125f
#define MTOT    (BATCH * N_SEQ)   // 4096
#define NEGINF  -1.0e30f
typedef unsigned long long u64;

// ---- mma.sync helpers ----
__device__ __forceinline__ uint32_t smem_u32(const void* p) {
    uint32_t a;
    asm("{ .reg .u64 t; cvta.to.shared.u64 t, %1; cvt.u32.u64 %0, t; }"
        : "=r"(a) : "l"(p));
    return a;
}
__device__ __forceinline__ void ldsm_x4(uint32_t* r, uint32_t addr) {
    asm volatile("ldmatrix.sync.aligned.m8n8.x4.shared.b16 {%0,%1,%2,%3}, [%4];"
        : "=r"(r[0]), "=r"(r[1]), "=r"(r[2]), "=r"(r[3]) : "r"(addr));
}
__device__ __forceinline__ void ldsm_x4_t(uint32_t* r, uint32_t addr) {
    asm volatile("ldmatrix.sync.aligned.m8n8.x4.trans.shared.b16 {%0,%1,%2,%3}, [%4];"
        : "=r"(r[0]), "=r"(r[1]), "=r"(r[2]), "=r"(r[3]) : "r"(addr));
}
__device__ __forceinline__ void mma_f16(float* d, const uint32_t* a,
                                        const uint32_t* b) {
    asm volatile(
        "mma.sync.aligned.m16n8k16.row.col.f32.f16.f16.f32 "
        "{%0,%1,%2,%3}, {%4,%5,%6,%7}, {%8,%9}, {%0,%1,%2,%3};"
        : "+f"(d[0]), "+f"(d[1]), "+f"(d[2]), "+f"(d[3])
        : "r"(a[0]), "r"(a[1]), "r"(a[2]), "r"(a[3]), "r"(b[0]), "r"(b[1]));
}
__device__ __forceinline__ void split_pack_h(float v0, float v1,
                                             uint32_t& h, uint32_t& l) {
    __half h0 = __float2half_rn(v0);
    __half h1 = __float2half_rn(v1);
    float r0 = v0 - __half2float(h0);
    float r1 = v1 - __half2float(h1);
    __half2 hh = __halves2half2(h0, h1);
    __half2 ll = __halves2half2(__float2half_rn(r0), __float2half_rn(r1));
    h = *(uint32_t*)&hh;
    l = *(uint32_t*)&ll;
}
__device__ __forceinline__ uint32_t pack_h(float v0, float v1) {
    __half2 hh = __halves2half2(__float2half_rn(v0), __float2half_rn(v1));
    return *(uint32_t*)&hh;
}
#define CP16(dst, src) \
    asm volatile("cp.async.cg.shared.global [%0], [%1], 16;" \
                 :: "r"(dst), "l"(src) : "memory")
#define CP_COMMIT() asm volatile("cp.async.commit_group;" ::: "memory")
#define CP_WAIT0()  asm volatile("cp.async.wait_group 0;" ::: "memory")
#define CP_WAIT1()  asm volatile("cp.async.wait_group 1;" ::: "memory")

// ---- scratch (device globals) ----
__device__ __half g_inh[MTOT * D_MODEL];
__device__ __half g_Qhi[MTOT * D_MODEL];
__device__ __half g_Qlo[MTOT * D_MODEL];
__device__ __half g_Khi[MTOT * D_MODEL];
__device__ __half g_Vhi[MTOT * D_MODEL];
__device__ __half g_Ohi[MTOT * D_MODEL];
__device__ __half g_wh[4][D_MODEL * D_MODEL];
__device__ u64    g_mbits[BATCH * N_SEQ * (N_SEQ / 64)];
__device__ int    g_mask_kind;

// ---------------------------------------------------------------------------
__global__ void detect_mask_kind(const unsigned char* __restrict__ m)
{
    __shared__ int s_maxb, s_nzoff;
    if (threadIdx.x == 0) { s_maxb = 0; s_nzoff = 0; }
    __syncthreads();
    int maxb = 0, nzoff = 0;
    for (int i = threadIdx.x; i < 65536; i += blockDim.x) {
        int v = m[i];
        if (v > maxb) maxb = v;
        if (v && (i & 3)) nzoff++;
    }
    atomicMax(&s_maxb, maxb);
    atomicAdd(&s_nzoff, nzoff);
    __syncthreads();
    if (threadIdx.x == 0)
        g_mask_kind = (s_maxb > 1) ? 2 : (s_nzoff ? 0 : 1);
}

// ---------------------------------------------------------------------------
// Pack mask to bits. Each warp packs 2 u64 words (128 elems, stride-32 lanes).
// ---------------------------------------------------------------------------
__global__ __launch_bounds__(256) void pack_mask(
    const void* __restrict__ m, u64* __restrict__ out)
{
    const int kind = g_mask_kind;
    const int wp   = blockIdx.x * 8 + (threadIdx.x >> 5);
    const int wi   = wp * 2;
    const int lane = threadIdx.x & 31;
    const int wpr  = N_SEQ / 64;   // 32
    const size_t base = (size_t)(wi / wpr) * N_SEQ + (size_t)(wi % wpr) * 64 + lane;
    bool v[4];
    if (kind == 1) {
        const int* p = (const int*)m;
#pragma unroll
        for (int j = 0; j < 4; j++) v[j] = p[base + 32 * j] != 0;
    } else if (kind == 0) {
        const unsigned char* p = (const unsigned char*)m;
#pragma unroll
        for (int j = 0; j < 4; j++) v[j] = p[base + 32 * j] != 0;
    } else {
        const float* p = (const float*)m;
#pragma unroll
        for (int j = 0; j < 4; j++) v[j] = p[base + 32 * j] != 0.f;
    }
    unsigned b0 = __ballot_sync(0xffffffffu, v[0]);
    unsigned b1 = __ballot_sync(0xffffffffu, v[1]);
    unsigned b2 = __ballot_sync(0xffffffffu, v[2]);
    unsigned b3 = __ballot_sync(0xffffffffu, v[3]);
    if (lane == 0) {
        out[wi + 0] = (u64)b0 | ((u64)b1 << 32);
        out[wi + 1] = (u64)b2 | ((u64)b3 << 32);
    }
}

// ---------------------------------------------------------------------------
__global__ __launch_bounds__(256) void round1_kernel(
    const float* __restrict__ x, __half* __restrict__ out, int n)
{
    int i = (blockIdx.x * 256 + threadIdx.x) * 4;
    if (i >= n) return;
    float4 v = *(const float4*)(x + i);
    *(uint2*)(out + i) = make_uint2(pack_h(v.x, v.y), pack_h(v.z, v.w));
}
__global__ __launch_bounds__(256) void round_h_kernel(
    const float* __restrict__ w0, const float* __restrict__ w1,
    const float* __restrict__ w2, const float* __restrict__ w3,
    __half* __restrict__ out, int nw)
{
    int i = (blockIdx.x * 256 + threadIdx.x) * 4;
    const float* src = (i < nw) ? w0 : (i < 2 * nw) ? w1 : (i < 3 * nw) ? w2 : w3;
    int j = i & (nw - 1);
    float4 v = *(const float4*)(src + j);
    *(uint2*)(out + i) = make_uint2(pack_h(v.x, v.y), pack_h(v.z, v.w));
}

// ---------------------------------------------------------------------------
// GEMM (NT): out = alpha*(Ahi[+Alo])*Wh^T (+bias). 1- or 2-term fp16.
// CTA 128x128, BK=32, 8 warps @ 32x64, 3-stage cp.async pipeline.
// ---------------------------------------------------------------------------
#define MBK    32
#define PITCH  80
#define TILE_B (128 * PITCH)          // 10240

template <bool TWO>
__device__ __forceinline__ void gemm_body(
    const __half* __restrict__ Ahi, const __half* __restrict__ Alo,
    const __half* __restrict__ Wh,
    const float* __restrict__ bias, float* __restrict__ Cf,
    __half* __restrict__ Chi, __half* __restrict__ Clo,
    int N, int K, float alpha, char* dsm)
{
    constexpr uint32_t SMAL = TILE_B;
    constexpr uint32_t SMW  = TWO ? 2u * TILE_B : TILE_B;
    constexpr uint32_t BUF  = TWO ? 3u * TILE_B : 2u * TILE_B;

    const uint32_t sbase = smem_u32(dsm);
    const int tid  = threadIdx.x;
    const int wid  = tid >> 5;
    const int lane = tid & 31;
    const int wm   = wid & 3;
    const int wn   = wid >> 2;
    const int m0   = blockIdx.y * 128;
    const int n0   = blockIdx.x * 128;

    const int q8  = lane >> 3;
    const int rin = lane & 7;
    const uint32_t lmoff = (uint32_t)(((q8 & 1) * 8 + rin) * PITCH + (q8 >> 1) * 16);

    const int lr0 = tid >> 2, lc0 = tid & 3;
    const int lr1 = (tid + 256) >> 2, lc1 = (tid + 256) & 3;
    const __half* gA0  = Ahi + (size_t)(m0 + lr0) * K + lc0 * 8;
    const __half* gA1  = Ahi + (size_t)(m0 + lr1) * K + lc1 * 8;
    const __half* gAl0 = TWO ? Alo + (size_t)(m0 + lr0) * K + lc0 * 8 : gA0;
    const __half* gAl1 = TWO ? Alo + (size_t)(m0 + lr1) * K + lc1 * 8 : gA1;
    const __half* gW0  = Wh + (size_t)(n0 + lr0) * K + lc0 * 8;
    const __half* gW1  = Wh + (size_t)(n0 + lr1) * K + lc1 * 8;
    const uint32_t s0 = lr0 * PITCH + lc0 * 16;
    const uint32_t s1 = lr1 * PITCH + lc1 * 16;

#define G_ISSUE(kb, bufo) do {                                                \
    const int _ko = (kb) * MBK;                                               \
    const uint32_t _d = sbase + (bufo);                                       \
    CP16(_d + s0, gA0 + _ko);  CP16(_d + s1, gA1 + _ko);                      \
    if (TWO) { CP16(_d + SMAL + s0, gAl0 + _ko);                              \
               CP16(_d + SMAL + s1, gAl1 + _ko); }                            \
    CP16(_d + SMW + s0, gW0 + _ko);   CP16(_d + SMW + s1, gW1 + _ko);         \
} while (0)

    float acc[2][8][4];
#pragma unroll
    for (int s = 0; s < 2; s++)
#pragma unroll
        for (int n = 0; n < 8; n++)
#pragma unroll
            for (int r = 0; r < 4; r++) acc[s][n][r] = 0.f;

    G_ISSUE(0, 0);
    CP_COMMIT();
    G_ISSUE(1, BUF);
    CP_COMMIT();

    const int nkb = K / MBK;
    uint32_t bufo = 0;
    uint32_t bufi = 2 * BUF;
    for (int kb = 0; kb < nkb; kb++) {
        if (kb + 1 < nkb) CP_WAIT1(); else CP_WAIT0();
        __syncthreads();
        if (kb + 2 < nkb) {
            G_ISSUE(kb + 2, bufi);
            CP_COMMIT();
            bufi = (bufi == 2 * BUF) ? 0 : bufi + BUF;
        }

        const uint32_t tb32 = sbase + bufo;
        const uint32_t aoff = tb32 + (wm * 32) * PITCH + lmoff;
        const uint32_t woff = tb32 + (wn * 64) * PITCH + lmoff;

#pragma unroll
        for (int ks = 0; ks < 2; ks++) {
            const uint32_t kso = ks * 32;
            uint32_t ahi[2][4], alo[2][4];
#pragma unroll
            for (int s = 0; s < 2; s++) {
                ldsm_x4(ahi[s], aoff + s * 16 * PITCH + kso);
                if (TWO) ldsm_x4(alo[s], aoff + SMAL + s * 16 * PITCH + kso);
            }
#pragma unroll
            for (int g = 0; g < 4; g++) {
                uint32_t rh[4];
                ldsm_x4(rh, woff + SMW + g * 16 * PITCH + kso);
                uint32_t b0[2] = {rh[0], rh[2]}, b1[2] = {rh[1], rh[3]};
#pragma unroll
                for (int s = 0; s < 2; s++) {
                    mma_f16(acc[s][2 * g], ahi[s], b0);
                    if (TWO) mma_f16(acc[s][2 * g], alo[s], b0);
                    mma_f16(acc[s][2 * g + 1], ahi[s], b1);
                    if (TWO) mma_f16(acc[s][2 * g + 1], alo[s], b1);
                }
            }
        }
        bufo = (bufo == 2 * BUF) ? 0 : bufo + BUF;
    }

#pragma unroll
    for (int s = 0; s < 2; s++) {
        const int r0 = m0 + wm * 32 + s * 16 + (lane >> 2);
#pragma unroll
        for (int n = 0; n < 8; n++) {
            const int col = n0 + wn * 64 + n * 8 + (lane & 3) * 2;
            const float b0 = bias ? bias[col] : 0.f;
            const float b1 = bias ? bias[col + 1] : 0.f;
            const float v0 = alpha * acc[s][n][0] + b0;
            const float v1 = alpha * acc[s][n][1] + b1;
            const float v2 = alpha * acc[s][n][2] + b0;
            const float v3 = alpha * acc[s][n][3] + b1;
            if (Cf) {
                *(float2*)&Cf[(size_t)r0 * N + col] = make_float2(v0, v1);
                *(float2*)&Cf[(size_t)(r0 + 8) * N + col] = make_float2(v2, v3);
            } else if (Clo) {
                uint32_t h, l;
                split_pack_h(v0, v1, h, l);
                *(uint32_t*)&Chi[(size_t)r0 * N + col] = h;
                *(uint32_t*)&Clo[(size_t)r0 * N + col] = l;
                split_pack_h(v2, v3, h, l);
                *(uint32_t*)&Chi[(size_t)(r0 + 8) * N + col] = h;
                *(uint32_t*)&Clo[(size_t)(r0 + 8) * N + col] = l;
            } else {
                *(uint32_t*)&Chi[(size_t)r0 * N + col] = pack_h(v0, v1);
                *(uint32_t*)&Chi[(size_t)(r0 + 8) * N + col] = pack_h(v2, v3);
            }
        }
    }
#undef G_ISSUE
}

// QKV projection, 1-term (x rounded to fp16). Q gets hi/lo split output.
__global__ __launch_bounds__(256, 2) void gemm_qkv(
    const __half* __restrict__ inh, const __half* __restrict__ wh,
    __half* __restrict__ Qhi, __half* __restrict__ Qlo,
    __half* __restrict__ Khi, __half* __restrict__ Vhi)
{
    extern __shared__ char dsm[];
    const int z = blockIdx.z;
    const int nw = D_MODEL * D_MODEL;
    const __half* Wh = wh + (size_t)z * nw;
    __half* Chi = (z == 0) ? Qhi : (z == 1) ? Khi : Vhi;
    __half* Clo = (z == 0) ? Qlo : nullptr;
    const float alpha = (z == 0) ? QSCALE : 1.0f;
    gemm_body<false>(inh, nullptr, Wh, nullptr, nullptr, Chi, Clo,
                     D_MODEL, D_MODEL, alpha, dsm);
}

// Output projection, 1-term (O fp16), fp32 + bias.
__global__ __launch_bounds__(256, 2) void gemm_out(
    const __half* __restrict__ Ahi, const __half* __restrict__ Wh,
    const float* __restrict__ bias, float* __restrict__ Cf)
{
    extern __shared__ char dsm[];
    gemm_body<false>(Ahi, nullptr, Wh, bias, Cf, nullptr, nullptr,
                     D_MODEL, D_MODEL, 1.0f, dsm);
}

// ---------------------------------------------------------------------------
// Tensor-core flash attention, k-tile 64, q-tile 128, 3-stage pipeline.
// QK^T: 2-term ((Qhi+Qlo)*Khi). PV: 1-term (P fp16, V hi). Bitmask.
// Output: fp16 (Ohi only).
// ---------------------------------------------------------------------------
#define APB    144
#define KTROWS 64
#define KREG   (KTROWS * APB)         // 9216
#define S_KHI  0
#define S_VHI  (1 * KREG)
#define ABUF   (2 * KREG)             // 18432 per stage
#define NKT    (N_SEQ / KTROWS)       // 32

__global__ __launch_bounds__(256, 2) void attn_mma(
    const __half* __restrict__ Qhi, const __half* __restrict__ Qlo,
    const __half* __restrict__ Khi, const __half* __restrict__ Vhi,
    const u64* __restrict__ mbits,
    __half* __restrict__ Ohi)
{
    extern __shared__ char smemb[];
    const uint32_t sb = smem_u32(smemb);

    const int tid  = threadIdx.x;
    const int warp = tid >> 5;
    const int lane = tid & 31;
    const int gq   = lane >> 2;
    const int tig  = lane & 3;
    const int q8   = lane >> 3;
    const int rin  = lane & 7;
    const uint32_t lmoff = (uint32_t)(((q8 & 1) * 8 + rin) * APB + (q8 >> 1) * 16);
    const int wrow = warp * 16;

    const int bh = blockIdx.y;
    const int b  = bh >> 4;
    const int h  = bh & 15;
    const int q0 = blockIdx.x * 128;
    const size_t rowbase = (size_t)b * N_SEQ;
    const int hoff = h * DHEAD;

    // ---- stage Q (128 rows): Qhi in stage0/1 S_KHI, Qlo in stage0/1 S_VHI ----
#pragma unroll
    for (int i = 0; i < 4; i++) {
        const int c = tid + 256 * i;
        const int row = c >> 3, colc = c & 7;
        const size_t src = (rowbase + q0 + row) * D_MODEL + hoff + colc * 8;
        const uint32_t off = (row >= 64 ? ABUF : 0) + (row & 63) * APB + colc * 16;
        *(uint4*)(smemb + S_KHI + off) = *(const uint4*)(Qhi + src);
        *(uint4*)(smemb + S_VHI + off) = *(const uint4*)(Qlo + src);
    }
    __syncthreads();
    uint32_t aQh[4][4], aQl[4][4];
    {
        const uint32_t qb = sb + (wrow >= 64 ? ABUF : 0) + (wrow & 63) * APB + lmoff;
#pragma unroll
        for (int ks = 0; ks < 4; ks++) {
            ldsm_x4(aQh[ks], qb + S_KHI + ks * 32);
            ldsm_x4(aQl[ks], qb + S_VHI + ks * 32);
        }
    }
    __syncthreads();

    float oacc[8][4];
#pragma unroll
    for (int n = 0; n < 8; n++)
#pragma unroll
        for (int r = 0; r < 4; r++) oacc[n][r] = 0.f;
    float mrow0 = NEGINF, mrow1 = NEGINF, lrow0 = 0.f, lrow1 = 0.f;

#define ISSUE_TILES(kt, bo) do {                                              \
    _Pragma("unroll")                                                         \
    for (int i = 0; i < 2; i++) {                                             \
        const int c = tid + 256 * i;                                          \
        const int row = c >> 3, colc = c & 7;                                 \
        const size_t src = (rowbase + (kt) * KTROWS + row) * D_MODEL + hoff + colc * 8; \
        const uint32_t dst = sb + (bo) + row * APB + colc * 16;               \
        CP16(dst + S_KHI, Khi + src);                                         \
        CP16(dst + S_VHI, Vhi + src);                                         \
    }                                                                         \
} while (0)

    ISSUE_TILES(0, 0);
    CP_COMMIT();
    ISSUE_TILES(1, ABUF);
    CP_COMMIT();

    const u64* mb0 = mbits + (size_t)(b * N_SEQ + q0 + wrow + gq) * (N_SEQ / 64);
    const u64* mb1 = mb0 + 8 * (N_SEQ / 64);

    uint32_t bo = 0;
    uint32_t bi = 2 * ABUF;
    for (int kt = 0; kt < NKT; kt++) {
        if (kt + 1 < NKT) CP_WAIT1(); else CP_WAIT0();
        __syncthreads();
        if (kt + 2 < NKT) {
            ISSUE_TILES(kt + 2, bi);
            CP_COMMIT();
            bi = (bi == 2 * ABUF) ? 0 : bi + ABUF;
        }

        // ---- S = (Qhi+Qlo) Khi^T (2-term fp16) ----
        float sc[8][4];
#pragma unroll
        for (int n = 0; n < 8; n++)
#pragma unroll
            for (int r = 0; r < 4; r++) sc[n][r] = 0.f;

#pragma unroll
        for (int ks = 0; ks < 4; ks++) {
#pragma unroll
            for (int g2 = 0; g2 < 4; g2++) {
                uint32_t rh[4];
                const uint32_t ka = sb + bo + g2 * 16 * APB + lmoff + ks * 32;
                ldsm_x4(rh, ka + S_KHI);
                uint32_t b0h[2] = {rh[0], rh[2]}, b1h[2] = {rh[1], rh[3]};
                mma_f16(sc[2 * g2], aQh[ks], b0h);
                mma_f16(sc[2 * g2], aQl[ks], b0h);
                mma_f16(sc[2 * g2 + 1], aQh[ks], b1h);
                mma_f16(sc[2 * g2 + 1], aQl[ks], b1h);
            }
        }

        // ---- mask from packed bits ----
        {
            const u64 w0 = mb0[kt];
            const u64 w1 = mb1[kt];
#pragma unroll
            for (int n = 0; n < 8; n++) {
                const unsigned s0 = (unsigned)(w0 >> (8 * n + 2 * tig));
                const unsigned s1 = (unsigned)(w1 >> (8 * n + 2 * tig));
                if (s0 & 1) sc[n][0] = NEGINF;
                if (s0 & 2) sc[n][1] = NEGINF;
                if (s1 & 1) sc[n][2] = NEGINF;
                if (s1 & 2) sc[n][3] = NEGINF;
            }
        }

        // ---- online softmax ----
        float mx0 = NEGINF, mx1 = NEGINF;
#pragma unroll
        for (int n = 0; n < 8; n++) {
            mx0 = fmaxf(mx0, fmaxf(sc[n][0], sc[n][1]));
            mx1 = fmaxf(mx1, fmaxf(sc[n][2], sc[n][3]));
        }
        mx0 = fmaxf(mx0, __shfl_xor_sync(0xffffffffu, mx0, 1));
        mx0 = fmaxf(mx0, __shfl_xor_sync(0xffffffffu, mx0, 2));
        mx1 = fmaxf(mx1, __shfl_xor_sync(0xffffffffu, mx1, 1));
        mx1 = fmaxf(mx1, __shfl_xor_sync(0xffffffffu, mx1, 2));

        const float mn0 = fmaxf(mrow0, mx0);
        const float mn1 = fmaxf(mrow1, mx1);
        const float f0 = __expf(mrow0 - mn0);
        const float f1 = __expf(mrow1 - mn1);

        float sum0 = 0.f, sum1 = 0.f;
#pragma unroll
        for (int n = 0; n < 8; n++) {
            sc[n][0] = __expf(sc[n][0] - mn0); sum0 += sc[n][0];
            sc[n][1] = __expf(sc[n][1] - mn0); sum0 += sc[n][1];
            sc[n][2] = __expf(sc[n][2] - mn1); sum1 += sc[n][2];
            sc[n][3] = __expf(sc[n][3] - mn1); sum1 += sc[n][3];
        }
        sum0 += __shfl_xor_sync(0xffffffffu, sum0, 1);
        sum0 += __shfl_xor_sync(0xffffffffu, sum0, 2);
        sum1 += __shfl_xor_sync(0xffffffffu, sum1, 1);
        sum1 += __shfl_xor_sync(0xffffffffu, sum1, 2);

        lrow0 = lrow0 * f0 + sum0; mrow0 = mn0;
        lrow1 = lrow1 * f1 + sum1; mrow1 = mn1;
#pragma unroll
        for (int n = 0; n < 8; n++) {
            oacc[n][0] *= f0; oacc[n][1] *= f0;
            oacc[n][2] *= f1; oacc[n][3] *= f1;
        }

        // ---- O += P V (1-term: P fp16, V hi) ----
#pragma unroll
        for (int kk = 0; kk < 4; kk++) {
            uint32_t aP[4];
            aP[0] = pack_h(sc[2 * kk][0], sc[2 * kk][1]);
            aP[1] = pack_h(sc[2 * kk][2], sc[2 * kk][3]);
            aP[2] = pack_h(sc[2 * kk + 1][0], sc[2 * kk + 1][1]);
            aP[3] = pack_h(sc[2 * kk + 1][2], sc[2 * kk + 1][3]);
#pragma unroll
            for (int g2 = 0; g2 < 4; g2++) {
                uint32_t rh[4];
                const uint32_t va = sb + bo + kk * 16 * APB + lmoff + g2 * 32;
                ldsm_x4_t(rh, va + S_VHI);
                uint32_t b0[2] = {rh[0], rh[1]}, b1[2] = {rh[2], rh[3]};
                mma_f16(oacc[2 * g2], aP, b0);
                mma_f16(oacc[2 * g2 + 1], aP, b1);
            }
        }
        bo = (bo == 2 * ABUF) ? 0 : bo + ABUF;
    }

    // ---- normalize + write fp16 ----
    const float inv0 = 1.f / lrow0;
    const float inv1 = 1.f / lrow1;
    const size_t orow0 = (rowbase + q0 + wrow + gq) * D_MODEL + hoff;
    const size_t orow1 = orow0 + 8 * D_MODEL;
#pragma unroll
    for (int n = 0; n < 8; n++) {
        const int col = 8 * n + 2 * tig;
        *(uint32_t*)&Ohi[orow0 + col] = pack_h(oacc[n][0] * inv0, oacc[n][1] * inv0);
        *(uint32_t*)&Ohi[orow1 + col] = pack_h(oacc[n][2] * inv1, oacc[n][3] * inv1);
    }
}

// ---------------------------------------------------------------------------
extern "C" void kernel_launch(void* const* d_in, const int* in_sizes, int n_in,
                              void* d_out, int out_size)
{
    const float* q  = (const float*)d_in[0];
    const void*  mk = d_in[1];
    const float* Wq = (const float*)d_in[2];
    const float* Wk = (const float*)d_in[3];
    const float* Wv = (const float*)d_in[4];
    const float* Wo = (const float*)d_in[5];
    const float* bo = (const float*)d_in[6];
    float* out      = (float*)d_out;

    __half *inh, *Qhi, *Qlo, *Khi, *Vhi, *Ohi, *wh;
    u64* mbits;
    cudaGetSymbolAddress((void**)&inh, g_inh);
    cudaGetSymbolAddress((void**)&Qhi, g_Qhi);
    cudaGetSymbolAddress((void**)&Qlo, g_Qlo);
    cudaGetSymbolAddress((void**)&Khi, g_Khi);
    cudaGetSymbolAddress((void**)&Vhi, g_Vhi);
    cudaGetSymbolAddress((void**)&Ohi, g_Ohi);
    cudaGetSymbolAddress((void**)&wh, g_wh);
    cudaGetSymbolAddress((void**)&mbits, g_mbits);

    detect_mask_kind<<<1, 256>>>((const unsigned char*)mk);

    const int nq = MTOT * D_MODEL;
    const int nw = D_MODEL * D_MODEL;
    round1_kernel<<<nq / 1024, 256>>>(q, inh, nq);
    round_h_kernel<<<4 * nw / 1024, 256>>>(Wq, Wk, Wv, Wo, wh, nw);
    pack_mask<<<(BATCH * N_SEQ * (N_SEQ / 64)) / 16, 256>>>(mk, mbits);

    const int qkv_smem = 3 * 2 * TILE_B;   // 61440
    cudaFuncSetAttribute(gemm_qkv, cudaFuncAttributeMaxDynamicSharedMemorySize,
                         qkv_smem);
    cudaFuncSetAttribute(gemm_out, cudaFuncAttributeMaxDynamicSharedMemorySize,
                         qkv_smem);

    gemm_qkv<<<dim3(D_MODEL / 128, MTOT / 128, 3), 256, qkv_smem>>>(
        inh, wh, Qhi, Qlo, Khi, Vhi);

    const int attn_smem = 3 * ABUF;   // 55296
    cudaFuncSetAttribute(attn_mma, cudaFuncAttributeMaxDynamicSharedMemorySize,
                         attn_smem);
    attn_mma<<<dim3(N_SEQ / 128, BATCH * NHEADS), 256, attn_smem>>>(
        Qhi, Qlo, Khi, Vhi, mbits, Ohi);

    gemm_out<<<dim3(D_MODEL / 128, MTOT / 128), 256, qkv_smem>>>(
        Ohi, wh + 3 * (size_t)nw, bo, out);
}

// round 16
// speedup vs baseline: 5.8447x; 1.0549x over previous
#include <cuda_runtime.h>
#include <cuda_fp16.h>
#include <math.h>
#include <stdint.h>

#define D_MODEL 1024
#define N_SEQ   2048
#define BATCH   2
#define NHEADS  16
#define DHEAD   64
#define QSCALE  0.125f
#define MTOT    (BATCH * N_SEQ)   // 4096
#define NQ      (MTOT * D_MODEL)  // 4M
#define NW      (D_MODEL * D_MODEL) // 1M
#define NEGINF  -1.0e30f
typedef unsigned long long u64;

// ---- mma.sync helpers ----
__device__ __forceinline__ uint32_t smem_u32(const void* p) {
    uint32_t a;
    asm("{ .reg .u64 t; cvta.to.shared.u64 t, %1; cvt.u32.u64 %0, t; }"
        : "=r"(a) : "l"(p));
    return a;
}
__device__ __forceinline__ void ldsm_x4(uint32_t* r, uint32_t addr) {
    asm volatile("ldmatrix.sync.aligned.m8n8.x4.shared.b16 {%0,%1,%2,%3}, [%4];"
        : "=r"(r[0]), "=r"(r[1]), "=r"(r[2]), "=r"(r[3]) : "r"(addr));
}
__device__ __forceinline__ void ldsm_x4_t(uint32_t* r, uint32_t addr) {
    asm volatile("ldmatrix.sync.aligned.m8n8.x4.trans.shared.b16 {%0,%1,%2,%3}, [%4];"
        : "=r"(r[0]), "=r"(r[1]), "=r"(r[2]), "=r"(r[3]) : "r"(addr));
}
__device__ __forceinline__ void mma_f16(float* d, const uint32_t* a,
                                        const uint32_t* b) {
    asm volatile(
        "mma.sync.aligned.m16n8k16.row.col.f32.f16.f16.f32 "
        "{%0,%1,%2,%3}, {%4,%5,%6,%7}, {%8,%9}, {%0,%1,%2,%3};"
        : "+f"(d[0]), "+f"(d[1]), "+f"(d[2]), "+f"(d[3])
        : "r"(a[0]), "r"(a[1]), "r"(a[2]), "r"(a[3]), "r"(b[0]), "r"(b[1]));
}
__device__ __forceinline__ void split_pack_h(float v0, float v1,
                                             uint32_t& h, uint32_t& l) {
    __half h0 = __float2half_rn(v0);
    __half h1 = __float2half_rn(v1);
    float r0 = v0 - __half2float(h0);
    float r1 = v1 - __half2float(h1);
    __half2 hh = __halves2half2(h0, h1);
    __half2 ll = __halves2half2(__float2half_rn(r0), __float2half_rn(r1));
    h = *(uint32_t*)&hh;
    l = *(uint32_t*)&ll;
}
__device__ __forceinline__ uint32_t pack_h(float v0, float v1) {
    __half2 hh = __halves2half2(__float2half_rn(v0), __float2half_rn(v1));
    return *(uint32_t*)&hh;
}
#define CP16(dst, src) \
    asm volatile("cp.async.cg.shared.global [%0], [%1], 16;" \
                 :: "r"(dst), "l"(src) : "memory")
#define CP_COMMIT() asm volatile("cp.async.commit_group;" ::: "memory")
#define CP_WAIT0()  asm volatile("cp.async.wait_group 0;" ::: "memory")
#define CP_WAIT1()  asm volatile("cp.async.wait_group 1;" ::: "memory")
#define CP_WAIT2()  asm volatile("cp.async.wait_group 2;" ::: "memory")

// ---- scratch (device globals) ----
__device__ __half g_inh[NQ];
__device__ __half g_Qhi[NQ];
__device__ __half g_Qlo[NQ];
__device__ __half g_Khi[NQ];
__device__ __half g_Vhi[NQ];
__device__ __half g_Ohi[NQ];
__device__ __half g_wh[4][NW];
__device__ u64    g_mbits[BATCH * N_SEQ * (N_SEQ / 64)];
__device__ int    g_mask_kind;

// ---------------------------------------------------------------------------
// Mask dtype detection: uint4 scan of first 64KB, word-level bit tests.
//   float32: some byte >= 2  ->  (w & 0xFEFEFEFE) != 0
//   uint8  : nonzero byte at offset%4 != 0  ->  (w & 0xFFFFFF00) != 0
//   else int32.
// ---------------------------------------------------------------------------
__global__ void detect_mask_kind(const uint4* __restrict__ m)
{
    __shared__ int s_flags;
    if (threadIdx.x == 0) s_flags = 0;
    __syncthreads();
    int fl = 0;
#pragma unroll
    for (int it = 0; it < 4; it++) {
        uint4 v = m[threadIdx.x + 256 * it];   // 4096 uint4 = 64KB
        uint32_t w[4] = {v.x, v.y, v.z, v.w};
#pragma unroll
        for (int j = 0; j < 4; j++) {
            if (w[j] & 0xFEFEFEFEu) fl |= 1;   // float evidence
            if (w[j] & 0xFFFFFF00u) fl |= 2;   // packed-byte evidence
        }
    }
    if (fl) atomicOr(&s_flags, fl);
    __syncthreads();
    if (threadIdx.x == 0) {
        int f = s_flags;
        g_mask_kind = (f & 1) ? 2 : ((f & 2) ? 0 : 1);
    }
}

// ---------------------------------------------------------------------------
// Pack mask to bits. Each warp packs 2 u64 words (128 elems, stride-32 lanes).
// ---------------------------------------------------------------------------
__global__ __launch_bounds__(256) void pack_mask(
    const void* __restrict__ m, u64* __restrict__ out)
{
    const int kind = g_mask_kind;
    const int wp   = blockIdx.x * 8 + (threadIdx.x >> 5);
    const int wi   = wp * 2;
    const int lane = threadIdx.x & 31;
    const int wpr  = N_SEQ / 64;   // 32
    const size_t base = (size_t)(wi / wpr) * N_SEQ + (size_t)(wi % wpr) * 64 + lane;
    bool v[4];
    if (kind == 1) {
        const int* p = (const int*)m;
#pragma unroll
        for (int j = 0; j < 4; j++) v[j] = p[base + 32 * j] != 0;
    } else if (kind == 0) {
        const unsigned char* p = (const unsigned char*)m;
#pragma unroll
        for (int j = 0; j < 4; j++) v[j] = p[base + 32 * j] != 0;
    } else {
        const float* p = (const float*)m;
#pragma unroll
        for (int j = 0; j < 4; j++) v[j] = p[base + 32 * j] != 0.f;
    }
    unsigned b0 = __ballot_sync(0xffffffffu, v[0]);
    unsigned b1 = __ballot_sync(0xffffffffu, v[1]);
    unsigned b2 = __ballot_sync(0xffffffffu, v[2]);
    unsigned b3 = __ballot_sync(0xffffffffu, v[3]);
    if (lane == 0) {
        out[wi + 0] = (u64)b0 | ((u64)b1 << 32);
        out[wi + 1] = (u64)b2 | ((u64)b3 << 32);
    }
}

// ---------------------------------------------------------------------------
// Fused fp32->fp16 rounding: input x (NQ elems) -> inh, 4 weights -> wh.
// Total NQ + 4*NW = 8M elements, 4 per thread.
// ---------------------------------------------------------------------------
__global__ __launch_bounds__(256) void round_all(
    const float* __restrict__ q,
    const float* __restrict__ w0, const float* __restrict__ w1,
    const float* __restrict__ w2, const float* __restrict__ w3,
    __half* __restrict__ inh, __half* __restrict__ wh)
{
    int i = (blockIdx.x * 256 + threadIdx.x) * 4;
    const float* src;
    __half* dst;
    if (i < NQ) {
        src = q + i;
        dst = inh + i;
    } else {
        const int j = i - NQ;
        const int sel = j >> 20;            // NW = 1<<20
        src = ((sel == 0) ? w0 : (sel == 1) ? w1 : (sel == 2) ? w2 : w3)
              + (j & (NW - 1));
        dst = wh + j;
    }
    float4 v = *(const float4*)src;
    *(uint2*)dst = make_uint2(pack_h(v.x, v.y), pack_h(v.z, v.w));
}

// ---------------------------------------------------------------------------
// GEMM (NT): out = alpha*(Ahi[+Alo])*Wh^T (+bias). 1- or 2-term fp16.
// CTA 128x128, BK=32, 8 warps @ 32x64, 4-stage cp.async pipeline.
// ---------------------------------------------------------------------------
#define MBK    32
#define PITCH  80
#define TILE_B (128 * PITCH)          // 10240

template <bool TWO>
__device__ __forceinline__ void gemm_body(
    const __half* __restrict__ Ahi, const __half* __restrict__ Alo,
    const __half* __restrict__ Wh,
    const float* __restrict__ bias, float* __restrict__ Cf,
    __half* __restrict__ Chi, __half* __restrict__ Clo,
    int N, int K, float alpha, char* dsm)
{
    constexpr uint32_t SMAL = TILE_B;
    constexpr uint32_t SMW  = TWO ? 2u * TILE_B : TILE_B;
    constexpr uint32_t BUF  = TWO ? 3u * TILE_B : 2u * TILE_B;

    const uint32_t sbase = smem_u32(dsm);
    const int tid  = threadIdx.x;
    const int wid  = tid >> 5;
    const int lane = tid & 31;
    const int wm   = wid & 3;
    const int wn   = wid >> 2;
    const int m0   = blockIdx.y * 128;
    const int n0   = blockIdx.x * 128;

    const int q8  = lane >> 3;
    const int rin = lane & 7;
    const uint32_t lmoff = (uint32_t)(((q8 & 1) * 8 + rin) * PITCH + (q8 >> 1) * 16);

    const int lr0 = tid >> 2, lc0 = tid & 3;
    const int lr1 = (tid + 256) >> 2, lc1 = (tid + 256) & 3;
    const __half* gA0  = Ahi + (size_t)(m0 + lr0) * K + lc0 * 8;
    const __half* gA1  = Ahi + (size_t)(m0 + lr1) * K + lc1 * 8;
    const __half* gAl0 = TWO ? Alo + (size_t)(m0 + lr0) * K + lc0 * 8 : gA0;
    const __half* gAl1 = TWO ? Alo + (size_t)(m0 + lr1) * K + lc1 * 8 : gA1;
    const __half* gW0  = Wh + (size_t)(n0 + lr0) * K + lc0 * 8;
    const __half* gW1  = Wh + (size_t)(n0 + lr1) * K + lc1 * 8;
    const uint32_t s0 = lr0 * PITCH + lc0 * 16;
    const uint32_t s1 = lr1 * PITCH + lc1 * 16;

#define G_ISSUE(kb) do {                                                      \
    const int _ko = (kb) * MBK;                                               \
    const uint32_t _d = sbase + ((kb) & 3) * BUF;                             \
    CP16(_d + s0, gA0 + _ko);  CP16(_d + s1, gA1 + _ko);                      \
    if (TWO) { CP16(_d + SMAL + s0, gAl0 + _ko);                              \
               CP16(_d + SMAL + s1, gAl1 + _ko); }                            \
    CP16(_d + SMW + s0, gW0 + _ko);   CP16(_d + SMW + s1, gW1 + _ko);         \
} while (0)

    float acc[2][8][4];
#pragma unroll
    for (int s = 0; s < 2; s++)
#pragma unroll
        for (int n = 0; n < 8; n++)
#pragma unroll
            for (int r = 0; r < 4; r++) acc[s][n][r] = 0.f;

    G_ISSUE(0); CP_COMMIT();
    G_ISSUE(1); CP_COMMIT();
    G_ISSUE(2); CP_COMMIT();

    const int nkb = K / MBK;
    for (int kb = 0; kb < nkb; kb++) {
        if (kb + 2 < nkb)      CP_WAIT2();
        else if (kb + 1 < nkb) CP_WAIT1();
        else                   CP_WAIT0();
        __syncthreads();
        if (kb + 3 < nkb) { G_ISSUE(kb + 3); CP_COMMIT(); }

        const uint32_t tb32 = sbase + (kb & 3) * BUF;
        const uint32_t aoff = tb32 + (wm * 32) * PITCH + lmoff;
        const uint32_t woff = tb32 + (wn * 64) * PITCH + lmoff;

#pragma unroll
        for (int ks = 0; ks < 2; ks++) {
            const uint32_t kso = ks * 32;
            uint32_t ahi[2][4], alo[2][4];
#pragma unroll
            for (int s = 0; s < 2; s++) {
                ldsm_x4(ahi[s], aoff + s * 16 * PITCH + kso);
                if (TWO) ldsm_x4(alo[s], aoff + SMAL + s * 16 * PITCH + kso);
            }
#pragma unroll
            for (int g = 0; g < 4; g++) {
                uint32_t rh[4];
                ldsm_x4(rh, woff + SMW + g * 16 * PITCH + kso);
                uint32_t b0[2] = {rh[0], rh[2]}, b1[2] = {rh[1], rh[3]};
#pragma unroll
                for (int s = 0; s < 2; s++) {
                    mma_f16(acc[s][2 * g], ahi[s], b0);
                    if (TWO) mma_f16(acc[s][2 * g], alo[s], b0);
                    mma_f16(acc[s][2 * g + 1], ahi[s], b1);
                    if (TWO) mma_f16(acc[s][2 * g + 1], alo[s], b1);
                }
            }
        }
    }

#pragma unroll
    for (int s = 0; s < 2; s++) {
        const int r0 = m0 + wm * 32 + s * 16 + (lane >> 2);
#pragma unroll
        for (int n = 0; n < 8; n++) {
            const int col = n0 + wn * 64 + n * 8 + (lane & 3) * 2;
            const float b0 = bias ? bias[col] : 0.f;
            const float b1 = bias ? bias[col + 1] : 0.f;
            const float v0 = alpha * acc[s][n][0] + b0;
            const float v1 = alpha * acc[s][n][1] + b1;
            const float v2 = alpha * acc[s][n][2] + b0;
            const float v3 = alpha * acc[s][n][3] + b1;
            if (Cf) {
                *(float2*)&Cf[(size_t)r0 * N + col] = make_float2(v0, v1);
                *(float2*)&Cf[(size_t)(r0 + 8) * N + col] = make_float2(v2, v3);
            } else if (Clo) {
                uint32_t h, l;
                split_pack_h(v0, v1, h, l);
                *(uint32_t*)&Chi[(size_t)r0 * N + col] = h;
                *(uint32_t*)&Clo[(size_t)r0 * N + col] = l;
                split_pack_h(v2, v3, h, l);
                *(uint32_t*)&Chi[(size_t)(r0 + 8) * N + col] = h;
                *(uint32_t*)&Clo[(size_t)(r0 + 8) * N + col] = l;
            } else {
                *(uint32_t*)&Chi[(size_t)r0 * N + col] = pack_h(v0, v1);
                *(uint32_t*)&Chi[(size_t)(r0 + 8) * N + col] = pack_h(v2, v3);
            }
        }
    }
#undef G_ISSUE
}

// QKV projection, 1-term (x rounded to fp16). Q gets hi/lo split output.
__global__ __launch_bounds__(256, 2) void gemm_qkv(
    const __half* __restrict__ inh, const __half* __restrict__ wh,
    __half* __restrict__ Qhi, __half* __restrict__ Qlo,
    __half* __restrict__ Khi, __half* __restrict__ Vhi)
{
    extern __shared__ char dsm[];
    const int z = blockIdx.z;
    const __half* Wh = wh + (size_t)z * NW;
    __half* Chi = (z == 0) ? Qhi : (z == 1) ? Khi : Vhi;
    __half* Clo = (z == 0) ? Qlo : nullptr;
    const float alpha = (z == 0) ? QSCALE : 1.0f;
    gemm_body<false>(inh, nullptr, Wh, nullptr, nullptr, Chi, Clo,
                     D_MODEL, D_MODEL, alpha, dsm);
}

// Output projection, 1-term (O fp16), fp32 + bias.
__global__ __launch_bounds__(256, 2) void gemm_out(
    const __half* __restrict__ Ahi, const __half* __restrict__ Wh,
    const float* __restrict__ bias, float* __restrict__ Cf)
{
    extern __shared__ char dsm[];
    gemm_body<false>(Ahi, nullptr, Wh, bias, Cf, nullptr, nullptr,
                     D_MODEL, D_MODEL, 1.0f, dsm);
}

// ---------------------------------------------------------------------------
// Tensor-core flash attention, k-tile 64, q-tile 128, 4-stage pipeline.
// QK^T: 2-term ((Qhi+Qlo)*Khi). PV: 1-term (P fp16, V hi). Bitmask.
// Output: fp16 (Ohi only).
// ---------------------------------------------------------------------------
#define APB    144
#define KTROWS 64
#define KREG   (KTROWS * APB)         // 9216
#define S_KHI  0
#define S_VHI  (1 * KREG)
#define ABUF   (2 * KREG)             // 18432 per stage
#define NKT    (N_SEQ / KTROWS)       // 32

__global__ __launch_bounds__(256, 2) void attn_mma(
    const __half* __restrict__ Qhi, const __half* __restrict__ Qlo,
    const __half* __restrict__ Khi, const __half* __restrict__ Vhi,
    const u64* __restrict__ mbits,
    __half* __restrict__ Ohi)
{
    extern __shared__ char smemb[];
    const uint32_t sb = smem_u32(smemb);

    const int tid  = threadIdx.x;
    const int warp = tid >> 5;
    const int lane = tid & 31;
    const int gq   = lane >> 2;
    const int tig  = lane & 3;
    const int q8   = lane >> 3;
    const int rin  = lane & 7;
    const uint32_t lmoff = (uint32_t)(((q8 & 1) * 8 + rin) * APB + (q8 >> 1) * 16);
    const int wrow = warp * 16;

    const int bh = blockIdx.y;
    const int b  = bh >> 4;
    const int h  = bh & 15;
    const int q0 = blockIdx.x * 128;
    const size_t rowbase = (size_t)b * N_SEQ;
    const int hoff = h * DHEAD;

    // ---- stage Q (128 rows): Qhi/Qlo across stage0/1 areas; read to regs ----
#pragma unroll
    for (int i = 0; i < 4; i++) {
        const int c = tid + 256 * i;
        const int row = c >> 3, colc = c & 7;
        const size_t src = (rowbase + q0 + row) * D_MODEL + hoff + colc * 8;
        const uint32_t off = (row >= 64 ? ABUF : 0) + (row & 63) * APB + colc * 16;
        *(uint4*)(smemb + S_KHI + off) = *(const uint4*)(Qhi + src);
        *(uint4*)(smemb + S_VHI + off) = *(const uint4*)(Qlo + src);
    }
    __syncthreads();
    uint32_t aQh[4][4], aQl[4][4];
    {
        const uint32_t qb = sb + (wrow >= 64 ? ABUF : 0) + (wrow & 63) * APB + lmoff;
#pragma unroll
        for (int ks = 0; ks < 4; ks++) {
            ldsm_x4(aQh[ks], qb + S_KHI + ks * 32);
            ldsm_x4(aQl[ks], qb + S_VHI + ks * 32);
        }
    }
    __syncthreads();

    float oacc[8][4];
#pragma unroll
    for (int n = 0; n < 8; n++)
#pragma unroll
        for (int r = 0; r < 4; r++) oacc[n][r] = 0.f;
    float mrow0 = NEGINF, mrow1 = NEGINF, lrow0 = 0.f, lrow1 = 0.f;

#define ISSUE_TILES(kt) do {                                                  \
    _Pragma("unroll")                                                         \
    for (int i = 0; i < 2; i++) {                                             \
        const int c = tid + 256 * i;                                          \
        const int row = c >> 3, colc = c & 7;                                 \
        const size_t src = (rowbase + (kt) * KTROWS + row) * D_MODEL + hoff + colc * 8; \
        const uint32_t dst = sb + ((kt) & 3) * ABUF + row * APB + colc * 16;  \
        CP16(dst + S_KHI, Khi + src);                                         \
        CP16(dst + S_VHI, Vhi + src);                                         \
    }                                                                         \
} while (0)

    ISSUE_TILES(0); CP_COMMIT();
    ISSUE_TILES(1); CP_COMMIT();
    ISSUE_TILES(2); CP_COMMIT();

    const u64* mb0 = mbits + (size_t)(b * N_SEQ + q0 + wrow + gq) * (N_SEQ / 64);
    const u64* mb1 = mb0 + 8 * (N_SEQ / 64);

    for (int kt = 0; kt < NKT; kt++) {
        if (kt + 2 < NKT)      CP_WAIT2();
        else if (kt + 1 < NKT) CP_WAIT1();
        else                   CP_WAIT0();
        __syncthreads();
        if (kt + 3 < NKT) { ISSUE_TILES(kt + 3); CP_COMMIT(); }

        const uint32_t bo = (kt & 3) * ABUF;

        // ---- S = (Qhi+Qlo) Khi^T (2-term fp16) ----
        float sc[8][4];
#pragma unroll
        for (int n = 0; n < 8; n++)
#pragma unroll
            for (int r = 0; r < 4; r++) sc[n][r] = 0.f;

#pragma unroll
        for (int ks = 0; ks < 4; ks++) {
#pragma unroll
            for (int g2 = 0; g2 < 4; g2++) {
                uint32_t rh[4];
                const uint32_t ka = sb + bo + g2 * 16 * APB + lmoff + ks * 32;
                ldsm_x4(rh, ka + S_KHI);
                uint32_t b0h[2] = {rh[0], rh[2]}, b1h[2] = {rh[1], rh[3]};
                mma_f16(sc[2 * g2], aQh[ks], b0h);
                mma_f16(sc[2 * g2], aQl[ks], b0h);
                mma_f16(sc[2 * g2 + 1], aQh[ks], b1h);
                mma_f16(sc[2 * g2 + 1], aQl[ks], b1h);
            }
        }

        // ---- mask from packed bits ----
        {
            const u64 w0 = mb0[kt];
            const u64 w1 = mb1[kt];
#pragma unroll
            for (int n = 0; n < 8; n++) {
                const unsigned s0 = (unsigned)(w0 >> (8 * n + 2 * tig));
                const unsigned s1 = (unsigned)(w1 >> (8 * n + 2 * tig));
                if (s0 & 1) sc[n][0] = NEGINF;
                if (s0 & 2) sc[n][1] = NEGINF;
                if (s1 & 1) sc[n][2] = NEGINF;
                if (s1 & 2) sc[n][3] = NEGINF;
            }
        }

        // ---- online softmax ----
        float mx0 = NEGINF, mx1 = NEGINF;
#pragma unroll
        for (int n = 0; n < 8; n++) {
            mx0 = fmaxf(mx0, fmaxf(sc[n][0], sc[n][1]));
            mx1 = fmaxf(mx1, fmaxf(sc[n][2], sc[n][3]));
        }
        mx0 = fmaxf(mx0, __shfl_xor_sync(0xffffffffu, mx0, 1));
        mx0 = fmaxf(mx0, __shfl_xor_sync(0xffffffffu, mx0, 2));
        mx1 = fmaxf(mx1, __shfl_xor_sync(0xffffffffu, mx1, 1));
        mx1 = fmaxf(mx1, __shfl_xor_sync(0xffffffffu, mx1, 2));

        const float mn0 = fmaxf(mrow0, mx0);
        const float mn1 = fmaxf(mrow1, mx1);
        const float f0 = __expf(mrow0 - mn0);
        const float f1 = __expf(mrow1 - mn1);

        float sum0 = 0.f, sum1 = 0.f;
#pragma unroll
        for (int n = 0; n < 8; n++) {
            sc[n][0] = __expf(sc[n][0] - mn0); sum0 += sc[n][0];
            sc[n][1] = __expf(sc[n][1] - mn0); sum0 += sc[n][1];
            sc[n][2] = __expf(sc[n][2] - mn1); sum1 += sc[n][2];
            sc[n][3] = __expf(sc[n][3] - mn1); sum1 += sc[n][3];
        }
        sum0 += __shfl_xor_sync(0xffffffffu, sum0, 1);
        sum0 += __shfl_xor_sync(0xffffffffu, sum0, 2);
        sum1 += __shfl_xor_sync(0xffffffffu, sum1, 1);
        sum1 += __shfl_xor_sync(0xffffffffu, sum1, 2);

        lrow0 = lrow0 * f0 + sum0; mrow0 = mn0;
        lrow1 = lrow1 * f1 + sum1; mrow1 = mn1;
#pragma unroll
        for (int n = 0; n < 8; n++) {
            oacc[n][0] *= f0; oacc[n][1] *= f0;
            oacc[n][2] *= f1; oacc[n][3] *= f1;
        }

        // ---- O += P V (1-term: P fp16, V hi) ----
#pragma unroll
        for (int kk = 0; kk < 4; kk++) {
            uint32_t aP[4];
            aP[0] = pack_h(sc[2 * kk][0], sc[2 * kk][1]);
            aP[1] = pack_h(sc[2 * kk][2], sc[2 * kk][3]);
            aP[2] = pack_h(sc[2 * kk + 1][0], sc[2 * kk + 1][1]);
            aP[3] = pack_h(sc[2 * kk + 1][2], sc[2 * kk + 1][3]);
#pragma unroll
            for (int g2 = 0; g2 < 4; g2++) {
                uint32_t rh[4];
                const uint32_t va = sb + bo + kk * 16 * APB + lmoff + g2 * 32;
                ldsm_x4_t(rh, va + S_VHI);
                uint32_t b0[2] = {rh[0], rh[1]}, b1[2] = {rh[2], rh[3]};
                mma_f16(oacc[2 * g2], aP, b0);
                mma_f16(oacc[2 * g2 + 1], aP, b1);
            }
        }
    }

    // ---- normalize + write fp16 ----
    const float inv0 = 1.f / lrow0;
    const float inv1 = 1.f / lrow1;
    const size_t orow0 = (rowbase + q0 + wrow + gq) * D_MODEL + hoff;
    const size_t orow1 = orow0 + 8 * D_MODEL;
#pragma unroll
    for (int n = 0; n < 8; n++) {
        const int col = 8 * n + 2 * tig;
        *(uint32_t*)&Ohi[orow0 + col] = pack_h(oacc[n][0] * inv0, oacc[n][1] * inv0);
        *(uint32_t*)&Ohi[orow1 + col] = pack_h(oacc[n][2] * inv1, oacc[n][3] * inv1);
    }
}

// ---------------------------------------------------------------------------
extern "C" void kernel_launch(void* const* d_in, const int* in_sizes, int n_in,
                              void* d_out, int out_size)
{
    const float* q  = (const float*)d_in[0];
    const void*  mk = d_in[1];
    const float* Wq = (const float*)d_in[2];
    const float* Wk = (const float*)d_in[3];
    const float* Wv = (const float*)d_in[4];
    const float* Wo = (const float*)d_in[5];
    const float* bo = (const float*)d_in[6];
    float* out      = (float*)d_out;

    __half *inh, *Qhi, *Qlo, *Khi, *Vhi, *Ohi, *wh;
    u64* mbits;
    cudaGetSymbolAddress((void**)&inh, g_inh);
    cudaGetSymbolAddress((void**)&Qhi, g_Qhi);
    cudaGetSymbolAddress((void**)&Qlo, g_Qlo);
    cudaGetSymbolAddress((void**)&Khi, g_Khi);
    cudaGetSymbolAddress((void**)&Vhi, g_Vhi);
    cudaGetSymbolAddress((void**)&Ohi, g_Ohi);
    cudaGetSymbolAddress((void**)&wh, g_wh);
    cudaGetSymbolAddress((void**)&mbits, g_mbits);

    detect_mask_kind<<<1, 256>>>((const uint4*)mk);

    round_all<<<(NQ + 4 * NW) / 1024, 256>>>(q, Wq, Wk, Wv, Wo, inh, wh);
    pack_mask<<<(BATCH * N_SEQ * (N_SEQ / 64)) / 16, 256>>>(mk, mbits);

    const int gemm_smem = 4 * 2 * TILE_B;   // 81920
    cudaFuncSetAttribute(gemm_qkv, cudaFuncAttributeMaxDynamicSharedMemorySize,
                         gemm_smem);
    cudaFuncSetAttribute(gemm_out, cudaFuncAttributeMaxDynamicSharedMemorySize,
                         gemm_smem);

    gemm_qkv<<<dim3(D_MODEL / 128, MTOT / 128, 3), 256, gemm_smem>>>(
        inh, wh, Qhi, Qlo, Khi, Vhi);

    const int attn_smem = 4 * ABUF;   // 73728
    cudaFuncSetAttribute(attn_mma, cudaFuncAttributeMaxDynamicSharedMemorySize,
                         attn_smem);
    attn_mma<<<dim3(N_SEQ / 128, BATCH * NHEADS), 256, attn_smem>>>(
        Qhi, Qlo, Khi, Vhi, mbits, Ohi);

    gemm_out<<<dim3(D_MODEL / 128, MTOT / 128), 256, gemm_smem>>>(
        Ohi, wh + 3 * (size_t)NW, bo, out);
}

// round 17
// speedup vs baseline: 5.9966x; 1.0260x over previous
#include <cuda_runtime.h>
#include <cuda_fp16.h>
#include <math.h>
#include <stdint.h>

#define D_MODEL 1024
#define N_SEQ   2048
#define BATCH   2
#define NHEADS  16
#define DHEAD   64
#define QSCALE  0.125f
#define LOG2E   1.44269504f
#define MTOT    (BATCH * N_SEQ)   // 4096
#define NQ      (MTOT * D_MODEL)  // 4M
#define NW      (D_MODEL * D_MODEL) // 1M
#define NEGINF  -1.0e30f
typedef unsigned long long u64;

// ---- mma.sync helpers ----
__device__ __forceinline__ uint32_t smem_u32(const void* p) {
    uint32_t a;
    asm("{ .reg .u64 t; cvta.to.shared.u64 t, %1; cvt.u32.u64 %0, t; }"
        : "=r"(a) : "l"(p));
    return a;
}
__device__ __forceinline__ void ldsm_x4(uint32_t* r, uint32_t addr) {
    asm volatile("ldmatrix.sync.aligned.m8n8.x4.shared.b16 {%0,%1,%2,%3}, [%4];"
        : "=r"(r[0]), "=r"(r[1]), "=r"(r[2]), "=r"(r[3]) : "r"(addr));
}
__device__ __forceinline__ void ldsm_x4_t(uint32_t* r, uint32_t addr) {
    asm volatile("ldmatrix.sync.aligned.m8n8.x4.trans.shared.b16 {%0,%1,%2,%3}, [%4];"
        : "=r"(r[0]), "=r"(r[1]), "=r"(r[2]), "=r"(r[3]) : "r"(addr));
}
__device__ __forceinline__ void mma_f16(float* d, const uint32_t* a,
                                        const uint32_t* b) {
    asm volatile(
        "mma.sync.aligned.m16n8k16.row.col.f32.f16.f16.f32 "
        "{%0,%1,%2,%3}, {%4,%5,%6,%7}, {%8,%9}, {%0,%1,%2,%3};"
        : "+f"(d[0]), "+f"(d[1]), "+f"(d[2]), "+f"(d[3])
        : "r"(a[0]), "r"(a[1]), "r"(a[2]), "r"(a[3]), "r"(b[0]), "r"(b[1]));
}
__device__ __forceinline__ void split_pack_h(float v0, float v1,
                                             uint32_t& h, uint32_t& l) {
    __half h0 = __float2half_rn(v0);
    __half h1 = __float2half_rn(v1);
    float r0 = v0 - __half2float(h0);
    float r1 = v1 - __half2float(h1);
    __half2 hh = __halves2half2(h0, h1);
    __half2 ll = __halves2half2(__float2half_rn(r0), __float2half_rn(r1));
    h = *(uint32_t*)&hh;
    l = *(uint32_t*)&ll;
}
__device__ __forceinline__ uint32_t pack_h(float v0, float v1) {
    __half2 hh = __halves2half2(__float2half_rn(v0), __float2half_rn(v1));
    return *(uint32_t*)&hh;
}
#define CP16(dst, src) \
    asm volatile("cp.async.cg.shared.global [%0], [%1], 16;" \
                 :: "r"(dst), "l"(src) : "memory")
#define CP_COMMIT() asm volatile("cp.async.commit_group;" ::: "memory")
#define CP_WAIT0()  asm volatile("cp.async.wait_group 0;" ::: "memory")
#define CP_WAIT1()  asm volatile("cp.async.wait_group 1;" ::: "memory")

// ---- scratch (device globals) ----
__device__ __half g_inh[NQ];
__device__ __half g_Qhi[NQ];
__device__ __half g_Qlo[NQ];
__device__ __half g_Khi[NQ];
__device__ __half g_Vhi[NQ];
__device__ __half g_Ohi[NQ];
__device__ __half g_wh[4][NW];
__device__ u64    g_mbits[BATCH * N_SEQ * (N_SEQ / 64)];
__device__ int    g_mask_kind;

// ---------------------------------------------------------------------------
// Mask dtype detection: uint4 scan of first 64KB, word-level bit tests.
// ---------------------------------------------------------------------------
__global__ void detect_mask_kind(const uint4* __restrict__ m)
{
    __shared__ int s_flags;
    if (threadIdx.x == 0) s_flags = 0;
    __syncthreads();
    int fl = 0;
#pragma unroll
    for (int it = 0; it < 4; it++) {
        uint4 v = m[threadIdx.x + 256 * it];
        uint32_t w[4] = {v.x, v.y, v.z, v.w};
#pragma unroll
        for (int j = 0; j < 4; j++) {
            if (w[j] & 0xFEFEFEFEu) fl |= 1;
            if (w[j] & 0xFFFFFF00u) fl |= 2;
        }
    }
    if (fl) atomicOr(&s_flags, fl);
    __syncthreads();
    if (threadIdx.x == 0) {
        int f = s_flags;
        g_mask_kind = (f & 1) ? 2 : ((f & 2) ? 0 : 1);
    }
}

// ---------------------------------------------------------------------------
__global__ __launch_bounds__(256) void pack_mask(
    const void* __restrict__ m, u64* __restrict__ out)
{
    const int kind = g_mask_kind;
    const int wp   = blockIdx.x * 8 + (threadIdx.x >> 5);
    const int wi   = wp * 2;
    const int lane = threadIdx.x & 31;
    const int wpr  = N_SEQ / 64;
    const size_t base = (size_t)(wi / wpr) * N_SEQ + (size_t)(wi % wpr) * 64 + lane;
    bool v[4];
    if (kind == 1) {
        const int* p = (const int*)m;
#pragma unroll
        for (int j = 0; j < 4; j++) v[j] = p[base + 32 * j] != 0;
    } else if (kind == 0) {
        const unsigned char* p = (const unsigned char*)m;
#pragma unroll
        for (int j = 0; j < 4; j++) v[j] = p[base + 32 * j] != 0;
    } else {
        const float* p = (const float*)m;
#pragma unroll
        for (int j = 0; j < 4; j++) v[j] = p[base + 32 * j] != 0.f;
    }
    unsigned b0 = __ballot_sync(0xffffffffu, v[0]);
    unsigned b1 = __ballot_sync(0xffffffffu, v[1]);
    unsigned b2 = __ballot_sync(0xffffffffu, v[2]);
    unsigned b3 = __ballot_sync(0xffffffffu, v[3]);
    if (lane == 0) {
        out[wi + 0] = (u64)b0 | ((u64)b1 << 32);
        out[wi + 1] = (u64)b2 | ((u64)b3 << 32);
    }
}

// ---------------------------------------------------------------------------
__global__ __launch_bounds__(256) void round_all(
    const float* __restrict__ q,
    const float* __restrict__ w0, const float* __restrict__ w1,
    const float* __restrict__ w2, const float* __restrict__ w3,
    __half* __restrict__ inh, __half* __restrict__ wh)
{
    int i = (blockIdx.x * 256 + threadIdx.x) * 4;
    const float* src;
    __half* dst;
    if (i < NQ) {
        src = q + i;
        dst = inh + i;
    } else {
        const int j = i - NQ;
        const int sel = j >> 20;
        src = ((sel == 0) ? w0 : (sel == 1) ? w1 : (sel == 2) ? w2 : w3)
              + (j & (NW - 1));
        dst = wh + j;
    }
    float4 v = *(const float4*)src;
    *(uint2*)dst = make_uint2(pack_h(v.x, v.y), pack_h(v.z, v.w));
}

// ---------------------------------------------------------------------------
// GEMM (NT): out = alpha*(Ahi[+Alo])*Wh^T (+bias). 1- or 2-term fp16.
// CTA 128x128, BK=32, 8 warps @ 32x64, 5-stage ring, sync every 2 K-blocks.
// ---------------------------------------------------------------------------
#define MBK    32
#define PITCH  80
#define TILE_B (128 * PITCH)          // 10240
#define NSTG   5

template <bool TWO>
__device__ __forceinline__ void gemm_body(
    const __half* __restrict__ Ahi, const __half* __restrict__ Alo,
    const __half* __restrict__ Wh,
    const float* __restrict__ bias, float* __restrict__ Cf,
    __half* __restrict__ Chi, __half* __restrict__ Clo,
    int N, int K, float alpha, char* dsm)
{
    constexpr uint32_t SMAL = TILE_B;
    constexpr uint32_t SMW  = TWO ? 2u * TILE_B : TILE_B;
    constexpr uint32_t BUF  = TWO ? 3u * TILE_B : 2u * TILE_B;

    const uint32_t sbase = smem_u32(dsm);
    const int tid  = threadIdx.x;
    const int wid  = tid >> 5;
    const int lane = tid & 31;
    const int wm   = wid & 3;
    const int wn   = wid >> 2;
    const int m0   = blockIdx.y * 128;
    const int n0   = blockIdx.x * 128;

    const int q8  = lane >> 3;
    const int rin = lane & 7;
    const uint32_t lmoff = (uint32_t)(((q8 & 1) * 8 + rin) * PITCH + (q8 >> 1) * 16);

    const int lr0 = tid >> 2, lc0 = tid & 3;
    const int lr1 = (tid + 256) >> 2, lc1 = (tid + 256) & 3;
    const __half* gA0  = Ahi + (size_t)(m0 + lr0) * K + lc0 * 8;
    const __half* gA1  = Ahi + (size_t)(m0 + lr1) * K + lc1 * 8;
    const __half* gAl0 = TWO ? Alo + (size_t)(m0 + lr0) * K + lc0 * 8 : gA0;
    const __half* gAl1 = TWO ? Alo + (size_t)(m0 + lr1) * K + lc1 * 8 : gA1;
    const __half* gW0  = Wh + (size_t)(n0 + lr0) * K + lc0 * 8;
    const __half* gW1  = Wh + (size_t)(n0 + lr1) * K + lc1 * 8;
    const uint32_t s0 = lr0 * PITCH + lc0 * 16;
    const uint32_t s1 = lr1 * PITCH + lc1 * 16;

#define G_ISSUE(kb) do {                                                      \
    const int _ko = (kb) * MBK;                                               \
    const uint32_t _d = sbase + (uint32_t)((kb) % NSTG) * BUF;                \
    CP16(_d + s0, gA0 + _ko);  CP16(_d + s1, gA1 + _ko);                      \
    if (TWO) { CP16(_d + SMAL + s0, gAl0 + _ko);                              \
               CP16(_d + SMAL + s1, gAl1 + _ko); }                            \
    CP16(_d + SMW + s0, gW0 + _ko);   CP16(_d + SMW + s1, gW1 + _ko);         \
} while (0)

#define G_COMPUTE(kb) do {                                                    \
    const uint32_t tb32 = sbase + (uint32_t)((kb) % NSTG) * BUF;              \
    const uint32_t aoff = tb32 + (wm * 32) * PITCH + lmoff;                   \
    const uint32_t woff = tb32 + (wn * 64) * PITCH + lmoff;                   \
    _Pragma("unroll")                                                         \
    for (int ks = 0; ks < 2; ks++) {                                          \
        const uint32_t kso = ks * 32;                                         \
        uint32_t ahi[2][4], alo[2][4];                                        \
        _Pragma("unroll")                                                     \
        for (int s = 0; s < 2; s++) {                                         \
            ldsm_x4(ahi[s], aoff + s * 16 * PITCH + kso);                     \
            if (TWO) ldsm_x4(alo[s], aoff + SMAL + s * 16 * PITCH + kso);     \
        }                                                                     \
        _Pragma("unroll")                                                     \
        for (int g = 0; g < 4; g++) {                                         \
            uint32_t rh[4];                                                   \
            ldsm_x4(rh, woff + SMW + g * 16 * PITCH + kso);                   \
            uint32_t b0[2] = {rh[0], rh[2]}, b1[2] = {rh[1], rh[3]};          \
            _Pragma("unroll")                                                 \
            for (int s = 0; s < 2; s++) {                                     \
                mma_f16(acc[s][2 * g], ahi[s], b0);                           \
                if (TWO) mma_f16(acc[s][2 * g], alo[s], b0);                  \
                mma_f16(acc[s][2 * g + 1], ahi[s], b1);                       \
                if (TWO) mma_f16(acc[s][2 * g + 1], alo[s], b1);              \
            }                                                                 \
        }                                                                     \
    }                                                                         \
} while (0)

    float acc[2][8][4];
#pragma unroll
    for (int s = 0; s < 2; s++)
#pragma unroll
        for (int n = 0; n < 8; n++)
#pragma unroll
            for (int r = 0; r < 4; r++) acc[s][n][r] = 0.f;

    G_ISSUE(0); CP_COMMIT();
    G_ISSUE(1); CP_COMMIT();
    G_ISSUE(2); CP_COMMIT();

    const int nkb = K / MBK;   // 32
    for (int kb = 0; kb < nkb; kb += 2) {
        if (kb + 2 < nkb) CP_WAIT1(); else CP_WAIT0();
        __syncthreads();
        if (kb + 3 < nkb) { G_ISSUE(kb + 3); CP_COMMIT(); }
        if (kb + 4 < nkb) { G_ISSUE(kb + 4); CP_COMMIT(); }
        G_COMPUTE(kb);
        G_COMPUTE(kb + 1);
    }

#pragma unroll
    for (int s = 0; s < 2; s++) {
        const int r0 = m0 + wm * 32 + s * 16 + (lane >> 2);
#pragma unroll
        for (int n = 0; n < 8; n++) {
            const int col = n0 + wn * 64 + n * 8 + (lane & 3) * 2;
            const float b0 = bias ? bias[col] : 0.f;
            const float b1 = bias ? bias[col + 1] : 0.f;
            const float v0 = alpha * acc[s][n][0] + b0;
            const float v1 = alpha * acc[s][n][1] + b1;
            const float v2 = alpha * acc[s][n][2] + b0;
            const float v3 = alpha * acc[s][n][3] + b1;
            if (Cf) {
                *(float2*)&Cf[(size_t)r0 * N + col] = make_float2(v0, v1);
                *(float2*)&Cf[(size_t)(r0 + 8) * N + col] = make_float2(v2, v3);
            } else if (Clo) {
                uint32_t h, l;
                split_pack_h(v0, v1, h, l);
                *(uint32_t*)&Chi[(size_t)r0 * N + col] = h;
                *(uint32_t*)&Clo[(size_t)r0 * N + col] = l;
                split_pack_h(v2, v3, h, l);
                *(uint32_t*)&Chi[(size_t)(r0 + 8) * N + col] = h;
                *(uint32_t*)&Clo[(size_t)(r0 + 8) * N + col] = l;
            } else {
                *(uint32_t*)&Chi[(size_t)r0 * N + col] = pack_h(v0, v1);
                *(uint32_t*)&Chi[(size_t)(r0 + 8) * N + col] = pack_h(v2, v3);
            }
        }
    }
#undef G_ISSUE
#undef G_COMPUTE
}

// QKV projection, 1-term. Q gets hi/lo split output, scaled by QSCALE*log2e
// (softmax runs in base-2 domain).
__global__ __launch_bounds__(256, 2) void gemm_qkv(
    const __half* __restrict__ inh, const __half* __restrict__ wh,
    __half* __restrict__ Qhi, __half* __restrict__ Qlo,
    __half* __restrict__ Khi, __half* __restrict__ Vhi)
{
    extern __shared__ char dsm[];
    const int z = blockIdx.z;
    const __half* Wh = wh + (size_t)z * NW;
    __half* Chi = (z == 0) ? Qhi : (z == 1) ? Khi : Vhi;
    __half* Clo = (z == 0) ? Qlo : nullptr;
    const float alpha = (z == 0) ? QSCALE * LOG2E : 1.0f;
    gemm_body<false>(inh, nullptr, Wh, nullptr, nullptr, Chi, Clo,
                     D_MODEL, D_MODEL, alpha, dsm);
}

// Output projection, 1-term (O fp16), fp32 + bias.
__global__ __launch_bounds__(256, 2) void gemm_out(
    const __half* __restrict__ Ahi, const __half* __restrict__ Wh,
    const float* __restrict__ bias, float* __restrict__ Cf)
{
    extern __shared__ char dsm[];
    gemm_body<false>(Ahi, nullptr, Wh, bias, Cf, nullptr, nullptr,
                     D_MODEL, D_MODEL, 1.0f, dsm);
}

// ---------------------------------------------------------------------------
// Tensor-core flash attention, k-tile 64, q-tile 128, 5-stage ring,
// sync every 2 k-tiles. Softmax in base-2 domain (scale folded into Q).
// QK^T: 2-term. PV: 1-term. Bitmask. Output: fp16.
// ---------------------------------------------------------------------------
#define APB    144
#define KTROWS 64
#define KREG   (KTROWS * APB)         // 9216
#define S_KHI  0
#define S_VHI  (1 * KREG)
#define ABUF   (2 * KREG)             // 18432 per stage
#define NKT    (N_SEQ / KTROWS)       // 32

__global__ __launch_bounds__(256, 2) void attn_mma(
    const __half* __restrict__ Qhi, const __half* __restrict__ Qlo,
    const __half* __restrict__ Khi, const __half* __restrict__ Vhi,
    const u64* __restrict__ mbits,
    __half* __restrict__ Ohi)
{
    extern __shared__ char smemb[];
    const uint32_t sb = smem_u32(smemb);

    const int tid  = threadIdx.x;
    const int warp = tid >> 5;
    const int lane = tid & 31;
    const int gq   = lane >> 2;
    const int tig  = lane & 3;
    const int q8   = lane >> 3;
    const int rin  = lane & 7;
    const uint32_t lmoff = (uint32_t)(((q8 & 1) * 8 + rin) * APB + (q8 >> 1) * 16);
    const int wrow = warp * 16;

    const int bh = blockIdx.y;
    const int b  = bh >> 4;
    const int h  = bh & 15;
    const int q0 = blockIdx.x * 128;
    const size_t rowbase = (size_t)b * N_SEQ;
    const int hoff = h * DHEAD;

    // ---- stage Q (128 rows) into ring stages 0/1; read to regs ----
#pragma unroll
    for (int i = 0; i < 4; i++) {
        const int c = tid + 256 * i;
        const int row = c >> 3, colc = c & 7;
        const size_t src = (rowbase + q0 + row) * D_MODEL + hoff + colc * 8;
        const uint32_t off = (row >= 64 ? ABUF : 0) + (row & 63) * APB + colc * 16;
        *(uint4*)(smemb + S_KHI + off) = *(const uint4*)(Qhi + src);
        *(uint4*)(smemb + S_VHI + off) = *(const uint4*)(Qlo + src);
    }
    __syncthreads();
    uint32_t aQh[4][4], aQl[4][4];
    {
        const uint32_t qb = sb + (wrow >= 64 ? ABUF : 0) + (wrow & 63) * APB + lmoff;
#pragma unroll
        for (int ks = 0; ks < 4; ks++) {
            ldsm_x4(aQh[ks], qb + S_KHI + ks * 32);
            ldsm_x4(aQl[ks], qb + S_VHI + ks * 32);
        }
    }
    __syncthreads();

    float oacc[8][4];
#pragma unroll
    for (int n = 0; n < 8; n++)
#pragma unroll
        for (int r = 0; r < 4; r++) oacc[n][r] = 0.f;
    float mrow0 = NEGINF, mrow1 = NEGINF, lrow0 = 0.f, lrow1 = 0.f;

#define ISSUE_TILES(kt) do {                                                  \
    _Pragma("unroll")                                                         \
    for (int i = 0; i < 2; i++) {                                             \
        const int c = tid + 256 * i;                                          \
        const int row = c >> 3, colc = c & 7;                                 \
        const size_t src = (rowbase + (kt) * KTROWS + row) * D_MODEL + hoff + colc * 8; \
        const uint32_t dst = sb + (uint32_t)((kt) % NSTG) * ABUF + row * APB + colc * 16; \
        CP16(dst + S_KHI, Khi + src);                                         \
        CP16(dst + S_VHI, Vhi + src);                                         \
    }                                                                         \
} while (0)

// One k-tile: QK^T (2-term), mask, base-2 online softmax, PV (1-term).
#define DO_TILE(kt) do {                                                      \
    const uint32_t bo = (uint32_t)((kt) % NSTG) * ABUF;                       \
    float sc[8][4];                                                           \
    _Pragma("unroll")                                                         \
    for (int n = 0; n < 8; n++)                                               \
        _Pragma("unroll")                                                     \
        for (int r = 0; r < 4; r++) sc[n][r] = 0.f;                           \
    _Pragma("unroll")                                                         \
    for (int ks = 0; ks < 4; ks++) {                                          \
        _Pragma("unroll")                                                     \
        for (int g2 = 0; g2 < 4; g2++) {                                      \
            uint32_t rh[4];                                                   \
            const uint32_t ka = sb + bo + g2 * 16 * APB + lmoff + ks * 32;    \
            ldsm_x4(rh, ka + S_KHI);                                          \
            uint32_t b0h[2] = {rh[0], rh[2]}, b1h[2] = {rh[1], rh[3]};        \
            mma_f16(sc[2 * g2], aQh[ks], b0h);                                \
            mma_f16(sc[2 * g2], aQl[ks], b0h);                                \
            mma_f16(sc[2 * g2 + 1], aQh[ks], b1h);                            \
            mma_f16(sc[2 * g2 + 1], aQl[ks], b1h);                            \
        }                                                                     \
    }                                                                         \
    {                                                                         \
        const u64 w0 = mb0[kt];                                               \
        const u64 w1 = mb1[kt];                                               \
        _Pragma("unroll")                                                     \
        for (int n = 0; n < 8; n++) {                                         \
            const unsigned t0 = (unsigned)(w0 >> (8 * n + 2 * tig));          \
            const unsigned t1 = (unsigned)(w1 >> (8 * n + 2 * tig));          \
            if (t0 & 1) sc[n][0] = NEGINF;                                    \
            if (t0 & 2) sc[n][1] = NEGINF;                                    \
            if (t1 & 1) sc[n][2] = NEGINF;                                    \
            if (t1 & 2) sc[n][3] = NEGINF;                                    \
        }                                                                     \
    }                                                                         \
    float mx0 = NEGINF, mx1 = NEGINF;                                         \
    _Pragma("unroll")                                                         \
    for (int n = 0; n < 8; n++) {                                             \
        mx0 = fmaxf(mx0, fmaxf(sc[n][0], sc[n][1]));                          \
        mx1 = fmaxf(mx1, fmaxf(sc[n][2], sc[n][3]));                          \
    }                                                                         \
    mx0 = fmaxf(mx0, __shfl_xor_sync(0xffffffffu, mx0, 1));                   \
    mx0 = fmaxf(mx0, __shfl_xor_sync(0xffffffffu, mx0, 2));                   \
    mx1 = fmaxf(mx1, __shfl_xor_sync(0xffffffffu, mx1, 1));                   \
    mx1 = fmaxf(mx1, __shfl_xor_sync(0xffffffffu, mx1, 2));                   \
    const float mn0 = fmaxf(mrow0, mx0);                                      \
    const float mn1 = fmaxf(mrow1, mx1);                                      \
    const float f0 = exp2f(mrow0 - mn0);                                      \
    const float f1 = exp2f(mrow1 - mn1);                                      \
    float sum0 = 0.f, sum1 = 0.f;                                             \
    _Pragma("unroll")                                                         \
    for (int n = 0; n < 8; n++) {                                             \
        sc[n][0] = exp2f(sc[n][0] - mn0); sum0 += sc[n][0];                   \
        sc[n][1] = exp2f(sc[n][1] - mn0); sum0 += sc[n][1];                   \
        sc[n][2] = exp2f(sc[n][2] - mn1); sum1 += sc[n][2];                   \
        sc[n][3] = exp2f(sc[n][3] - mn1); sum1 += sc[n][3];                   \
    }                                                                         \
    sum0 += __shfl_xor_sync(0xffffffffu, sum0, 1);                            \
    sum0 += __shfl_xor_sync(0xffffffffu, sum0, 2);                            \
    sum1 += __shfl_xor_sync(0xffffffffu, sum1, 1);                            \
    sum1 += __shfl_xor_sync(0xffffffffu, sum1, 2);                            \
    lrow0 = lrow0 * f0 + sum0; mrow0 = mn0;                                   \
    lrow1 = lrow1 * f1 + sum1; mrow1 = mn1;                                   \
    _Pragma("unroll")                                                         \
    for (int n = 0; n < 8; n++) {                                             \
        oacc[n][0] *= f0; oacc[n][1] *= f0;                                   \
        oacc[n][2] *= f1; oacc[n][3] *= f1;                                   \
    }                                                                         \
    _Pragma("unroll")                                                         \
    for (int kk = 0; kk < 4; kk++) {                                          \
        uint32_t aP[4];                                                       \
        aP[0] = pack_h(sc[2 * kk][0], sc[2 * kk][1]);                         \
        aP[1] = pack_h(sc[2 * kk][2], sc[2 * kk][3]);                         \
        aP[2] = pack_h(sc[2 * kk + 1][0], sc[2 * kk + 1][1]);                 \
        aP[3] = pack_h(sc[2 * kk + 1][2], sc[2 * kk + 1][3]);                 \
        _Pragma("unroll")                                                     \
        for (int g2 = 0; g2 < 4; g2++) {                                      \
            uint32_t rh[4];                                                   \
            const uint32_t va = sb + bo + kk * 16 * APB + lmoff + g2 * 32;    \
            ldsm_x4_t(rh, va + S_VHI);                                        \
            uint32_t b0[2] = {rh[0], rh[1]}, b1[2] = {rh[2], rh[3]};          \
            mma_f16(oacc[2 * g2], aP, b0);                                    \
            mma_f16(oacc[2 * g2 + 1], aP, b1);                                \
        }                                                                     \
    }                                                                         \
} while (0)

    ISSUE_TILES(0); CP_COMMIT();
    ISSUE_TILES(1); CP_COMMIT();
    ISSUE_TILES(2); CP_COMMIT();

    const u64* mb0 = mbits + (size_t)(b * N_SEQ + q0 + wrow + gq) * (N_SEQ / 64);
    const u64* mb1 = mb0 + 8 * (N_SEQ / 64);

    for (int kt = 0; kt < NKT; kt += 2) {
        if (kt + 2 < NKT) CP_WAIT1(); else CP_WAIT0();
        __syncthreads();
        if (kt + 3 < NKT) { ISSUE_TILES(kt + 3); CP_COMMIT(); }
        if (kt + 4 < NKT) { ISSUE_TILES(kt + 4); CP_COMMIT(); }
        DO_TILE(kt);
        DO_TILE(kt + 1);
    }

    // ---- normalize + write fp16 ----
    const float inv0 = 1.f / lrow0;
    const float inv1 = 1.f / lrow1;
    const size_t orow0 = (rowbase + q0 + wrow + gq) * D_MODEL + hoff;
    const size_t orow1 = orow0 + 8 * D_MODEL;
#pragma unroll
    for (int n = 0; n < 8; n++) {
        const int col = 8 * n + 2 * tig;
        *(uint32_t*)&Ohi[orow0 + col] = pack_h(oacc[n][0] * inv0, oacc[n][1] * inv0);
        *(uint32_t*)&Ohi[orow1 + col] = pack_h(oacc[n][2] * inv1, oacc[n][3] * inv1);
    }
#undef ISSUE_TILES
#undef DO_TILE
}

// ---------------------------------------------------------------------------
extern "C" void kernel_launch(void* const* d_in, const int* in_sizes, int n_in,
                              void* d_out, int out_size)
{
    const float* q  = (const float*)d_in[0];
    const void*  mk = d_in[1];
    const float* Wq = (const float*)d_in[2];
    const float* Wk = (const float*)d_in[3];
    const float* Wv = (const float*)d_in[4];
    const float* Wo = (const float*)d_in[5];
    const float* bo = (const float*)d_in[6];
    float* out      = (float*)d_out;

    __half *inh, *Qhi, *Qlo, *Khi, *Vhi, *Ohi, *wh;
    u64* mbits;
    cudaGetSymbolAddress((void**)&inh, g_inh);
    cudaGetSymbolAddress((void**)&Qhi, g_Qhi);
    cudaGetSymbolAddress((void**)&Qlo, g_Qlo);
    cudaGetSymbolAddress((void**)&Khi, g_Khi);
    cudaGetSymbolAddress((void**)&Vhi, g_Vhi);
    cudaGetSymbolAddress((void**)&Ohi, g_Ohi);
    cudaGetSymbolAddress((void**)&wh, g_wh);
    cudaGetSymbolAddress((void**)&mbits, g_mbits);

    detect_mask_kind<<<1, 256>>>((const uint4*)mk);

    round_all<<<(NQ + 4 * NW) / 1024, 256>>>(q, Wq, Wk, Wv, Wo, inh, wh);
    pack_mask<<<(BATCH * N_SEQ * (N_SEQ / 64)) / 16, 256>>>(mk, mbits);

    const int gemm_smem = NSTG * 2 * TILE_B;   // 102400
    cudaFuncSetAttribute(gemm_qkv, cudaFuncAttributeMaxDynamicSharedMemorySize,
                         gemm_smem);
    cudaFuncSetAttribute(gemm_out, cudaFuncAttributeMaxDynamicSharedMemorySize,
                         gemm_smem);

    gemm_qkv<<<dim3(D_MODEL / 128, MTOT / 128, 3), 256, gemm_smem>>>(
        inh, wh, Qhi, Qlo, Khi, Vhi);

    const int attn_smem = NSTG * ABUF;   // 92160
    cudaFuncSetAttribute(attn_mma, cudaFuncAttributeMaxDynamicSharedMemorySize,
                         attn_smem);
    attn_mma<<<dim3(N_SEQ / 128, BATCH * NHEADS), 256, attn_smem>>>(
        Qhi, Qlo, Khi, Vhi, mbits, Ohi);

    gemm_out<<<dim3(D_MODEL / 128, MTOT / 128), 256, gemm_smem>>>(
        Ohi, wh + 3 * (size_t)NW, bo, out);
}